// round 1
// baseline (speedup 1.0000x reference)
#include <cuda_runtime.h>
#include <math.h>

#define NNODES 50000
#define NEDGES 800000
#define FDIM   256          // H*C
#define TOTE   (NEDGES + NNODES)
#define NB_SCAN ((NNODES + 511) / 512)

// ---------------- scratch (static device globals; no allocation) ----------------
__device__ float g_bufA[(size_t)NNODES * FDIM];   // 51.2 MB
__device__ float g_bufB[(size_t)NNODES * FDIM];   // 51.2 MB
__device__ float g_asrcv[NNODES * 4];
__device__ float g_adstv[NNODES * 4];
__device__ int   g_deg[NNODES];
__device__ int   g_rowptr[NNODES + 1];
__device__ int   g_cursor[NNODES];
__device__ int   g_srclist[TOTE];
__device__ int   g_blksums[256];

// ---------------- CSR build ----------------
__global__ void k_init_deg() {
    int i = blockIdx.x * blockDim.x + threadIdx.x;
    if (i < NNODES) g_deg[i] = 1;   // self loop
}

__global__ void k_count(const int* __restrict__ ei) {
    int i = blockIdx.x * blockDim.x + threadIdx.x;
    if (i < NEDGES) atomicAdd(&g_deg[ei[NEDGES + i]], 1);
}

__global__ void k_scan1() {
    __shared__ int s[512];
    int tid = threadIdx.x;
    int i = blockIdx.x * 512 + tid;
    int v = (i < NNODES) ? g_deg[i] : 0;
    s[tid] = v;
    __syncthreads();
    for (int off = 1; off < 512; off <<= 1) {
        int t = (tid >= off) ? s[tid - off] : 0;
        __syncthreads();
        s[tid] += t;
        __syncthreads();
    }
    if (i < NNODES) g_rowptr[i] = s[tid] - v;      // exclusive (partial)
    if (tid == 511) g_blksums[blockIdx.x] = s[511];
}

__global__ void k_scan2() {
    if (threadIdx.x == 0 && blockIdx.x == 0) {
        int run = 0;
        for (int b = 0; b < NB_SCAN; b++) {
            int t = g_blksums[b];
            g_blksums[b] = run;
            run += t;
        }
    }
}

__global__ void k_scan3() {
    int i = blockIdx.x * blockDim.x + threadIdx.x;
    if (i < NNODES) g_rowptr[i] += g_blksums[i >> 9];
    if (i == 0) g_rowptr[NNODES] = TOTE;
}

__global__ void k_fill_init() {
    int n = blockIdx.x * blockDim.x + threadIdx.x;
    if (n < NNODES) {
        int r = g_rowptr[n];
        g_srclist[r] = n;        // self loop goes first
        g_cursor[n] = r + 1;
    }
}

__global__ void k_fill(const int* __restrict__ ei) {
    int i = blockIdx.x * blockDim.x + threadIdx.x;
    if (i < NEDGES) {
        int s = ei[i];
        int d = ei[NEDGES + i];
        int pos = atomicAdd(&g_cursor[d], 1);
        g_srclist[pos] = s;
    }
}

// make per-node edge order deterministic (sort segment by src; duplicates are
// identical contributions so ties don't matter)
__global__ void k_sort() {
    int n = blockIdx.x * blockDim.x + threadIdx.x;
    if (n >= NNODES) return;
    int beg = g_rowptr[n] + 1;
    int end = g_rowptr[n + 1];
    for (int i = beg + 1; i < end; i++) {
        int key = g_srclist[i];
        int j = i - 1;
        while (j >= beg && g_srclist[j] > key) {
            g_srclist[j + 1] = g_srclist[j];
            j--;
        }
        g_srclist[j + 1] = key;
    }
}

// ---------------- SGEMM: C[M,Nn] = A[M,K] * B[K,Nn], row-major fp32 ----------------
// 128x128 tile, BK=8, 256 threads, 8x8 per thread
__global__ void k_sgemm(const float* __restrict__ A, const float* __restrict__ B,
                        float* __restrict__ C, int M, int Nn, int K) {
    __shared__ float As[8][128];
    __shared__ float Bs[8][128];
    int tid = threadIdx.x;
    int bx = blockIdx.x, by = blockIdx.y;

    int arow = tid >> 1;            // 0..127
    int acol = (tid & 1) * 4;       // 0 or 4
    int brow = tid >> 5;            // 0..7
    int bcol = (tid & 31) * 4;      // 0..124
    int tx = tid & 15, ty = tid >> 4;

    float acc[8][8];
#pragma unroll
    for (int i = 0; i < 8; i++)
#pragma unroll
        for (int j = 0; j < 8; j++) acc[i][j] = 0.f;

    int aRow = by * 128 + arow;
    bool aValid = (aRow < M);
    const float* Aptr = A + (size_t)aRow * K + acol;
    const float* Bptr = B + (size_t)brow * Nn + bx * 128 + bcol;

    for (int kt = 0; kt < K; kt += 8) {
        float4 av = aValid ? *(const float4*)(Aptr + kt) : make_float4(0.f, 0.f, 0.f, 0.f);
        float4 bv = *(const float4*)(Bptr + (size_t)kt * Nn);
        __syncthreads();
        As[acol + 0][arow] = av.x;
        As[acol + 1][arow] = av.y;
        As[acol + 2][arow] = av.z;
        As[acol + 3][arow] = av.w;
        *(float4*)&Bs[brow][bcol] = bv;
        __syncthreads();
#pragma unroll
        for (int k = 0; k < 8; k++) {
            float4 a0 = *(const float4*)&As[k][ty * 8];
            float4 a1 = *(const float4*)&As[k][ty * 8 + 4];
            float4 b0 = *(const float4*)&Bs[k][tx * 8];
            float4 b1 = *(const float4*)&Bs[k][tx * 8 + 4];
            float ra[8] = {a0.x, a0.y, a0.z, a0.w, a1.x, a1.y, a1.z, a1.w};
            float rb[8] = {b0.x, b0.y, b0.z, b0.w, b1.x, b1.y, b1.z, b1.w};
#pragma unroll
            for (int i = 0; i < 8; i++)
#pragma unroll
                for (int j = 0; j < 8; j++) acc[i][j] += ra[i] * rb[j];
        }
    }

#pragma unroll
    for (int i = 0; i < 8; i++) {
        int row = by * 128 + ty * 8 + i;
        if (row < M) {
            float* cp = C + (size_t)row * Nn + bx * 128 + tx * 8;
            *(float4*)cp = make_float4(acc[i][0], acc[i][1], acc[i][2], acc[i][3]);
            *(float4*)(cp + 4) = make_float4(acc[i][4], acc[i][5], acc[i][6], acc[i][7]);
        }
    }
}

// ---------------- per-node attention dot products ----------------
// one warp per node; lane l owns channels [8l, 8l+8) (head = l>>3)
__global__ void k_attn(const float* __restrict__ X,
                       const float* __restrict__ a_src,
                       const float* __restrict__ a_dst) {
    int gwarp = (blockIdx.x * blockDim.x + threadIdx.x) >> 5;
    int lane = threadIdx.x & 31;
    if (gwarp >= NNODES) return;
    int ch0 = lane * 8;
    const float4* xp = (const float4*)(X + (size_t)gwarp * FDIM + ch0);
    float4 v0 = xp[0], v1 = xp[1];
    const float4* sp = (const float4*)(a_src + ch0);
    const float4* dp = (const float4*)(a_dst + ch0);
    float4 s0 = sp[0], s1 = sp[1];
    float4 d0 = dp[0], d1 = dp[1];
    float ps = v0.x * s0.x + v0.y * s0.y + v0.z * s0.z + v0.w * s0.w
             + v1.x * s1.x + v1.y * s1.y + v1.z * s1.z + v1.w * s1.w;
    float pd = v0.x * d0.x + v0.y * d0.y + v0.z * d0.z + v0.w * d0.w
             + v1.x * d1.x + v1.y * d1.y + v1.z * d1.z + v1.w * d1.w;
#pragma unroll
    for (int off = 4; off > 0; off >>= 1) {
        ps += __shfl_down_sync(0xffffffffu, ps, off, 8);
        pd += __shfl_down_sync(0xffffffffu, pd, off, 8);
    }
    if ((lane & 7) == 0) {
        int h = lane >> 3;
        g_asrcv[gwarp * 4 + h] = ps;
        g_adstv[gwarp * 4 + h] = pd;
    }
}

// ---------------- GAT aggregation (online softmax) + bias + BN + ReLU ----------------
__global__ void k_agg(const float* __restrict__ X,
                      const float* __restrict__ bias,
                      const float* __restrict__ gam,
                      const float* __restrict__ bet,
                      const float* __restrict__ mu,
                      const float* __restrict__ var,
                      float* __restrict__ OUT) {
    int gwarp = (blockIdx.x * blockDim.x + threadIdx.x) >> 5;
    int lane = threadIdx.x & 31;
    if (gwarp >= NNODES) return;
    int n = gwarp;
    int ch0 = lane * 8;
    int hl = lane >> 3;

    float m = -1e30f, dsum = 0.f;
    float acc[8];
#pragma unroll
    for (int j = 0; j < 8; j++) acc[j] = 0.f;

    float adv = g_adstv[n * 4 + hl];
    int r0 = g_rowptr[n], r1 = g_rowptr[n + 1];

    for (int k = r0; k < r1; k++) {
        int s = g_srclist[k];
        float e = g_asrcv[s * 4 + hl] + adv;
        e = (e > 0.f) ? e : 0.2f * e;              // leaky relu slope 0.2
        float mn = fmaxf(m, e);
        float sc = __expf(m - mn);
        float p  = __expf(e - mn);
        dsum = dsum * sc + p;
        const float4* hp = (const float4*)(X + (size_t)s * FDIM + ch0);
        float4 v0 = hp[0], v1 = hp[1];
        acc[0] = acc[0] * sc + p * v0.x;
        acc[1] = acc[1] * sc + p * v0.y;
        acc[2] = acc[2] * sc + p * v0.z;
        acc[3] = acc[3] * sc + p * v0.w;
        acc[4] = acc[4] * sc + p * v1.x;
        acc[5] = acc[5] * sc + p * v1.y;
        acc[6] = acc[6] * sc + p * v1.z;
        acc[7] = acc[7] * sc + p * v1.w;
        m = mn;
    }

    float inv = 1.f / (dsum + 1e-16f);
    float ov[8];
#pragma unroll
    for (int j = 0; j < 8; j++) {
        int ch = ch0 + j;
        float val = acc[j] * inv + bias[ch];
        val = (val - mu[ch]) * rsqrtf(var[ch] + 1e-5f) * gam[ch] + bet[ch];
        ov[j] = fmaxf(val, 0.f);
    }
    float4* op = (float4*)(OUT + (size_t)n * FDIM + ch0);
    op[0] = make_float4(ov[0], ov[1], ov[2], ov[3]);
    op[1] = make_float4(ov[4], ov[5], ov[6], ov[7]);
}

// ---------------- log_softmax over 256 channels ----------------
__global__ void k_lsm(const float* __restrict__ X, float* __restrict__ OUT) {
    int gwarp = (blockIdx.x * blockDim.x + threadIdx.x) >> 5;
    int lane = threadIdx.x & 31;
    if (gwarp >= NNODES) return;
    int ch0 = lane * 8;
    const float4* xp = (const float4*)(X + (size_t)gwarp * FDIM + ch0);
    float4 v0 = xp[0], v1 = xp[1];
    float v[8] = {v0.x, v0.y, v0.z, v0.w, v1.x, v1.y, v1.z, v1.w};
    float mx = v[0];
#pragma unroll
    for (int j = 1; j < 8; j++) mx = fmaxf(mx, v[j]);
#pragma unroll
    for (int off = 16; off > 0; off >>= 1) mx = fmaxf(mx, __shfl_xor_sync(0xffffffffu, mx, off));
    float se = 0.f;
#pragma unroll
    for (int j = 0; j < 8; j++) se += __expf(v[j] - mx);
#pragma unroll
    for (int off = 16; off > 0; off >>= 1) se += __shfl_xor_sync(0xffffffffu, se, off);
    float lse = mx + logf(se);
    float4* op = (float4*)(OUT + (size_t)gwarp * FDIM + ch0);
    op[0] = make_float4(v[0] - lse, v[1] - lse, v[2] - lse, v[3] - lse);
    op[1] = make_float4(v[4] - lse, v[5] - lse, v[6] - lse, v[7] - lse);
}

// ---------------- launch ----------------
extern "C" void kernel_launch(void* const* d_in, const int* in_sizes, int n_in,
                              void* d_out, int out_size) {
    const float* x    = (const float*)d_in[0];
    const int*   ei   = (const int*)d_in[1];
    const float* W1   = (const float*)d_in[2];
    const float* as1  = (const float*)d_in[3];
    const float* ad1  = (const float*)d_in[4];
    const float* b1   = (const float*)d_in[5];
    const float* gam1 = (const float*)d_in[6];
    const float* be1  = (const float*)d_in[7];
    const float* m1   = (const float*)d_in[8];
    const float* v1   = (const float*)d_in[9];
    const float* W2   = (const float*)d_in[10];
    const float* as2  = (const float*)d_in[11];
    const float* ad2  = (const float*)d_in[12];
    const float* b2   = (const float*)d_in[13];
    const float* gam2 = (const float*)d_in[14];
    const float* be2  = (const float*)d_in[15];
    const float* m2   = (const float*)d_in[16];
    const float* v2   = (const float*)d_in[17];
    float* out = (float*)d_out;

    float *bufA, *bufB;
    cudaGetSymbolAddress((void**)&bufA, g_bufA);
    cudaGetSymbolAddress((void**)&bufB, g_bufB);

    // ---- CSR build (per call; deterministic after sort) ----
    k_init_deg<<<(NNODES + 255) / 256, 256>>>();
    k_count<<<(NEDGES + 255) / 256, 256>>>(ei);
    k_scan1<<<NB_SCAN, 512>>>();
    k_scan2<<<1, 32>>>();
    k_scan3<<<(NNODES + 255) / 256, 256>>>();
    k_fill_init<<<(NNODES + 255) / 256, 256>>>();
    k_fill<<<(NEDGES + 255) / 256, 256>>>(ei);
    k_sort<<<(NNODES + 255) / 256, 256>>>();

    dim3 ggrid(FDIM / 128, (NNODES + 127) / 128);
    int nodeBlocks = (NNODES + 7) / 8;   // one warp per node, 8 warps/block

    // ---- layer 1 ----
    k_sgemm<<<ggrid, 256>>>(x, W1, bufA, NNODES, FDIM, 128);
    k_attn<<<nodeBlocks, 256>>>(bufA, as1, ad1);
    k_agg<<<nodeBlocks, 256>>>(bufA, b1, gam1, be1, m1, v1, bufB);

    // ---- layer 2 ----
    k_sgemm<<<ggrid, 256>>>(bufB, W2, bufA, NNODES, FDIM, FDIM);
    k_attn<<<nodeBlocks, 256>>>(bufA, as2, ad2);
    k_agg<<<nodeBlocks, 256>>>(bufA, b2, gam2, be2, m2, v2, bufB);

    // ---- log_softmax ----
    k_lsm<<<nodeBlocks, 256>>>(bufB, out);
}

// round 3
// speedup vs baseline: 1.3036x; 1.3036x over previous
#include <cuda_runtime.h>
#include <cuda_bf16.h>
#include <math.h>
#include <stdint.h>

#define NNODES 50000
#define NEDGES 800000
#define FDIM   256          // H*C
#define TOTE   (NEDGES + NNODES)
#define NB_SCAN ((NNODES + 511) / 512)

// ---------------- scratch (static device globals; no allocation) ----------------
__device__ float g_bufA[(size_t)NNODES * FDIM];   // 51.2 MB
__device__ float g_bufB[(size_t)NNODES * FDIM];   // 51.2 MB
__device__ float g_asrcv[NNODES * 4];
__device__ float g_adstv[NNODES * 4];
__device__ int   g_deg[NNODES];
__device__ int   g_rowptr[NNODES + 1];
__device__ int   g_cursor[NNODES];
__device__ int   g_srclist[TOTE];
__device__ int   g_blksums[256];
// pre-split weights: bf16 hi/lo, row-major [K][256] (max K=256)
__device__ __nv_bfloat16 g_Bh[65536];
__device__ __nv_bfloat16 g_Bl[65536];

// ---------------- PTX helpers (portable: sm_80+ instructions only) ----------------
__device__ __forceinline__ uint32_t s2u(const void* p) {
    uint32_t a;
    asm("{ .reg .u64 t; cvta.to.shared.u64 t, %1; cvt.u32.u64 %0, t; }" : "=r"(a) : "l"(p));
    return a;
}

__device__ __forceinline__ void ldsm4(uint32_t* r, uint32_t addr) {
    asm volatile("ldmatrix.sync.aligned.m8n8.x4.shared.b16 {%0,%1,%2,%3}, [%4];"
                 : "=r"(r[0]), "=r"(r[1]), "=r"(r[2]), "=r"(r[3]) : "r"(addr));
}

__device__ __forceinline__ void ldsm4t(uint32_t* r, uint32_t addr) {
    asm volatile("ldmatrix.sync.aligned.m8n8.x4.trans.shared.b16 {%0,%1,%2,%3}, [%4];"
                 : "=r"(r[0]), "=r"(r[1]), "=r"(r[2]), "=r"(r[3]) : "r"(addr));
}

__device__ __forceinline__ void mma16816(float* d, const uint32_t* a, const uint32_t* b) {
    asm volatile("mma.sync.aligned.m16n8k16.row.col.f32.bf16.bf16.f32 "
                 "{%0,%1,%2,%3}, {%4,%5,%6,%7}, {%8,%9}, {%0,%1,%2,%3};"
                 : "+f"(d[0]), "+f"(d[1]), "+f"(d[2]), "+f"(d[3])
                 : "r"(a[0]), "r"(a[1]), "r"(a[2]), "r"(a[3]), "r"(b[0]), "r"(b[1]));
}

__device__ __forceinline__ uint32_t pack_bf16(float x, float y) {
    __nv_bfloat16 hx = __float2bfloat16_rn(x);
    __nv_bfloat16 hy = __float2bfloat16_rn(y);
    return (uint32_t)__bfloat16_as_ushort(hx) | ((uint32_t)__bfloat16_as_ushort(hy) << 16);
}

// ---------------- CSR build ----------------
__global__ void k_init_deg() {
    int i = blockIdx.x * blockDim.x + threadIdx.x;
    if (i < NNODES) g_deg[i] = 1;   // self loop
}

__global__ void k_count(const int* __restrict__ ei) {
    int i = blockIdx.x * blockDim.x + threadIdx.x;
    if (i < NEDGES) atomicAdd(&g_deg[ei[NEDGES + i]], 1);
}

__global__ void k_scan1() {
    __shared__ int s[512];
    int tid = threadIdx.x;
    int i = blockIdx.x * 512 + tid;
    int v = (i < NNODES) ? g_deg[i] : 0;
    s[tid] = v;
    __syncthreads();
    for (int off = 1; off < 512; off <<= 1) {
        int t = (tid >= off) ? s[tid - off] : 0;
        __syncthreads();
        s[tid] += t;
        __syncthreads();
    }
    if (i < NNODES) g_rowptr[i] = s[tid] - v;
    if (tid == 511) g_blksums[blockIdx.x] = s[511];
}

__global__ void k_scan2() {
    if (threadIdx.x == 0 && blockIdx.x == 0) {
        int run = 0;
        for (int b = 0; b < NB_SCAN; b++) {
            int t = g_blksums[b];
            g_blksums[b] = run;
            run += t;
        }
    }
}

__global__ void k_scan3() {
    int i = blockIdx.x * blockDim.x + threadIdx.x;
    if (i < NNODES) g_rowptr[i] += g_blksums[i >> 9];
    if (i == 0) g_rowptr[NNODES] = TOTE;
}

__global__ void k_fill_init() {
    int n = blockIdx.x * blockDim.x + threadIdx.x;
    if (n < NNODES) {
        int r = g_rowptr[n];
        g_srclist[r] = n;
        g_cursor[n] = r + 1;
    }
}

__global__ void k_fill(const int* __restrict__ ei) {
    int i = blockIdx.x * blockDim.x + threadIdx.x;
    if (i < NEDGES) {
        int s = ei[i];
        int d = ei[NEDGES + i];
        int pos = atomicAdd(&g_cursor[d], 1);
        g_srclist[pos] = s;
    }
}

__global__ void k_sort() {
    int n = blockIdx.x * blockDim.x + threadIdx.x;
    if (n >= NNODES) return;
    int beg = g_rowptr[n] + 1;
    int end = g_rowptr[n + 1];
    for (int i = beg + 1; i < end; i++) {
        int key = g_srclist[i];
        int j = i - 1;
        while (j >= beg && g_srclist[j] > key) {
            g_srclist[j + 1] = g_srclist[j];
            j--;
        }
        g_srclist[j + 1] = key;
    }
}

// ---------------- weight split: W[K,256] fp32 -> bf16 hi/lo (row-major) ----------------
__global__ void k_prepB(const float* __restrict__ W, int total) {
    int i = blockIdx.x * 256 + threadIdx.x;
    if (i >= total) return;
    float v = W[i];
    __nv_bfloat16 h = __float2bfloat16_rn(v);
    g_Bh[i] = h;
    g_Bl[i] = __float2bfloat16_rn(v - __bfloat162float(h));
}

// ---------------- tensor-core GEMM via mma.sync ----------------
// C[M,256] = A[M,K] * W[K,256]; A fp32 split to bf16 hi/lo in-flight,
// W pre-split in g_Bh/g_Bl. 3-product compensation: AhBh + AhBl + AlBh.
// CTA tile 128x128, 8 warps (4x2), warp tile 32x64, BK=32 fp32 cols/chunk.
__global__ void __launch_bounds__(256) k_gemm_mma(const float* __restrict__ A,
                                                  float* __restrict__ C, int K) {
    __shared__ __nv_bfloat16 sAh[128][40];
    __shared__ __nv_bfloat16 sAl[128][40];
    __shared__ __nv_bfloat16 sBh[32][136];
    __shared__ __nv_bfloat16 sBl[32][136];

    int tid = threadIdx.x;
    int lane = tid & 31, w = tid >> 5;
    int wm = w & 3, wn = w >> 2;          // warp tile origin (wm*32, wn*64)
    int bx = blockIdx.x, by = blockIdx.y;
    int nch = K >> 5;

    float acc[2][8][4];
#pragma unroll
    for (int i = 0; i < 2; i++)
#pragma unroll
        for (int j = 0; j < 8; j++)
#pragma unroll
            for (int q = 0; q < 4; q++) acc[i][j][q] = 0.f;

    // prefetch registers
    float4 pa[4];
    uint4 pbh[2], pbl[2];

    // ---- load chunk 0 ----
#pragma unroll
    for (int i = 0; i < 4; i++) {
        int p = tid + 256 * i;
        int r = p >> 3, c = (p & 7) * 4;
        int gr = by * 128 + r;
        pa[i] = (gr < NNODES) ? *(const float4*)(A + (size_t)gr * K + c)
                              : make_float4(0.f, 0.f, 0.f, 0.f);
    }
#pragma unroll
    for (int i = 0; i < 2; i++) {
        int p = tid + 256 * i;
        int r = p >> 4, c = (p & 15) * 8;
        size_t off = (size_t)r * 256 + bx * 128 + c;
        pbh[i] = *(const uint4*)(g_Bh + off);
        pbl[i] = *(const uint4*)(g_Bl + off);
    }

    for (int kc = 0; kc < nch; kc++) {
        __syncthreads();   // previous compute done; smem free
        // ---- store prefetched chunk to smem (convert A) ----
#pragma unroll
        for (int i = 0; i < 4; i++) {
            int p = tid + 256 * i;
            int r = p >> 3, c = (p & 7) * 4;
            float4 f = pa[i];
            uint32_t h0 = pack_bf16(f.x, f.y), h1 = pack_bf16(f.z, f.w);
            float rx = f.x - __bfloat162float(__float2bfloat16_rn(f.x));
            float ry = f.y - __bfloat162float(__float2bfloat16_rn(f.y));
            float rz = f.z - __bfloat162float(__float2bfloat16_rn(f.z));
            float rw = f.w - __bfloat162float(__float2bfloat16_rn(f.w));
            uint32_t l0 = pack_bf16(rx, ry), l1 = pack_bf16(rz, rw);
            *(uint2*)&sAh[r][c] = make_uint2(h0, h1);
            *(uint2*)&sAl[r][c] = make_uint2(l0, l1);
        }
#pragma unroll
        for (int i = 0; i < 2; i++) {
            int p = tid + 256 * i;
            int r = p >> 4, c = (p & 15) * 8;
            *(uint4*)&sBh[r][c] = pbh[i];
            *(uint4*)&sBl[r][c] = pbl[i];
        }
        __syncthreads();

        // ---- issue prefetch for next chunk (overlaps with MMA below) ----
        if (kc + 1 < nch) {
            int kof = (kc + 1) * 32;
#pragma unroll
            for (int i = 0; i < 4; i++) {
                int p = tid + 256 * i;
                int r = p >> 3, c = (p & 7) * 4;
                int gr = by * 128 + r;
                pa[i] = (gr < NNODES) ? *(const float4*)(A + (size_t)gr * K + kof + c)
                                      : make_float4(0.f, 0.f, 0.f, 0.f);
            }
#pragma unroll
            for (int i = 0; i < 2; i++) {
                int p = tid + 256 * i;
                int r = p >> 4, c = (p & 15) * 8;
                size_t off = (size_t)(kof + r) * 256 + bx * 128 + c;
                pbh[i] = *(const uint4*)(g_Bh + off);
                pbl[i] = *(const uint4*)(g_Bl + off);
            }
        }

        // ---- compute: 2 k-steps of 16 ----
#pragma unroll
        for (int ks = 0; ks < 2; ks++) {
            uint32_t ah[2][4], al[2][4], bh[4][4], bl[4][4];
#pragma unroll
            for (int mt = 0; mt < 2; mt++) {
                int row = wm * 32 + mt * 16 + (lane & 15);
                int col = ks * 16 + (lane >> 4) * 8;
                ldsm4(ah[mt], s2u(&sAh[row][col]));
                ldsm4(al[mt], s2u(&sAl[row][col]));
            }
#pragma unroll
            for (int nt = 0; nt < 4; nt++) {
                int row = ks * 16 + (lane & 15);
                int col = wn * 64 + nt * 16 + (lane >> 4) * 8;
                ldsm4t(bh[nt], s2u(&sBh[row][col]));
                ldsm4t(bl[nt], s2u(&sBl[row][col]));
            }
#pragma unroll
            for (int mt = 0; mt < 2; mt++)
#pragma unroll
                for (int nt = 0; nt < 4; nt++)
#pragma unroll
                    for (int h = 0; h < 2; h++) {
                        float* d = acc[mt][nt * 2 + h];
                        mma16816(d, ah[mt], &bh[nt][h * 2]);
                        mma16816(d, ah[mt], &bl[nt][h * 2]);
                        mma16816(d, al[mt], &bh[nt][h * 2]);
                    }
        }
    }

    // ---- epilogue: write fp32 C ----
#pragma unroll
    for (int mt = 0; mt < 2; mt++) {
        int r0 = by * 128 + wm * 32 + mt * 16 + (lane >> 2);
#pragma unroll
        for (int nt = 0; nt < 8; nt++) {
            int cc = bx * 128 + wn * 64 + nt * 8 + (lane & 3) * 2;
            if (r0 < NNODES) {
                float2* p0 = (float2*)(C + (size_t)r0 * FDIM + cc);
                *p0 = make_float2(acc[mt][nt][0], acc[mt][nt][1]);
            }
            if (r0 + 8 < NNODES) {
                float2* p1 = (float2*)(C + (size_t)(r0 + 8) * FDIM + cc);
                *p1 = make_float2(acc[mt][nt][2], acc[mt][nt][3]);
            }
        }
    }
}

// ---------------- per-node attention dot products ----------------
__global__ void k_attn(const float* __restrict__ X,
                       const float* __restrict__ a_src,
                       const float* __restrict__ a_dst) {
    int gwarp = (blockIdx.x * blockDim.x + threadIdx.x) >> 5;
    int lane = threadIdx.x & 31;
    if (gwarp >= NNODES) return;
    int ch0 = lane * 8;
    const float4* xp = (const float4*)(X + (size_t)gwarp * FDIM + ch0);
    float4 v0 = xp[0], v1 = xp[1];
    const float4* sp = (const float4*)(a_src + ch0);
    const float4* dp = (const float4*)(a_dst + ch0);
    float4 s0 = sp[0], s1 = sp[1];
    float4 d0 = dp[0], d1 = dp[1];
    float ps = v0.x * s0.x + v0.y * s0.y + v0.z * s0.z + v0.w * s0.w
             + v1.x * s1.x + v1.y * s1.y + v1.z * s1.z + v1.w * s1.w;
    float pd = v0.x * d0.x + v0.y * d0.y + v0.z * d0.z + v0.w * d0.w
             + v1.x * d1.x + v1.y * d1.y + v1.z * d1.z + v1.w * d1.w;
#pragma unroll
    for (int off = 4; off > 0; off >>= 1) {
        ps += __shfl_down_sync(0xffffffffu, ps, off, 8);
        pd += __shfl_down_sync(0xffffffffu, pd, off, 8);
    }
    if ((lane & 7) == 0) {
        int h = lane >> 3;
        g_asrcv[gwarp * 4 + h] = ps;
        g_adstv[gwarp * 4 + h] = pd;
    }
}

// ---------------- GAT aggregation (online softmax) + bias + BN + ReLU ----------------
__global__ void k_agg(const float* __restrict__ X,
                      const float* __restrict__ bias,
                      const float* __restrict__ gam,
                      const float* __restrict__ bet,
                      const float* __restrict__ mu,
                      const float* __restrict__ var,
                      float* __restrict__ OUT) {
    int gwarp = (blockIdx.x * blockDim.x + threadIdx.x) >> 5;
    int lane = threadIdx.x & 31;
    if (gwarp >= NNODES) return;
    int n = gwarp;
    int ch0 = lane * 8;
    int hl = lane >> 3;

    float m = -1e30f, dsum = 0.f;
    float acc[8];
#pragma unroll
    for (int j = 0; j < 8; j++) acc[j] = 0.f;

    float adv = g_adstv[n * 4 + hl];
    int r0 = g_rowptr[n], r1 = g_rowptr[n + 1];

    for (int k = r0; k < r1; k++) {
        int s = g_srclist[k];
        float e = g_asrcv[s * 4 + hl] + adv;
        e = (e > 0.f) ? e : 0.2f * e;
        float mn = fmaxf(m, e);
        float sc = __expf(m - mn);
        float p  = __expf(e - mn);
        dsum = dsum * sc + p;
        const float4* hp = (const float4*)(X + (size_t)s * FDIM + ch0);
        float4 v0 = hp[0], v1 = hp[1];
        acc[0] = acc[0] * sc + p * v0.x;
        acc[1] = acc[1] * sc + p * v0.y;
        acc[2] = acc[2] * sc + p * v0.z;
        acc[3] = acc[3] * sc + p * v0.w;
        acc[4] = acc[4] * sc + p * v1.x;
        acc[5] = acc[5] * sc + p * v1.y;
        acc[6] = acc[6] * sc + p * v1.z;
        acc[7] = acc[7] * sc + p * v1.w;
        m = mn;
    }

    float inv = 1.f / (dsum + 1e-16f);
    float ov[8];
#pragma unroll
    for (int j = 0; j < 8; j++) {
        int ch = ch0 + j;
        float val = acc[j] * inv + bias[ch];
        val = (val - mu[ch]) * rsqrtf(var[ch] + 1e-5f) * gam[ch] + bet[ch];
        ov[j] = fmaxf(val, 0.f);
    }
    float4* op = (float4*)(OUT + (size_t)n * FDIM + ch0);
    op[0] = make_float4(ov[0], ov[1], ov[2], ov[3]);
    op[1] = make_float4(ov[4], ov[5], ov[6], ov[7]);
}

// ---------------- layer-2 aggregation fused with log_softmax ----------------
__global__ void k_agg_lsm(const float* __restrict__ X,
                          const float* __restrict__ bias,
                          const float* __restrict__ gam,
                          const float* __restrict__ bet,
                          const float* __restrict__ mu,
                          const float* __restrict__ var,
                          float* __restrict__ OUT) {
    int gwarp = (blockIdx.x * blockDim.x + threadIdx.x) >> 5;
    int lane = threadIdx.x & 31;
    if (gwarp >= NNODES) return;
    int n = gwarp;
    int ch0 = lane * 8;
    int hl = lane >> 3;

    float m = -1e30f, dsum = 0.f;
    float acc[8];
#pragma unroll
    for (int j = 0; j < 8; j++) acc[j] = 0.f;

    float adv = g_adstv[n * 4 + hl];
    int r0 = g_rowptr[n], r1 = g_rowptr[n + 1];

    for (int k = r0; k < r1; k++) {
        int s = g_srclist[k];
        float e = g_asrcv[s * 4 + hl] + adv;
        e = (e > 0.f) ? e : 0.2f * e;
        float mn = fmaxf(m, e);
        float sc = __expf(m - mn);
        float p  = __expf(e - mn);
        dsum = dsum * sc + p;
        const float4* hp = (const float4*)(X + (size_t)s * FDIM + ch0);
        float4 v0 = hp[0], v1 = hp[1];
        acc[0] = acc[0] * sc + p * v0.x;
        acc[1] = acc[1] * sc + p * v0.y;
        acc[2] = acc[2] * sc + p * v0.z;
        acc[3] = acc[3] * sc + p * v0.w;
        acc[4] = acc[4] * sc + p * v1.x;
        acc[5] = acc[5] * sc + p * v1.y;
        acc[6] = acc[6] * sc + p * v1.z;
        acc[7] = acc[7] * sc + p * v1.w;
        m = mn;
    }

    float inv = 1.f / (dsum + 1e-16f);
    float ov[8];
#pragma unroll
    for (int j = 0; j < 8; j++) {
        int ch = ch0 + j;
        float val = acc[j] * inv + bias[ch];
        val = (val - mu[ch]) * rsqrtf(var[ch] + 1e-5f) * gam[ch] + bet[ch];
        ov[j] = fmaxf(val, 0.f);
    }
    // fused log_softmax over the warp's 256 channels
    float mx = ov[0];
#pragma unroll
    for (int j = 1; j < 8; j++) mx = fmaxf(mx, ov[j]);
#pragma unroll
    for (int off = 16; off > 0; off >>= 1) mx = fmaxf(mx, __shfl_xor_sync(0xffffffffu, mx, off));
    float se = 0.f;
#pragma unroll
    for (int j = 0; j < 8; j++) se += __expf(ov[j] - mx);
#pragma unroll
    for (int off = 16; off > 0; off >>= 1) se += __shfl_xor_sync(0xffffffffu, se, off);
    float lse = mx + logf(se);

    float4* op = (float4*)(OUT + (size_t)n * FDIM + ch0);
    op[0] = make_float4(ov[0] - lse, ov[1] - lse, ov[2] - lse, ov[3] - lse);
    op[1] = make_float4(ov[4] - lse, ov[5] - lse, ov[6] - lse, ov[7] - lse);
}

// ---------------- launch ----------------
extern "C" void kernel_launch(void* const* d_in, const int* in_sizes, int n_in,
                              void* d_out, int out_size) {
    const float* x    = (const float*)d_in[0];
    const int*   ei   = (const int*)d_in[1];
    const float* W1   = (const float*)d_in[2];
    const float* as1  = (const float*)d_in[3];
    const float* ad1  = (const float*)d_in[4];
    const float* b1   = (const float*)d_in[5];
    const float* gam1 = (const float*)d_in[6];
    const float* be1  = (const float*)d_in[7];
    const float* m1   = (const float*)d_in[8];
    const float* v1   = (const float*)d_in[9];
    const float* W2   = (const float*)d_in[10];
    const float* as2  = (const float*)d_in[11];
    const float* ad2  = (const float*)d_in[12];
    const float* b2   = (const float*)d_in[13];
    const float* gam2 = (const float*)d_in[14];
    const float* be2  = (const float*)d_in[15];
    const float* m2   = (const float*)d_in[16];
    const float* v2   = (const float*)d_in[17];
    float* out = (float*)d_out;

    float *bufA, *bufB;
    cudaGetSymbolAddress((void**)&bufA, g_bufA);
    cudaGetSymbolAddress((void**)&bufB, g_bufB);

    // ---- CSR build (per call; deterministic after sort) ----
    k_init_deg<<<(NNODES + 255) / 256, 256>>>();
    k_count<<<(NEDGES + 255) / 256, 256>>>(ei);
    k_scan1<<<NB_SCAN, 512>>>();
    k_scan2<<<1, 32>>>();
    k_scan3<<<(NNODES + 255) / 256, 256>>>();
    k_fill_init<<<(NNODES + 255) / 256, 256>>>();
    k_fill<<<(NEDGES + 255) / 256, 256>>>(ei);
    k_sort<<<(NNODES + 255) / 256, 256>>>();

    dim3 ggrid(2, (NNODES + 127) / 128);
    int nodeBlocks = (NNODES + 7) / 8;

    // ---- layer 1 ----
    k_prepB<<<(128 * 256 + 255) / 256, 256>>>(W1, 128 * 256);
    k_gemm_mma<<<ggrid, 256>>>(x, bufA, 128);
    k_attn<<<nodeBlocks, 256>>>(bufA, as1, ad1);
    k_agg<<<nodeBlocks, 256>>>(bufA, b1, gam1, be1, m1, v1, bufB);

    // ---- layer 2 ----
    k_prepB<<<(256 * 256 + 255) / 256, 256>>>(W2, 256 * 256);
    k_gemm_mma<<<ggrid, 256>>>(bufB, bufA, 256);
    k_attn<<<nodeBlocks, 256>>>(bufA, as2, ad2);
    k_agg_lsm<<<nodeBlocks, 256>>>(bufA, b2, gam2, be2, m2, v2, out);
}

// round 4
// speedup vs baseline: 1.3389x; 1.0271x over previous
#include <cuda_runtime.h>
#include <cuda_bf16.h>
#include <math.h>
#include <stdint.h>

#define NNODES 50000
#define NEDGES 800000
#define FDIM   256          // H*C
#define TOTE   (NEDGES + NNODES)
#define NB_SCAN ((NNODES + 511) / 512)

// ---------------- scratch (static device globals; no allocation) ----------------
__device__ float g_bufA[(size_t)NNODES * FDIM];   // 51.2 MB
__device__ float g_bufB[(size_t)NNODES * FDIM];   // 51.2 MB
__device__ float g_asrcv[NNODES * 4];
__device__ float g_adstv[NNODES * 4];
__device__ int   g_deg[NNODES];
__device__ int   g_rowptr[NNODES + 1];
__device__ int   g_cursor[NNODES];
__device__ int   g_srclist[TOTE];
__device__ int   g_blksums[256];
// pre-split weights: bf16 hi/lo, row-major [K][256] (max K=256)
__device__ __nv_bfloat16 g_Bh[65536];
__device__ __nv_bfloat16 g_Bl[65536];

// ---------------- PTX helpers (portable: sm_80+ instructions only) ----------------
__device__ __forceinline__ uint32_t s2u(const void* p) {
    uint32_t a;
    asm("{ .reg .u64 t; cvta.to.shared.u64 t, %1; cvt.u32.u64 %0, t; }" : "=r"(a) : "l"(p));
    return a;
}

__device__ __forceinline__ void ldsm4(uint32_t* r, uint32_t addr) {
    asm volatile("ldmatrix.sync.aligned.m8n8.x4.shared.b16 {%0,%1,%2,%3}, [%4];"
                 : "=r"(r[0]), "=r"(r[1]), "=r"(r[2]), "=r"(r[3]) : "r"(addr));
}

__device__ __forceinline__ void ldsm4t(uint32_t* r, uint32_t addr) {
    asm volatile("ldmatrix.sync.aligned.m8n8.x4.trans.shared.b16 {%0,%1,%2,%3}, [%4];"
                 : "=r"(r[0]), "=r"(r[1]), "=r"(r[2]), "=r"(r[3]) : "r"(addr));
}

__device__ __forceinline__ void mma16816(float* d, const uint32_t* a, const uint32_t* b) {
    asm volatile("mma.sync.aligned.m16n8k16.row.col.f32.bf16.bf16.f32 "
                 "{%0,%1,%2,%3}, {%4,%5,%6,%7}, {%8,%9}, {%0,%1,%2,%3};"
                 : "+f"(d[0]), "+f"(d[1]), "+f"(d[2]), "+f"(d[3])
                 : "r"(a[0]), "r"(a[1]), "r"(a[2]), "r"(a[3]), "r"(b[0]), "r"(b[1]));
}

__device__ __forceinline__ uint32_t pack_bf16(float x, float y) {
    __nv_bfloat16 hx = __float2bfloat16_rn(x);
    __nv_bfloat16 hy = __float2bfloat16_rn(y);
    return (uint32_t)__bfloat16_as_ushort(hx) | ((uint32_t)__bfloat16_as_ushort(hy) << 16);
}

// ---------------- CSR build ----------------
__global__ void k_init_deg() {
    int i = blockIdx.x * blockDim.x + threadIdx.x;
    if (i < NNODES) g_deg[i] = 1;   // self loop
}

__global__ void k_count(const int* __restrict__ ei) {
    int i = blockIdx.x * blockDim.x + threadIdx.x;
    if (i < NEDGES) atomicAdd(&g_deg[ei[NEDGES + i]], 1);
}

__global__ void k_scan1() {
    __shared__ int s[512];
    int tid = threadIdx.x;
    int i = blockIdx.x * 512 + tid;
    int v = (i < NNODES) ? g_deg[i] : 0;
    s[tid] = v;
    __syncthreads();
    for (int off = 1; off < 512; off <<= 1) {
        int t = (tid >= off) ? s[tid - off] : 0;
        __syncthreads();
        s[tid] += t;
        __syncthreads();
    }
    if (i < NNODES) g_rowptr[i] = s[tid] - v;
    if (tid == 511) g_blksums[blockIdx.x] = s[511];
}

__global__ void k_scan2() {
    if (threadIdx.x == 0 && blockIdx.x == 0) {
        int run = 0;
        for (int b = 0; b < NB_SCAN; b++) {
            int t = g_blksums[b];
            g_blksums[b] = run;
            run += t;
        }
    }
}

// fused: finalize rowptr + seed self-loop + init cursor
__global__ void k_scan3f() {
    int i = blockIdx.x * blockDim.x + threadIdx.x;
    if (i < NNODES) {
        int r = g_rowptr[i] + g_blksums[i >> 9];
        g_rowptr[i] = r;
        g_srclist[r] = i;        // self loop first
        g_cursor[i] = r + 1;
    }
    if (i == 0) g_rowptr[NNODES] = TOTE;
}

__global__ void k_fill(const int* __restrict__ ei) {
    int i = blockIdx.x * blockDim.x + threadIdx.x;
    if (i < NEDGES) {
        int s = ei[i];
        int d = ei[NEDGES + i];
        int pos = atomicAdd(&g_cursor[d], 1);
        g_srclist[pos] = s;
    }
}

__global__ void k_sort() {
    int n = blockIdx.x * blockDim.x + threadIdx.x;
    if (n >= NNODES) return;
    int beg = g_rowptr[n] + 1;
    int end = g_rowptr[n + 1];
    for (int i = beg + 1; i < end; i++) {
        int key = g_srclist[i];
        int j = i - 1;
        while (j >= beg && g_srclist[j] > key) {
            g_srclist[j + 1] = g_srclist[j];
            j--;
        }
        g_srclist[j + 1] = key;
    }
}

// ---------------- weight split: W[K,256] fp32 -> bf16 hi/lo (row-major) ----------------
__global__ void k_prepB(const float* __restrict__ W, int total) {
    int i = blockIdx.x * 256 + threadIdx.x;
    if (i >= total) return;
    float v = W[i];
    __nv_bfloat16 h = __float2bfloat16_rn(v);
    g_Bh[i] = h;
    g_Bl[i] = __float2bfloat16_rn(v - __bfloat162float(h));
}

// ---------------- tensor-core GEMM via mma.sync, fused attention-dot epilogue ----------------
// C[M,256] = A[M,K] * W[K,256]; 3-product bf16 compensation.
// CTA tile 128x128, 8 warps (4x2), warp tile 32x64. Each warp tile spans exactly
// one GAT head (64 channels), so asrc/adst dots reduce in-register.
__global__ void __launch_bounds__(256) k_gemm_mma(const float* __restrict__ A,
                                                  float* __restrict__ C, int K,
                                                  const float* __restrict__ Asrc,
                                                  const float* __restrict__ Adst) {
    __shared__ __nv_bfloat16 sAh[128][40];
    __shared__ __nv_bfloat16 sAl[128][40];
    __shared__ __nv_bfloat16 sBh[32][136];
    __shared__ __nv_bfloat16 sBl[32][136];

    int tid = threadIdx.x;
    int lane = tid & 31, w = tid >> 5;
    int wm = w & 3, wn = w >> 2;          // warp tile origin (wm*32, wn*64)
    int bx = blockIdx.x, by = blockIdx.y;
    int nch = K >> 5;

    float acc[2][8][4];
#pragma unroll
    for (int i = 0; i < 2; i++)
#pragma unroll
        for (int j = 0; j < 8; j++)
#pragma unroll
            for (int q = 0; q < 4; q++) acc[i][j][q] = 0.f;

    float4 pa[4];
    uint4 pbh[2], pbl[2];

    // ---- load chunk 0 ----
#pragma unroll
    for (int i = 0; i < 4; i++) {
        int p = tid + 256 * i;
        int r = p >> 3, c = (p & 7) * 4;
        int gr = by * 128 + r;
        pa[i] = (gr < NNODES) ? *(const float4*)(A + (size_t)gr * K + c)
                              : make_float4(0.f, 0.f, 0.f, 0.f);
    }
#pragma unroll
    for (int i = 0; i < 2; i++) {
        int p = tid + 256 * i;
        int r = p >> 4, c = (p & 15) * 8;
        size_t off = (size_t)r * 256 + bx * 128 + c;
        pbh[i] = *(const uint4*)(g_Bh + off);
        pbl[i] = *(const uint4*)(g_Bl + off);
    }

    for (int kc = 0; kc < nch; kc++) {
        __syncthreads();
#pragma unroll
        for (int i = 0; i < 4; i++) {
            int p = tid + 256 * i;
            int r = p >> 3, c = (p & 7) * 4;
            float4 f = pa[i];
            uint32_t h0 = pack_bf16(f.x, f.y), h1 = pack_bf16(f.z, f.w);
            float rx = f.x - __bfloat162float(__float2bfloat16_rn(f.x));
            float ry = f.y - __bfloat162float(__float2bfloat16_rn(f.y));
            float rz = f.z - __bfloat162float(__float2bfloat16_rn(f.z));
            float rw = f.w - __bfloat162float(__float2bfloat16_rn(f.w));
            uint32_t l0 = pack_bf16(rx, ry), l1 = pack_bf16(rz, rw);
            *(uint2*)&sAh[r][c] = make_uint2(h0, h1);
            *(uint2*)&sAl[r][c] = make_uint2(l0, l1);
        }
#pragma unroll
        for (int i = 0; i < 2; i++) {
            int p = tid + 256 * i;
            int r = p >> 4, c = (p & 15) * 8;
            *(uint4*)&sBh[r][c] = pbh[i];
            *(uint4*)&sBl[r][c] = pbl[i];
        }
        __syncthreads();

        if (kc + 1 < nch) {
            int kof = (kc + 1) * 32;
#pragma unroll
            for (int i = 0; i < 4; i++) {
                int p = tid + 256 * i;
                int r = p >> 3, c = (p & 7) * 4;
                int gr = by * 128 + r;
                pa[i] = (gr < NNODES) ? *(const float4*)(A + (size_t)gr * K + kof + c)
                                      : make_float4(0.f, 0.f, 0.f, 0.f);
            }
#pragma unroll
            for (int i = 0; i < 2; i++) {
                int p = tid + 256 * i;
                int r = p >> 4, c = (p & 15) * 8;
                size_t off = (size_t)(kof + r) * 256 + bx * 128 + c;
                pbh[i] = *(const uint4*)(g_Bh + off);
                pbl[i] = *(const uint4*)(g_Bl + off);
            }
        }

#pragma unroll
        for (int ks = 0; ks < 2; ks++) {
            uint32_t ah[2][4], al[2][4], bh[4][4], bl[4][4];
#pragma unroll
            for (int mt = 0; mt < 2; mt++) {
                int row = wm * 32 + mt * 16 + (lane & 15);
                int col = ks * 16 + (lane >> 4) * 8;
                ldsm4(ah[mt], s2u(&sAh[row][col]));
                ldsm4(al[mt], s2u(&sAl[row][col]));
            }
#pragma unroll
            for (int nt = 0; nt < 4; nt++) {
                int row = ks * 16 + (lane & 15);
                int col = wn * 64 + nt * 16 + (lane >> 4) * 8;
                ldsm4t(bh[nt], s2u(&sBh[row][col]));
                ldsm4t(bl[nt], s2u(&sBl[row][col]));
            }
#pragma unroll
            for (int mt = 0; mt < 2; mt++)
#pragma unroll
                for (int nt = 0; nt < 4; nt++)
#pragma unroll
                    for (int h = 0; h < 2; h++) {
                        float* d = acc[mt][nt * 2 + h];
                        mma16816(d, ah[mt], &bh[nt][h * 2]);
                        mma16816(d, ah[mt], &bl[nt][h * 2]);
                        mma16816(d, al[mt], &bh[nt][h * 2]);
                    }
        }
    }

    // ---- epilogue: write fp32 C + fused per-head attention dots ----
    int head = bx * 2 + wn;
#pragma unroll
    for (int mt = 0; mt < 2; mt++) {
        int r0 = by * 128 + wm * 32 + mt * 16 + (lane >> 2);
        float ps0 = 0.f, ps1 = 0.f, pd0 = 0.f, pd1 = 0.f;
#pragma unroll
        for (int nt = 0; nt < 8; nt++) {
            int cc = bx * 128 + wn * 64 + nt * 8 + (lane & 3) * 2;
            float as0 = Asrc[cc], as1v = Asrc[cc + 1];
            float ad0 = Adst[cc], ad1v = Adst[cc + 1];
            ps0 += acc[mt][nt][0] * as0 + acc[mt][nt][1] * as1v;
            pd0 += acc[mt][nt][0] * ad0 + acc[mt][nt][1] * ad1v;
            ps1 += acc[mt][nt][2] * as0 + acc[mt][nt][3] * as1v;
            pd1 += acc[mt][nt][2] * ad0 + acc[mt][nt][3] * ad1v;
            if (r0 < NNODES) {
                float2* p0 = (float2*)(C + (size_t)r0 * FDIM + cc);
                *p0 = make_float2(acc[mt][nt][0], acc[mt][nt][1]);
            }
            if (r0 + 8 < NNODES) {
                float2* p1 = (float2*)(C + (size_t)(r0 + 8) * FDIM + cc);
                *p1 = make_float2(acc[mt][nt][2], acc[mt][nt][3]);
            }
        }
#pragma unroll
        for (int off = 1; off <= 2; off <<= 1) {
            ps0 += __shfl_xor_sync(0xffffffffu, ps0, off);
            ps1 += __shfl_xor_sync(0xffffffffu, ps1, off);
            pd0 += __shfl_xor_sync(0xffffffffu, pd0, off);
            pd1 += __shfl_xor_sync(0xffffffffu, pd1, off);
        }
        if ((lane & 3) == 0) {
            if (r0 < NNODES) {
                g_asrcv[r0 * 4 + head] = ps0;
                g_adstv[r0 * 4 + head] = pd0;
            }
            if (r0 + 8 < NNODES) {
                g_asrcv[(r0 + 8) * 4 + head] = ps1;
                g_adstv[(r0 + 8) * 4 + head] = pd1;
            }
        }
    }
}

// ---------------- GAT aggregation: two-pass exact softmax + BN + ReLU (+opt lsm) ----------------
template <bool LSM>
__global__ void k_agg(const float* __restrict__ X,
                      const float* __restrict__ bias,
                      const float* __restrict__ gam,
                      const float* __restrict__ bet,
                      const float* __restrict__ mu,
                      const float* __restrict__ var,
                      float* __restrict__ OUT) {
    int gwarp = (blockIdx.x * blockDim.x + threadIdx.x) >> 5;
    int lane = threadIdx.x & 31;
    if (gwarp >= NNODES) return;
    int n = gwarp;
    int ch0 = lane * 8;
    int hl = lane >> 3;

    float adv = g_adstv[n * 4 + hl];
    int r0 = g_rowptr[n], r1 = g_rowptr[n + 1];

    // pass 1: exact segment max (scores only; no gather)
    float mx = -1e30f;
    for (int k = r0; k < r1; k++) {
        int s = g_srclist[k];
        float e = g_asrcv[s * 4 + hl] + adv;
        e = (e > 0.f) ? e : 0.2f * e;
        mx = fmaxf(mx, e);
    }

    // pass 2: gather + weighted sum (no rescale chain)
    float dsum = 0.f;
    float acc[8];
#pragma unroll
    for (int j = 0; j < 8; j++) acc[j] = 0.f;

    for (int k = r0; k < r1; k++) {
        int s = g_srclist[k];
        float e = g_asrcv[s * 4 + hl] + adv;
        e = (e > 0.f) ? e : 0.2f * e;
        float p = __expf(e - mx);
        dsum += p;
        const float4* hp = (const float4*)(X + (size_t)s * FDIM + ch0);
        float4 v0 = hp[0], v1 = hp[1];
        acc[0] += p * v0.x;
        acc[1] += p * v0.y;
        acc[2] += p * v0.z;
        acc[3] += p * v0.w;
        acc[4] += p * v1.x;
        acc[5] += p * v1.y;
        acc[6] += p * v1.z;
        acc[7] += p * v1.w;
    }

    float inv = 1.f / (dsum + 1e-16f);
    float ov[8];
#pragma unroll
    for (int j = 0; j < 8; j++) {
        int ch = ch0 + j;
        float val = acc[j] * inv + bias[ch];
        val = (val - mu[ch]) * rsqrtf(var[ch] + 1e-5f) * gam[ch] + bet[ch];
        ov[j] = fmaxf(val, 0.f);
    }

    if (LSM) {
        float m2 = ov[0];
#pragma unroll
        for (int j = 1; j < 8; j++) m2 = fmaxf(m2, ov[j]);
#pragma unroll
        for (int off = 16; off > 0; off >>= 1) m2 = fmaxf(m2, __shfl_xor_sync(0xffffffffu, m2, off));
        float se = 0.f;
#pragma unroll
        for (int j = 0; j < 8; j++) se += __expf(ov[j] - m2);
#pragma unroll
        for (int off = 16; off > 0; off >>= 1) se += __shfl_xor_sync(0xffffffffu, se, off);
        float lse = m2 + logf(se);
#pragma unroll
        for (int j = 0; j < 8; j++) ov[j] -= lse;
    }

    float4* op = (float4*)(OUT + (size_t)n * FDIM + ch0);
    op[0] = make_float4(ov[0], ov[1], ov[2], ov[3]);
    op[1] = make_float4(ov[4], ov[5], ov[6], ov[7]);
}

// ---------------- launch ----------------
extern "C" void kernel_launch(void* const* d_in, const int* in_sizes, int n_in,
                              void* d_out, int out_size) {
    const float* x    = (const float*)d_in[0];
    const int*   ei   = (const int*)d_in[1];
    const float* W1   = (const float*)d_in[2];
    const float* as1  = (const float*)d_in[3];
    const float* ad1  = (const float*)d_in[4];
    const float* b1   = (const float*)d_in[5];
    const float* gam1 = (const float*)d_in[6];
    const float* be1  = (const float*)d_in[7];
    const float* m1   = (const float*)d_in[8];
    const float* v1   = (const float*)d_in[9];
    const float* W2   = (const float*)d_in[10];
    const float* as2  = (const float*)d_in[11];
    const float* ad2  = (const float*)d_in[12];
    const float* b2   = (const float*)d_in[13];
    const float* gam2 = (const float*)d_in[14];
    const float* be2  = (const float*)d_in[15];
    const float* m2   = (const float*)d_in[16];
    const float* v2   = (const float*)d_in[17];
    float* out = (float*)d_out;

    float *bufA, *bufB;
    cudaGetSymbolAddress((void**)&bufA, g_bufA);
    cudaGetSymbolAddress((void**)&bufB, g_bufB);

    // ---- CSR build (per call; deterministic after sort) ----
    k_init_deg<<<(NNODES + 255) / 256, 256>>>();
    k_count<<<(NEDGES + 255) / 256, 256>>>(ei);
    k_scan1<<<NB_SCAN, 512>>>();
    k_scan2<<<1, 32>>>();
    k_scan3f<<<(NNODES + 255) / 256, 256>>>();
    k_fill<<<(NEDGES + 255) / 256, 256>>>(ei);
    k_sort<<<(NNODES + 255) / 256, 256>>>();

    dim3 ggrid(2, (NNODES + 127) / 128);
    int nodeBlocks = (NNODES + 7) / 8;

    // ---- layer 1 ----
    k_prepB<<<(128 * 256 + 255) / 256, 256>>>(W1, 128 * 256);
    k_gemm_mma<<<ggrid, 256>>>(x, bufA, 128, as1, ad1);
    k_agg<false><<<nodeBlocks, 256>>>(bufA, b1, gam1, be1, m1, v1, bufB);

    // ---- layer 2 ----
    k_prepB<<<(256 * 256 + 255) / 256, 256>>>(W2, 256 * 256);
    k_gemm_mma<<<ggrid, 256>>>(bufB, bufA, 256, as2, ad2);
    k_agg<true><<<nodeBlocks, 256>>>(bufA, b2, gam2, be2, m2, v2, out);
}

// round 5
// speedup vs baseline: 1.5691x; 1.1719x over previous
#include <cuda_runtime.h>
#include <cuda_bf16.h>
#include <cuda_fp16.h>
#include <math.h>
#include <stdint.h>

#define NNODES 50000
#define NEDGES 800000
#define FDIM   256          // H*C
#define TOTE   (NEDGES + NNODES)
#define NB_SCAN ((NNODES + 511) / 512)

// ---------------- scratch (static device globals; no allocation) ----------------
__device__ float  g_bufA[(size_t)NNODES * FDIM];   // fp32 inter-layer buffer (agg1 out)
__device__ __half g_bufH[(size_t)NNODES * FDIM];   // fp16 h image (gather source)
__device__ float g_asrcv[NNODES * 4];
__device__ float g_adstv[NNODES * 4];
__device__ int   g_deg[NNODES];
__device__ int   g_rowptr[NNODES + 1];
__device__ int   g_cursor[NNODES];
__device__ int   g_srclist[TOTE];
__device__ int   g_blksums[256];
// pre-split weights: bf16 hi/lo, row-major [K][256] (max K=256)
__device__ __nv_bfloat16 g_Bh[65536];
__device__ __nv_bfloat16 g_Bl[65536];

// ---------------- PTX helpers (portable: sm_80+ instructions only) ----------------
__device__ __forceinline__ uint32_t s2u(const void* p) {
    uint32_t a;
    asm("{ .reg .u64 t; cvta.to.shared.u64 t, %1; cvt.u32.u64 %0, t; }" : "=r"(a) : "l"(p));
    return a;
}

__device__ __forceinline__ void ldsm4(uint32_t* r, uint32_t addr) {
    asm volatile("ldmatrix.sync.aligned.m8n8.x4.shared.b16 {%0,%1,%2,%3}, [%4];"
                 : "=r"(r[0]), "=r"(r[1]), "=r"(r[2]), "=r"(r[3]) : "r"(addr));
}

__device__ __forceinline__ void ldsm4t(uint32_t* r, uint32_t addr) {
    asm volatile("ldmatrix.sync.aligned.m8n8.x4.trans.shared.b16 {%0,%1,%2,%3}, [%4];"
                 : "=r"(r[0]), "=r"(r[1]), "=r"(r[2]), "=r"(r[3]) : "r"(addr));
}

__device__ __forceinline__ void mma16816(float* d, const uint32_t* a, const uint32_t* b) {
    asm volatile("mma.sync.aligned.m16n8k16.row.col.f32.bf16.bf16.f32 "
                 "{%0,%1,%2,%3}, {%4,%5,%6,%7}, {%8,%9}, {%0,%1,%2,%3};"
                 : "+f"(d[0]), "+f"(d[1]), "+f"(d[2]), "+f"(d[3])
                 : "r"(a[0]), "r"(a[1]), "r"(a[2]), "r"(a[3]), "r"(b[0]), "r"(b[1]));
}

__device__ __forceinline__ uint32_t pack_bf16(float x, float y) {
    __nv_bfloat16 hx = __float2bfloat16_rn(x);
    __nv_bfloat16 hy = __float2bfloat16_rn(y);
    return (uint32_t)__bfloat16_as_ushort(hx) | ((uint32_t)__bfloat16_as_ushort(hy) << 16);
}

// ---------------- CSR build ----------------
__global__ void k_init_deg() {
    int i = blockIdx.x * blockDim.x + threadIdx.x;
    if (i < NNODES) g_deg[i] = 1;   // self loop
}

__global__ void k_count(const int* __restrict__ ei) {
    int i = blockIdx.x * blockDim.x + threadIdx.x;
    if (i < NEDGES) atomicAdd(&g_deg[ei[NEDGES + i]], 1);
}

__global__ void k_scan1() {
    __shared__ int s[512];
    int tid = threadIdx.x;
    int i = blockIdx.x * 512 + tid;
    int v = (i < NNODES) ? g_deg[i] : 0;
    s[tid] = v;
    __syncthreads();
    for (int off = 1; off < 512; off <<= 1) {
        int t = (tid >= off) ? s[tid - off] : 0;
        __syncthreads();
        s[tid] += t;
        __syncthreads();
    }
    if (i < NNODES) g_rowptr[i] = s[tid] - v;
    if (tid == 511) g_blksums[blockIdx.x] = s[511];
}

__global__ void k_scan2() {
    if (threadIdx.x == 0 && blockIdx.x == 0) {
        int run = 0;
        for (int b = 0; b < NB_SCAN; b++) {
            int t = g_blksums[b];
            g_blksums[b] = run;
            run += t;
        }
    }
}

// fused: finalize rowptr + seed self-loop + init cursor
__global__ void k_scan3f() {
    int i = blockIdx.x * blockDim.x + threadIdx.x;
    if (i < NNODES) {
        int r = g_rowptr[i] + g_blksums[i >> 9];
        g_rowptr[i] = r;
        g_srclist[r] = i;        // self loop first
        g_cursor[i] = r + 1;
    }
    if (i == 0) g_rowptr[NNODES] = TOTE;
}

__global__ void k_fill(const int* __restrict__ ei) {
    int i = blockIdx.x * blockDim.x + threadIdx.x;
    if (i < NEDGES) {
        int s = ei[i];
        int d = ei[NEDGES + i];
        int pos = atomicAdd(&g_cursor[d], 1);
        g_srclist[pos] = s;
    }
}

__global__ void k_sort() {
    int n = blockIdx.x * blockDim.x + threadIdx.x;
    if (n >= NNODES) return;
    int beg = g_rowptr[n] + 1;
    int end = g_rowptr[n + 1];
    for (int i = beg + 1; i < end; i++) {
        int key = g_srclist[i];
        int j = i - 1;
        while (j >= beg && g_srclist[j] > key) {
            g_srclist[j + 1] = g_srclist[j];
            j--;
        }
        g_srclist[j + 1] = key;
    }
}

// ---------------- weight split: W[K,256] fp32 -> bf16 hi/lo (row-major) ----------------
__global__ void k_prepB(const float* __restrict__ W, int total) {
    int i = blockIdx.x * 256 + threadIdx.x;
    if (i >= total) return;
    float v = W[i];
    __nv_bfloat16 h = __float2bfloat16_rn(v);
    g_Bh[i] = h;
    g_Bl[i] = __float2bfloat16_rn(v - __bfloat162float(h));
}

// ---------------- tensor-core GEMM via mma.sync, fused attention dots, fp16 output ----------------
// H[M,256] = fp16(A[M,K] * W[K,256]); 3-product bf16 compensation, fp32 accum.
// CTA tile 128x128, 8 warps (4x2), warp tile 32x64 = one GAT head.
__global__ void __launch_bounds__(256) k_gemm_mma(const float* __restrict__ A,
                                                  __half* __restrict__ H, int K,
                                                  const float* __restrict__ Asrc,
                                                  const float* __restrict__ Adst) {
    __shared__ __nv_bfloat16 sAh[128][40];
    __shared__ __nv_bfloat16 sAl[128][40];
    __shared__ __nv_bfloat16 sBh[32][136];
    __shared__ __nv_bfloat16 sBl[32][136];

    int tid = threadIdx.x;
    int lane = tid & 31, w = tid >> 5;
    int wm = w & 3, wn = w >> 2;          // warp tile origin (wm*32, wn*64)
    int bx = blockIdx.x, by = blockIdx.y;
    int nch = K >> 5;

    float acc[2][8][4];
#pragma unroll
    for (int i = 0; i < 2; i++)
#pragma unroll
        for (int j = 0; j < 8; j++)
#pragma unroll
            for (int q = 0; q < 4; q++) acc[i][j][q] = 0.f;

    float4 pa[4];
    uint4 pbh[2], pbl[2];

    // ---- load chunk 0 ----
#pragma unroll
    for (int i = 0; i < 4; i++) {
        int p = tid + 256 * i;
        int r = p >> 3, c = (p & 7) * 4;
        int gr = by * 128 + r;
        pa[i] = (gr < NNODES) ? *(const float4*)(A + (size_t)gr * K + c)
                              : make_float4(0.f, 0.f, 0.f, 0.f);
    }
#pragma unroll
    for (int i = 0; i < 2; i++) {
        int p = tid + 256 * i;
        int r = p >> 4, c = (p & 15) * 8;
        size_t off = (size_t)r * 256 + bx * 128 + c;
        pbh[i] = *(const uint4*)(g_Bh + off);
        pbl[i] = *(const uint4*)(g_Bl + off);
    }

    for (int kc = 0; kc < nch; kc++) {
        __syncthreads();
#pragma unroll
        for (int i = 0; i < 4; i++) {
            int p = tid + 256 * i;
            int r = p >> 3, c = (p & 7) * 4;
            float4 f = pa[i];
            uint32_t h0 = pack_bf16(f.x, f.y), h1 = pack_bf16(f.z, f.w);
            float rx = f.x - __bfloat162float(__float2bfloat16_rn(f.x));
            float ry = f.y - __bfloat162float(__float2bfloat16_rn(f.y));
            float rz = f.z - __bfloat162float(__float2bfloat16_rn(f.z));
            float rw = f.w - __bfloat162float(__float2bfloat16_rn(f.w));
            uint32_t l0 = pack_bf16(rx, ry), l1 = pack_bf16(rz, rw);
            *(uint2*)&sAh[r][c] = make_uint2(h0, h1);
            *(uint2*)&sAl[r][c] = make_uint2(l0, l1);
        }
#pragma unroll
        for (int i = 0; i < 2; i++) {
            int p = tid + 256 * i;
            int r = p >> 4, c = (p & 15) * 8;
            *(uint4*)&sBh[r][c] = pbh[i];
            *(uint4*)&sBl[r][c] = pbl[i];
        }
        __syncthreads();

        if (kc + 1 < nch) {
            int kof = (kc + 1) * 32;
#pragma unroll
            for (int i = 0; i < 4; i++) {
                int p = tid + 256 * i;
                int r = p >> 3, c = (p & 7) * 4;
                int gr = by * 128 + r;
                pa[i] = (gr < NNODES) ? *(const float4*)(A + (size_t)gr * K + kof + c)
                                      : make_float4(0.f, 0.f, 0.f, 0.f);
            }
#pragma unroll
            for (int i = 0; i < 2; i++) {
                int p = tid + 256 * i;
                int r = p >> 4, c = (p & 15) * 8;
                size_t off = (size_t)(kof + r) * 256 + bx * 128 + c;
                pbh[i] = *(const uint4*)(g_Bh + off);
                pbl[i] = *(const uint4*)(g_Bl + off);
            }
        }

#pragma unroll
        for (int ks = 0; ks < 2; ks++) {
            uint32_t ah[2][4], al[2][4], bh[4][4], bl[4][4];
#pragma unroll
            for (int mt = 0; mt < 2; mt++) {
                int row = wm * 32 + mt * 16 + (lane & 15);
                int col = ks * 16 + (lane >> 4) * 8;
                ldsm4(ah[mt], s2u(&sAh[row][col]));
                ldsm4(al[mt], s2u(&sAl[row][col]));
            }
#pragma unroll
            for (int nt = 0; nt < 4; nt++) {
                int row = ks * 16 + (lane & 15);
                int col = wn * 64 + nt * 16 + (lane >> 4) * 8;
                ldsm4t(bh[nt], s2u(&sBh[row][col]));
                ldsm4t(bl[nt], s2u(&sBl[row][col]));
            }
#pragma unroll
            for (int mt = 0; mt < 2; mt++)
#pragma unroll
                for (int nt = 0; nt < 4; nt++)
#pragma unroll
                    for (int h = 0; h < 2; h++) {
                        float* d = acc[mt][nt * 2 + h];
                        mma16816(d, ah[mt], &bh[nt][h * 2]);
                        mma16816(d, ah[mt], &bl[nt][h * 2]);
                        mma16816(d, al[mt], &bh[nt][h * 2]);
                    }
        }
    }

    // ---- epilogue: write fp16 H + fused per-head attention dots ----
    int head = bx * 2 + wn;
#pragma unroll
    for (int mt = 0; mt < 2; mt++) {
        int r0 = by * 128 + wm * 32 + mt * 16 + (lane >> 2);
        float ps0 = 0.f, ps1 = 0.f, pd0 = 0.f, pd1 = 0.f;
#pragma unroll
        for (int nt = 0; nt < 8; nt++) {
            int cc = bx * 128 + wn * 64 + nt * 8 + (lane & 3) * 2;
            float as0 = Asrc[cc], as1v = Asrc[cc + 1];
            float ad0 = Adst[cc], ad1v = Adst[cc + 1];
            ps0 += acc[mt][nt][0] * as0 + acc[mt][nt][1] * as1v;
            pd0 += acc[mt][nt][0] * ad0 + acc[mt][nt][1] * ad1v;
            ps1 += acc[mt][nt][2] * as0 + acc[mt][nt][3] * as1v;
            pd1 += acc[mt][nt][2] * ad0 + acc[mt][nt][3] * ad1v;
            if (r0 < NNODES) {
                *(__half2*)(H + (size_t)r0 * FDIM + cc) =
                    __floats2half2_rn(acc[mt][nt][0], acc[mt][nt][1]);
            }
            if (r0 + 8 < NNODES) {
                *(__half2*)(H + (size_t)(r0 + 8) * FDIM + cc) =
                    __floats2half2_rn(acc[mt][nt][2], acc[mt][nt][3]);
            }
        }
#pragma unroll
        for (int off = 1; off <= 2; off <<= 1) {
            ps0 += __shfl_xor_sync(0xffffffffu, ps0, off);
            ps1 += __shfl_xor_sync(0xffffffffu, ps1, off);
            pd0 += __shfl_xor_sync(0xffffffffu, pd0, off);
            pd1 += __shfl_xor_sync(0xffffffffu, pd1, off);
        }
        if ((lane & 3) == 0) {
            if (r0 < NNODES) {
                g_asrcv[r0 * 4 + head] = ps0;
                g_adstv[r0 * 4 + head] = pd0;
            }
            if (r0 + 8 < NNODES) {
                g_asrcv[(r0 + 8) * 4 + head] = ps1;
                g_adstv[(r0 + 8) * 4 + head] = pd1;
            }
        }
    }
}

// ---------------- GAT aggregation: two-pass exact softmax, fp16 gather + BN + ReLU (+opt lsm) ----------------
template <bool LSM>
__global__ void __launch_bounds__(256) k_agg(const __half* __restrict__ X,
                      const float* __restrict__ bias,
                      const float* __restrict__ gam,
                      const float* __restrict__ bet,
                      const float* __restrict__ mu,
                      const float* __restrict__ var,
                      float* __restrict__ OUT) {
    int gwarp = (blockIdx.x * blockDim.x + threadIdx.x) >> 5;
    int lane = threadIdx.x & 31;
    if (gwarp >= NNODES) return;
    int n = gwarp;
    int ch0 = lane * 8;
    int hl = lane >> 3;

    float adv = g_adstv[n * 4 + hl];
    int r0 = g_rowptr[n], r1 = g_rowptr[n + 1];

    // pass 1: exact segment max (scores only; no gather)
    float mx = -1e30f;
    for (int k = r0; k < r1; k++) {
        int s = g_srclist[k];
        float e = g_asrcv[s * 4 + hl] + adv;
        e = (e > 0.f) ? e : 0.2f * e;
        mx = fmaxf(mx, e);
    }

    // pass 2: fp16 gather + fp32 weighted sum
    float dsum = 0.f;
    float acc[8];
#pragma unroll
    for (int j = 0; j < 8; j++) acc[j] = 0.f;

    for (int k = r0; k < r1; k++) {
        int s = g_srclist[k];
        float e = g_asrcv[s * 4 + hl] + adv;
        e = (e > 0.f) ? e : 0.2f * e;
        float p = __expf(e - mx);
        dsum += p;
        uint4 raw = *(const uint4*)(X + (size_t)s * FDIM + ch0);
        float2 f0 = __half22float2(*(__half2*)&raw.x);
        float2 f1 = __half22float2(*(__half2*)&raw.y);
        float2 f2 = __half22float2(*(__half2*)&raw.z);
        float2 f3 = __half22float2(*(__half2*)&raw.w);
        acc[0] += p * f0.x;
        acc[1] += p * f0.y;
        acc[2] += p * f1.x;
        acc[3] += p * f1.y;
        acc[4] += p * f2.x;
        acc[5] += p * f2.y;
        acc[6] += p * f3.x;
        acc[7] += p * f3.y;
    }

    float inv = 1.f / (dsum + 1e-16f);
    float ov[8];
#pragma unroll
    for (int j = 0; j < 8; j++) {
        int ch = ch0 + j;
        float val = acc[j] * inv + bias[ch];
        val = (val - mu[ch]) * rsqrtf(var[ch] + 1e-5f) * gam[ch] + bet[ch];
        ov[j] = fmaxf(val, 0.f);
    }

    if (LSM) {
        float m2 = ov[0];
#pragma unroll
        for (int j = 1; j < 8; j++) m2 = fmaxf(m2, ov[j]);
#pragma unroll
        for (int off = 16; off > 0; off >>= 1) m2 = fmaxf(m2, __shfl_xor_sync(0xffffffffu, m2, off));
        float se = 0.f;
#pragma unroll
        for (int j = 0; j < 8; j++) se += __expf(ov[j] - m2);
#pragma unroll
        for (int off = 16; off > 0; off >>= 1) se += __shfl_xor_sync(0xffffffffu, se, off);
        float lse = m2 + logf(se);
#pragma unroll
        for (int j = 0; j < 8; j++) ov[j] -= lse;
    }

    float4* op = (float4*)(OUT + (size_t)n * FDIM + ch0);
    op[0] = make_float4(ov[0], ov[1], ov[2], ov[3]);
    op[1] = make_float4(ov[4], ov[5], ov[6], ov[7]);
}

// ---------------- launch ----------------
extern "C" void kernel_launch(void* const* d_in, const int* in_sizes, int n_in,
                              void* d_out, int out_size) {
    const float* x    = (const float*)d_in[0];
    const int*   ei   = (const int*)d_in[1];
    const float* W1   = (const float*)d_in[2];
    const float* as1  = (const float*)d_in[3];
    const float* ad1  = (const float*)d_in[4];
    const float* b1   = (const float*)d_in[5];
    const float* gam1 = (const float*)d_in[6];
    const float* be1  = (const float*)d_in[7];
    const float* m1   = (const float*)d_in[8];
    const float* v1   = (const float*)d_in[9];
    const float* W2   = (const float*)d_in[10];
    const float* as2  = (const float*)d_in[11];
    const float* ad2  = (const float*)d_in[12];
    const float* b2   = (const float*)d_in[13];
    const float* gam2 = (const float*)d_in[14];
    const float* be2  = (const float*)d_in[15];
    const float* m2   = (const float*)d_in[16];
    const float* v2   = (const float*)d_in[17];
    float* out = (float*)d_out;

    float *bufA;
    __half *bufH;
    cudaGetSymbolAddress((void**)&bufA, g_bufA);
    cudaGetSymbolAddress((void**)&bufH, g_bufH);

    dim3 ggrid(2, (NNODES + 127) / 128);
    int nodeBlocks = (NNODES + 7) / 8;

    // launch order arranged so k_gemm_mma is the 4th launch (ncu sampling position)
    k_prepB<<<(128 * 256 + 255) / 256, 256>>>(W1, 128 * 256);          // 0
    k_init_deg<<<(NNODES + 255) / 256, 256>>>();                       // 1
    k_count<<<(NEDGES + 255) / 256, 256>>>(ei);                        // 2
    k_gemm_mma<<<ggrid, 256>>>(x, bufH, 128, as1, ad1);                // 3  <- profiled
    k_scan1<<<NB_SCAN, 512>>>();                                       // 4
    k_scan2<<<1, 32>>>();                                              // 5
    k_scan3f<<<(NNODES + 255) / 256, 256>>>();                         // 6
    k_fill<<<(NEDGES + 255) / 256, 256>>>(ei);                         // 7
    k_sort<<<(NNODES + 255) / 256, 256>>>();                           // 8
    k_agg<false><<<nodeBlocks, 256>>>(bufH, b1, gam1, be1, m1, v1, bufA); // 9

    // ---- layer 2 ----
    k_prepB<<<(256 * 256 + 255) / 256, 256>>>(W2, 256 * 256);          // 10
    k_gemm_mma<<<ggrid, 256>>>(bufA, bufH, 256, as2, ad2);             // 11
    k_agg<true><<<nodeBlocks, 256>>>(bufH, b2, gam2, be2, m2, v2, out);   // 12
}

// round 6
// speedup vs baseline: 1.5851x; 1.0102x over previous
#include <cuda_runtime.h>
#include <cuda_bf16.h>
#include <cuda_fp16.h>
#include <math.h>
#include <stdint.h>

#define NNODES 50000
#define NEDGES 800000
#define FDIM   256          // H*C
#define TOTE   (NEDGES + NNODES)
#define NB_SCAN ((NNODES + 511) / 512)

// ---------------- scratch (static device globals; no allocation) ----------------
__device__ __nv_bfloat16 g_Ah[(size_t)NNODES * FDIM];  // A operand hi (bf16)
__device__ __nv_bfloat16 g_Al[(size_t)NNODES * FDIM];  // A operand lo (bf16)
__device__ __half g_bufH[(size_t)NNODES * FDIM];       // fp16 h image (gather source)
__device__ float g_asrcv[NNODES * 4];
__device__ float g_adstv[NNODES * 4];
__device__ int   g_deg[NNODES];
__device__ int   g_rowptr[NNODES + 1];
__device__ int   g_cursor[NNODES];
__device__ int   g_srclist[TOTE];
__device__ int   g_blksums[256];
__device__ __nv_bfloat16 g_Bh[65536];   // weights hi, row-major [K][256]
__device__ __nv_bfloat16 g_Bl[65536];   // weights lo

// ---------------- PTX helpers (portable: sm_80+ instructions only) ----------------
__device__ __forceinline__ uint32_t s2u(const void* p) {
    uint32_t a;
    asm("{ .reg .u64 t; cvta.to.shared.u64 t, %1; cvt.u32.u64 %0, t; }" : "=r"(a) : "l"(p));
    return a;
}

__device__ __forceinline__ void ldsm4(uint32_t* r, uint32_t addr) {
    asm volatile("ldmatrix.sync.aligned.m8n8.x4.shared.b16 {%0,%1,%2,%3}, [%4];"
                 : "=r"(r[0]), "=r"(r[1]), "=r"(r[2]), "=r"(r[3]) : "r"(addr));
}

__device__ __forceinline__ void ldsm4t(uint32_t* r, uint32_t addr) {
    asm volatile("ldmatrix.sync.aligned.m8n8.x4.trans.shared.b16 {%0,%1,%2,%3}, [%4];"
                 : "=r"(r[0]), "=r"(r[1]), "=r"(r[2]), "=r"(r[3]) : "r"(addr));
}

__device__ __forceinline__ void mma16816(float* d, const uint32_t* a, const uint32_t* b) {
    asm volatile("mma.sync.aligned.m16n8k16.row.col.f32.bf16.bf16.f32 "
                 "{%0,%1,%2,%3}, {%4,%5,%6,%7}, {%8,%9}, {%0,%1,%2,%3};"
                 : "+f"(d[0]), "+f"(d[1]), "+f"(d[2]), "+f"(d[3])
                 : "r"(a[0]), "r"(a[1]), "r"(a[2]), "r"(a[3]), "r"(b[0]), "r"(b[1]));
}

__device__ __forceinline__ void cpasync16(uint32_t dst, const void* src, int sz) {
    asm volatile("cp.async.cg.shared.global [%0], [%1], 16, %2;"
                 :: "r"(dst), "l"(src), "r"(sz) : "memory");
}

// ---------------- CSR build ----------------
__global__ void k_init_deg() {
    int i = blockIdx.x * blockDim.x + threadIdx.x;
    if (i < NNODES) g_deg[i] = 1;   // self loop
}

__global__ void k_count(const int* __restrict__ ei) {
    int i = blockIdx.x * blockDim.x + threadIdx.x;
    if (i < NEDGES) atomicAdd(&g_deg[ei[NEDGES + i]], 1);
}

__global__ void k_scan1() {
    __shared__ int s[512];
    int tid = threadIdx.x;
    int i = blockIdx.x * 512 + tid;
    int v = (i < NNODES) ? g_deg[i] : 0;
    s[tid] = v;
    __syncthreads();
    for (int off = 1; off < 512; off <<= 1) {
        int t = (tid >= off) ? s[tid - off] : 0;
        __syncthreads();
        s[tid] += t;
        __syncthreads();
    }
    if (i < NNODES) g_rowptr[i] = s[tid] - v;
    if (tid == 511) g_blksums[blockIdx.x] = s[511];
}

__global__ void k_scan2() {
    if (threadIdx.x == 0 && blockIdx.x == 0) {
        int run = 0;
        for (int b = 0; b < NB_SCAN; b++) {
            int t = g_blksums[b];
            g_blksums[b] = run;
            run += t;
        }
    }
}

__global__ void k_scan3f() {
    int i = blockIdx.x * blockDim.x + threadIdx.x;
    if (i < NNODES) {
        int r = g_rowptr[i] + g_blksums[i >> 9];
        g_rowptr[i] = r;
        g_srclist[r] = i;        // self loop first
        g_cursor[i] = r + 1;
    }
    if (i == 0) g_rowptr[NNODES] = TOTE;
}

__global__ void k_fill(const int* __restrict__ ei) {
    int i = blockIdx.x * blockDim.x + threadIdx.x;
    if (i < NEDGES) {
        int s = ei[i];
        int d = ei[NEDGES + i];
        int pos = atomicAdd(&g_cursor[d], 1);
        g_srclist[pos] = s;
    }
}

__global__ void k_sort() {
    int n = blockIdx.x * blockDim.x + threadIdx.x;
    if (n >= NNODES) return;
    int beg = g_rowptr[n] + 1;
    int end = g_rowptr[n + 1];
    for (int i = beg + 1; i < end; i++) {
        int key = g_srclist[i];
        int j = i - 1;
        while (j >= beg && g_srclist[j] > key) {
            g_srclist[j + 1] = g_srclist[j];
            j--;
        }
        g_srclist[j + 1] = key;
    }
}

// ---------------- operand splits ----------------
__global__ void k_prepB(const float* __restrict__ W, int total) {
    int i = blockIdx.x * 256 + threadIdx.x;
    if (i >= total) return;
    float v = W[i];
    __nv_bfloat16 h = __float2bfloat16_rn(v);
    g_Bh[i] = h;
    g_Bl[i] = __float2bfloat16_rn(v - __bfloat162float(h));
}

__global__ void k_prepA(const float* __restrict__ X, int total) {
    int i = blockIdx.x * 256 + threadIdx.x;
    if (i >= total) return;
    float v = X[i];
    __nv_bfloat16 h = __float2bfloat16_rn(v);
    g_Ah[i] = h;
    g_Al[i] = __float2bfloat16_rn(v - __bfloat162float(h));
}

// ---------------- tensor-core GEMM: cp.async double-buffered, 512 thr, 128x256 tile ----------------
// H[M,256] = fp16(A[M,K] * W[K,256]); A pre-split bf16 hi/lo, 3-product compensation.
// 16 warps (4m x 4n), warp tile 32x64 = one GAT head. Fused attention-dot epilogue.
// smem stage: Ah[128][80B] Al | Bh[32][528B] Bl  = 54272 B; 2 stages.
#define GSTAGE 54272
__global__ void __launch_bounds__(512) k_gemm_mma(const __nv_bfloat16* __restrict__ Ahp,
                                                  const __nv_bfloat16* __restrict__ Alp,
                                                  __half* __restrict__ H, int K,
                                                  const float* __restrict__ Asrc,
                                                  const float* __restrict__ Adst) {
    extern __shared__ char sm[];
    uint32_t sbase = s2u(sm);

    int tid = threadIdx.x;
    int lane = tid & 31, w = tid >> 5;
    int wm = w & 3, wn = w >> 2;          // warp tile origin (wm*32, wn*64)
    int by = blockIdx.x;
    int nch = K >> 5;

    // cp.async assignments (fixed per thread)
    int ar = tid >> 2, ac = tid & 3;                 // A: row 0..127, chunk 0..3 (16B each)
    int agr = by * 128 + ar;
    int asz = (agr < NNODES) ? 16 : 0;
    int agc = (agr < NNODES) ? agr : 0;
    const char* gAh = (const char*)(Ahp + (size_t)agc * K + ac * 8);
    const char* gAl = (const char*)(Alp + (size_t)agc * K + ac * 8);
    uint32_t dA = (uint32_t)(ar * 80 + ac * 16);

    float acc[2][8][4];
#pragma unroll
    for (int i = 0; i < 2; i++)
#pragma unroll
        for (int j = 0; j < 8; j++)
#pragma unroll
            for (int q = 0; q < 4; q++) acc[i][j][q] = 0.f;

    // ---- issue stage for chunk kc into buffer s ----
#define ISSUE(kc, s) do {                                                          \
        uint32_t so = sbase + (s) * GSTAGE;                                        \
        cpasync16(so + dA, gAh + (size_t)(kc) * 64, asz);                          \
        cpasync16(so + 10240 + dA, gAl + (size_t)(kc) * 64, asz);                  \
        _Pragma("unroll")                                                          \
        for (int i = 0; i < 2; i++) {                                              \
            int p = tid + 512 * i;                                                 \
            int rr = p >> 5, c2 = p & 31;                                          \
            size_t go = (size_t)((kc) * 32 + rr) * 256 + c2 * 8;                   \
            uint32_t db = so + 20480 + rr * 528 + c2 * 16;                         \
            cpasync16(db, (const char*)(g_Bh + go), 16);                           \
            cpasync16(db + 16896, (const char*)(g_Bl + go), 16);                   \
        }                                                                          \
        asm volatile("cp.async.commit_group;" ::: "memory");                       \
    } while (0)

    ISSUE(0, 0);

    for (int kc = 0; kc < nch; kc++) {
        int s = kc & 1;
        if (kc + 1 < nch) {
            ISSUE(kc + 1, (kc + 1) & 1);
            asm volatile("cp.async.wait_group 1;" ::: "memory");
        } else {
            asm volatile("cp.async.wait_group 0;" ::: "memory");
        }
        __syncthreads();

        uint32_t aoff = sbase + s * GSTAGE;
        uint32_t boff = aoff + 20480;
#pragma unroll
        for (int ks = 0; ks < 2; ks++) {
            uint32_t ah[2][4], al[2][4], bh[4][4], bl[4][4];
#pragma unroll
            for (int mt = 0; mt < 2; mt++) {
                int row = wm * 32 + mt * 16 + (lane & 15);
                uint32_t addr = aoff + row * 80 + ks * 32 + (lane >> 4) * 16;
                ldsm4(ah[mt], addr);
                ldsm4(al[mt], addr + 10240);
            }
#pragma unroll
            for (int nt = 0; nt < 4; nt++) {
                int row = ks * 16 + (lane & 15);
                uint32_t addr = boff + row * 528 + (wn * 64 + nt * 16) * 2 + (lane >> 4) * 16;
                ldsm4t(bh[nt], addr);
                ldsm4t(bl[nt], addr + 16896);
            }
#pragma unroll
            for (int mt = 0; mt < 2; mt++)
#pragma unroll
                for (int nt = 0; nt < 4; nt++)
#pragma unroll
                    for (int h = 0; h < 2; h++) {
                        float* d = acc[mt][nt * 2 + h];
                        mma16816(d, ah[mt], &bh[nt][h * 2]);
                        mma16816(d, ah[mt], &bl[nt][h * 2]);
                        mma16816(d, al[mt], &bh[nt][h * 2]);
                    }
        }
        __syncthreads();
    }

    // ---- epilogue: write fp16 H + fused per-head attention dots ----
    int head = wn;
#pragma unroll
    for (int mt = 0; mt < 2; mt++) {
        int r0 = by * 128 + wm * 32 + mt * 16 + (lane >> 2);
        float ps0 = 0.f, ps1 = 0.f, pd0 = 0.f, pd1 = 0.f;
#pragma unroll
        for (int nt = 0; nt < 8; nt++) {
            int cc = wn * 64 + nt * 8 + (lane & 3) * 2;
            float as0 = Asrc[cc], as1v = Asrc[cc + 1];
            float ad0 = Adst[cc], ad1v = Adst[cc + 1];
            ps0 += acc[mt][nt][0] * as0 + acc[mt][nt][1] * as1v;
            pd0 += acc[mt][nt][0] * ad0 + acc[mt][nt][1] * ad1v;
            ps1 += acc[mt][nt][2] * as0 + acc[mt][nt][3] * as1v;
            pd1 += acc[mt][nt][2] * ad0 + acc[mt][nt][3] * ad1v;
            if (r0 < NNODES) {
                *(__half2*)(H + (size_t)r0 * FDIM + cc) =
                    __floats2half2_rn(acc[mt][nt][0], acc[mt][nt][1]);
            }
            if (r0 + 8 < NNODES) {
                *(__half2*)(H + (size_t)(r0 + 8) * FDIM + cc) =
                    __floats2half2_rn(acc[mt][nt][2], acc[mt][nt][3]);
            }
        }
#pragma unroll
        for (int off = 1; off <= 2; off <<= 1) {
            ps0 += __shfl_xor_sync(0xffffffffu, ps0, off);
            ps1 += __shfl_xor_sync(0xffffffffu, ps1, off);
            pd0 += __shfl_xor_sync(0xffffffffu, pd0, off);
            pd1 += __shfl_xor_sync(0xffffffffu, pd1, off);
        }
        if ((lane & 3) == 0) {
            if (r0 < NNODES) {
                g_asrcv[r0 * 4 + head] = ps0;
                g_adstv[r0 * 4 + head] = pd0;
            }
            if (r0 + 8 < NNODES) {
                g_asrcv[(r0 + 8) * 4 + head] = ps1;
                g_adstv[(r0 + 8) * 4 + head] = pd1;
            }
        }
    }
}

// ---------------- GAT aggregation: two-pass exact softmax, fp16 gather + BN + ReLU ----------------
// MODE 0: write bf16 hi/lo (next layer's A operand). MODE 1: log_softmax + fp32 out.
template <int MODE>
__global__ void __launch_bounds__(256) k_agg(const __half* __restrict__ X,
                      const float* __restrict__ bias,
                      const float* __restrict__ gam,
                      const float* __restrict__ bet,
                      const float* __restrict__ mu,
                      const float* __restrict__ var,
                      float* __restrict__ OUT) {
    int gwarp = (blockIdx.x * blockDim.x + threadIdx.x) >> 5;
    int lane = threadIdx.x & 31;
    if (gwarp >= NNODES) return;
    int n = gwarp;
    int ch0 = lane * 8;
    int hl = lane >> 3;

    float adv = g_adstv[n * 4 + hl];
    int r0 = g_rowptr[n], r1 = g_rowptr[n + 1];

    // pass 1: exact segment max (scores only)
    float mx = -1e30f;
    for (int k = r0; k < r1; k++) {
        int s = g_srclist[k];
        float e = g_asrcv[s * 4 + hl] + adv;
        e = (e > 0.f) ? e : 0.2f * e;
        mx = fmaxf(mx, e);
    }

    // pass 2: fp16 gather + fp32 weighted sum
    float dsum = 0.f;
    float acc[8];
#pragma unroll
    for (int j = 0; j < 8; j++) acc[j] = 0.f;

    for (int k = r0; k < r1; k++) {
        int s = g_srclist[k];
        float e = g_asrcv[s * 4 + hl] + adv;
        e = (e > 0.f) ? e : 0.2f * e;
        float p = __expf(e - mx);
        dsum += p;
        uint4 raw = *(const uint4*)(X + (size_t)s * FDIM + ch0);
        float2 f0 = __half22float2(*(__half2*)&raw.x);
        float2 f1 = __half22float2(*(__half2*)&raw.y);
        float2 f2 = __half22float2(*(__half2*)&raw.z);
        float2 f3 = __half22float2(*(__half2*)&raw.w);
        acc[0] += p * f0.x;
        acc[1] += p * f0.y;
        acc[2] += p * f1.x;
        acc[3] += p * f1.y;
        acc[4] += p * f2.x;
        acc[5] += p * f2.y;
        acc[6] += p * f3.x;
        acc[7] += p * f3.y;
    }

    float inv = 1.f / (dsum + 1e-16f);
    float ov[8];
#pragma unroll
    for (int j = 0; j < 8; j++) {
        int ch = ch0 + j;
        float val = acc[j] * inv + bias[ch];
        val = (val - mu[ch]) * rsqrtf(var[ch] + 1e-5f) * gam[ch] + bet[ch];
        ov[j] = fmaxf(val, 0.f);
    }

    if (MODE == 0) {
        // emit bf16 hi/lo pair (A operand of next layer)
        ushort hs[8], ls[8];
#pragma unroll
        for (int j = 0; j < 8; j++) {
            __nv_bfloat16 h = __float2bfloat16_rn(ov[j]);
            hs[j] = __bfloat16_as_ushort(h);
            ls[j] = __bfloat16_as_ushort(__float2bfloat16_rn(ov[j] - __bfloat162float(h)));
        }
        uint4 hv, lv;
        hv.x = (uint32_t)hs[0] | ((uint32_t)hs[1] << 16);
        hv.y = (uint32_t)hs[2] | ((uint32_t)hs[3] << 16);
        hv.z = (uint32_t)hs[4] | ((uint32_t)hs[5] << 16);
        hv.w = (uint32_t)hs[6] | ((uint32_t)hs[7] << 16);
        lv.x = (uint32_t)ls[0] | ((uint32_t)ls[1] << 16);
        lv.y = (uint32_t)ls[2] | ((uint32_t)ls[3] << 16);
        lv.z = (uint32_t)ls[4] | ((uint32_t)ls[5] << 16);
        lv.w = (uint32_t)ls[6] | ((uint32_t)ls[7] << 16);
        *(uint4*)(g_Ah + (size_t)n * FDIM + ch0) = hv;
        *(uint4*)(g_Al + (size_t)n * FDIM + ch0) = lv;
    } else {
        float m2 = ov[0];
#pragma unroll
        for (int j = 1; j < 8; j++) m2 = fmaxf(m2, ov[j]);
#pragma unroll
        for (int off = 16; off > 0; off >>= 1) m2 = fmaxf(m2, __shfl_xor_sync(0xffffffffu, m2, off));
        float se = 0.f;
#pragma unroll
        for (int j = 0; j < 8; j++) se += __expf(ov[j] - m2);
#pragma unroll
        for (int off = 16; off > 0; off >>= 1) se += __shfl_xor_sync(0xffffffffu, se, off);
        float lse = m2 + logf(se);
        float4* op = (float4*)(OUT + (size_t)n * FDIM + ch0);
        op[0] = make_float4(ov[0] - lse, ov[1] - lse, ov[2] - lse, ov[3] - lse);
        op[1] = make_float4(ov[4] - lse, ov[5] - lse, ov[6] - lse, ov[7] - lse);
    }
}

// ---------------- launch ----------------
extern "C" void kernel_launch(void* const* d_in, const int* in_sizes, int n_in,
                              void* d_out, int out_size) {
    const float* x    = (const float*)d_in[0];
    const int*   ei   = (const int*)d_in[1];
    const float* W1   = (const float*)d_in[2];
    const float* as1  = (const float*)d_in[3];
    const float* ad1  = (const float*)d_in[4];
    const float* b1   = (const float*)d_in[5];
    const float* gam1 = (const float*)d_in[6];
    const float* be1  = (const float*)d_in[7];
    const float* m1   = (const float*)d_in[8];
    const float* v1   = (const float*)d_in[9];
    const float* W2   = (const float*)d_in[10];
    const float* as2  = (const float*)d_in[11];
    const float* ad2  = (const float*)d_in[12];
    const float* b2   = (const float*)d_in[13];
    const float* gam2 = (const float*)d_in[14];
    const float* be2  = (const float*)d_in[15];
    const float* m2   = (const float*)d_in[16];
    const float* v2   = (const float*)d_in[17];
    float* out = (float*)d_out;

    __nv_bfloat16 *Ah, *Al;
    __half *bufH;
    cudaGetSymbolAddress((void**)&Ah, g_Ah);
    cudaGetSymbolAddress((void**)&Al, g_Al);
    cudaGetSymbolAddress((void**)&bufH, g_bufH);

    const int GSMEM = 2 * GSTAGE;  // 108544
    cudaFuncSetAttribute(k_gemm_mma, cudaFuncAttributeMaxDynamicSharedMemorySize, GSMEM);

    int gemmBlocks = (NNODES + 127) / 128;   // 391
    int nodeBlocks = (NNODES + 7) / 8;

    k_prepA<<<(NNODES * 128 + 255) / 256, 256>>>(x, NNODES * 128);        // 0
    k_prepB<<<(128 * 256 + 255) / 256, 256>>>(W1, 128 * 256);             // 1
    k_init_deg<<<(NNODES + 255) / 256, 256>>>();                          // 2
    k_gemm_mma<<<gemmBlocks, 512, GSMEM>>>(Ah, Al, bufH, 128, as1, ad1);  // 3  <- profiled
    k_count<<<(NEDGES + 255) / 256, 256>>>(ei);                           // 4
    k_scan1<<<NB_SCAN, 512>>>();                                          // 5
    k_scan2<<<1, 32>>>();                                                 // 6
    k_scan3f<<<(NNODES + 255) / 256, 256>>>();                            // 7
    k_fill<<<(NEDGES + 255) / 256, 256>>>(ei);                            // 8
    k_sort<<<(NNODES + 255) / 256, 256>>>();                              // 9
    k_agg<0><<<nodeBlocks, 256>>>(bufH, b1, gam1, be1, m1, v1, nullptr);  // 10

    // ---- layer 2 ----
    k_prepB<<<(256 * 256 + 255) / 256, 256>>>(W2, 256 * 256);             // 11
    k_gemm_mma<<<gemmBlocks, 512, GSMEM>>>(Ah, Al, bufH, 256, as2, ad2);  // 12
    k_agg<1><<<nodeBlocks, 256>>>(bufH, b2, gam2, be2, m2, v2, out);      // 13
}

// round 7
// speedup vs baseline: 1.7273x; 1.0897x over previous
#include <cuda_runtime.h>
#include <cuda_bf16.h>
#include <cuda_fp16.h>
#include <math.h>
#include <stdint.h>

#define NNODES 50000
#define NEDGES 800000
#define FDIM   256          // H*C
#define TOTE   (NEDGES + NNODES)
#define NB_SCAN ((NNODES + 511) / 512)

// ---------------- scratch (static device globals; no allocation) ----------------
__device__ __nv_bfloat16 g_Ah[(size_t)NNODES * FDIM];  // A operand hi (bf16)
__device__ __nv_bfloat16 g_Al[(size_t)NNODES * FDIM];  // A operand lo (bf16)
__device__ __half g_bufH[(size_t)NNODES * FDIM];       // fp16 h image (gather source)
__device__ float g_asrcv[NNODES * 4];
__device__ float g_adstv[NNODES * 4];
__device__ int   g_deg[NNODES];
__device__ int   g_rowptr[NNODES + 1];
__device__ int   g_cursor[NNODES];
__device__ int   g_srclist[TOTE];
__device__ int   g_blksums[256];
__device__ __nv_bfloat16 g_Bh[65536];   // weights hi, row-major [K][256]
__device__ __nv_bfloat16 g_Bl[65536];   // weights lo
__device__ float g_bnA[512];            // folded BN scale (layer0: [0,256), layer1: [256,512))
__device__ float g_bnB[512];            // folded BN shift

// ---------------- PTX helpers (portable: sm_80+ instructions only) ----------------
__device__ __forceinline__ uint32_t s2u(const void* p) {
    uint32_t a;
    asm("{ .reg .u64 t; cvta.to.shared.u64 t, %1; cvt.u32.u64 %0, t; }" : "=r"(a) : "l"(p));
    return a;
}

__device__ __forceinline__ void ldsm4(uint32_t* r, uint32_t addr) {
    asm volatile("ldmatrix.sync.aligned.m8n8.x4.shared.b16 {%0,%1,%2,%3}, [%4];"
                 : "=r"(r[0]), "=r"(r[1]), "=r"(r[2]), "=r"(r[3]) : "r"(addr));
}

__device__ __forceinline__ void ldsm4t(uint32_t* r, uint32_t addr) {
    asm volatile("ldmatrix.sync.aligned.m8n8.x4.trans.shared.b16 {%0,%1,%2,%3}, [%4];"
                 : "=r"(r[0]), "=r"(r[1]), "=r"(r[2]), "=r"(r[3]) : "r"(addr));
}

__device__ __forceinline__ void mma16816(float* d, const uint32_t* a, const uint32_t* b) {
    asm volatile("mma.sync.aligned.m16n8k16.row.col.f32.bf16.bf16.f32 "
                 "{%0,%1,%2,%3}, {%4,%5,%6,%7}, {%8,%9}, {%0,%1,%2,%3};"
                 : "+f"(d[0]), "+f"(d[1]), "+f"(d[2]), "+f"(d[3])
                 : "r"(a[0]), "r"(a[1]), "r"(a[2]), "r"(a[3]), "r"(b[0]), "r"(b[1]));
}

__device__ __forceinline__ void cpasync16(uint32_t dst, const void* src, int sz) {
    asm volatile("cp.async.cg.shared.global [%0], [%1], 16, %2;"
                 :: "r"(dst), "l"(src), "r"(sz) : "memory");
}

__device__ __forceinline__ float lrelu(float e) {
    return (e > 0.f) ? e : 0.2f * e;
}

// ---------------- CSR build ----------------
__global__ void k_init_deg() {
    int i = blockIdx.x * blockDim.x + threadIdx.x;
    if (i < NNODES) g_deg[i] = 1;   // self loop
}

__global__ void k_count(const int* __restrict__ ei) {
    int i = blockIdx.x * blockDim.x + threadIdx.x;
    if (i < NEDGES) atomicAdd(&g_deg[ei[NEDGES + i]], 1);
}

__global__ void k_scan1() {
    __shared__ int s[512];
    int tid = threadIdx.x;
    int i = blockIdx.x * 512 + tid;
    int v = (i < NNODES) ? g_deg[i] : 0;
    s[tid] = v;
    __syncthreads();
    for (int off = 1; off < 512; off <<= 1) {
        int t = (tid >= off) ? s[tid - off] : 0;
        __syncthreads();
        s[tid] += t;
        __syncthreads();
    }
    if (i < NNODES) g_rowptr[i] = s[tid] - v;
    if (tid == 511) g_blksums[blockIdx.x] = s[511];
}

__global__ void k_scan2() {
    if (threadIdx.x == 0 && blockIdx.x == 0) {
        int run = 0;
        for (int b = 0; b < NB_SCAN; b++) {
            int t = g_blksums[b];
            g_blksums[b] = run;
            run += t;
        }
    }
}

__global__ void k_scan3f() {
    int i = blockIdx.x * blockDim.x + threadIdx.x;
    if (i < NNODES) {
        int r = g_rowptr[i] + g_blksums[i >> 9];
        g_rowptr[i] = r;
        g_srclist[r] = i;        // self loop first
        g_cursor[i] = r + 1;
    }
    if (i == 0) g_rowptr[NNODES] = TOTE;
}

__global__ void k_fill(const int* __restrict__ ei) {
    int i = blockIdx.x * blockDim.x + threadIdx.x;
    if (i < NEDGES) {
        int s = ei[i];
        int d = ei[NEDGES + i];
        int pos = atomicAdd(&g_cursor[d], 1);
        g_srclist[pos] = s;
    }
}

__global__ void k_sort() {
    int n = blockIdx.x * blockDim.x + threadIdx.x;
    if (n >= NNODES) return;
    int beg = g_rowptr[n] + 1;
    int end = g_rowptr[n + 1];
    for (int i = beg + 1; i < end; i++) {
        int key = g_srclist[i];
        int j = i - 1;
        while (j >= beg && g_srclist[j] > key) {
            g_srclist[j + 1] = g_srclist[j];
            j--;
        }
        g_srclist[j + 1] = key;
    }
}

// ---------------- operand splits + BN fold ----------------
__global__ void k_prepB(const float* __restrict__ W, int total) {
    int i = blockIdx.x * 256 + threadIdx.x;
    if (i >= total) return;
    float v = W[i];
    __nv_bfloat16 h = __float2bfloat16_rn(v);
    g_Bh[i] = h;
    g_Bl[i] = __float2bfloat16_rn(v - __bfloat162float(h));
}

__global__ void k_prepA(const float* __restrict__ X, int total) {
    int i = blockIdx.x * 256 + threadIdx.x;
    if (i >= total) return;
    float v = X[i];
    __nv_bfloat16 h = __float2bfloat16_rn(v);
    g_Ah[i] = h;
    g_Al[i] = __float2bfloat16_rn(v - __bfloat162float(h));
}

// folded BN: A = gam*rsqrt(var+eps); B = (bias-mu)*A + bet
__global__ void k_prepBN(const float* __restrict__ bias, const float* __restrict__ gam,
                         const float* __restrict__ bet, const float* __restrict__ mu,
                         const float* __restrict__ var, int slot) {
    int i = threadIdx.x;   // 256
    float s = gam[i] * rsqrtf(var[i] + 1e-5f);
    g_bnA[slot * 256 + i] = s;
    g_bnB[slot * 256 + i] = (bias[i] - mu[i]) * s + bet[i];
}

// ---------------- tensor-core GEMM: cp.async double-buffered, 512 thr, 128x256 tile ----------------
#define GSTAGE 54272
__global__ void __launch_bounds__(512) k_gemm_mma(const __nv_bfloat16* __restrict__ Ahp,
                                                  const __nv_bfloat16* __restrict__ Alp,
                                                  __half* __restrict__ H, int K,
                                                  const float* __restrict__ Asrc,
                                                  const float* __restrict__ Adst) {
    extern __shared__ char sm[];
    uint32_t sbase = s2u(sm);

    int tid = threadIdx.x;
    int lane = tid & 31, w = tid >> 5;
    int wm = w & 3, wn = w >> 2;          // warp tile origin (wm*32, wn*64)
    int by = blockIdx.x;
    int nch = K >> 5;

    int ar = tid >> 2, ac = tid & 3;
    int agr = by * 128 + ar;
    int asz = (agr < NNODES) ? 16 : 0;
    int agc = (agr < NNODES) ? agr : 0;
    const char* gAh = (const char*)(Ahp + (size_t)agc * K + ac * 8);
    const char* gAl = (const char*)(Alp + (size_t)agc * K + ac * 8);
    uint32_t dA = (uint32_t)(ar * 80 + ac * 16);

    float acc[2][8][4];
#pragma unroll
    for (int i = 0; i < 2; i++)
#pragma unroll
        for (int j = 0; j < 8; j++)
#pragma unroll
            for (int q = 0; q < 4; q++) acc[i][j][q] = 0.f;

#define ISSUE(kc, s) do {                                                          \
        uint32_t so = sbase + (s) * GSTAGE;                                        \
        cpasync16(so + dA, gAh + (size_t)(kc) * 64, asz);                          \
        cpasync16(so + 10240 + dA, gAl + (size_t)(kc) * 64, asz);                  \
        _Pragma("unroll")                                                          \
        for (int i = 0; i < 2; i++) {                                              \
            int p = tid + 512 * i;                                                 \
            int rr = p >> 5, c2 = p & 31;                                          \
            size_t go = (size_t)((kc) * 32 + rr) * 256 + c2 * 8;                   \
            uint32_t db = so + 20480 + rr * 528 + c2 * 16;                         \
            cpasync16(db, (const char*)(g_Bh + go), 16);                           \
            cpasync16(db + 16896, (const char*)(g_Bl + go), 16);                   \
        }                                                                          \
        asm volatile("cp.async.commit_group;" ::: "memory");                       \
    } while (0)

    ISSUE(0, 0);

    for (int kc = 0; kc < nch; kc++) {
        int s = kc & 1;
        if (kc + 1 < nch) {
            ISSUE(kc + 1, (kc + 1) & 1);
            asm volatile("cp.async.wait_group 1;" ::: "memory");
        } else {
            asm volatile("cp.async.wait_group 0;" ::: "memory");
        }
        __syncthreads();

        uint32_t aoff = sbase + s * GSTAGE;
        uint32_t boff = aoff + 20480;
#pragma unroll
        for (int ks = 0; ks < 2; ks++) {
            uint32_t ah[2][4], al[2][4], bh[4][4], bl[4][4];
#pragma unroll
            for (int mt = 0; mt < 2; mt++) {
                int row = wm * 32 + mt * 16 + (lane & 15);
                uint32_t addr = aoff + row * 80 + ks * 32 + (lane >> 4) * 16;
                ldsm4(ah[mt], addr);
                ldsm4(al[mt], addr + 10240);
            }
#pragma unroll
            for (int nt = 0; nt < 4; nt++) {
                int row = ks * 16 + (lane & 15);
                uint32_t addr = boff + row * 528 + (wn * 64 + nt * 16) * 2 + (lane >> 4) * 16;
                ldsm4t(bh[nt], addr);
                ldsm4t(bl[nt], addr + 16896);
            }
#pragma unroll
            for (int mt = 0; mt < 2; mt++)
#pragma unroll
                for (int nt = 0; nt < 4; nt++)
#pragma unroll
                    for (int h = 0; h < 2; h++) {
                        float* d = acc[mt][nt * 2 + h];
                        mma16816(d, ah[mt], &bh[nt][h * 2]);
                        mma16816(d, ah[mt], &bl[nt][h * 2]);
                        mma16816(d, al[mt], &bh[nt][h * 2]);
                    }
        }
        __syncthreads();
    }

    // ---- epilogue: write fp16 H + fused per-head attention dots ----
    int head = wn;
#pragma unroll
    for (int mt = 0; mt < 2; mt++) {
        int r0 = by * 128 + wm * 32 + mt * 16 + (lane >> 2);
        float ps0 = 0.f, ps1 = 0.f, pd0 = 0.f, pd1 = 0.f;
#pragma unroll
        for (int nt = 0; nt < 8; nt++) {
            int cc = wn * 64 + nt * 8 + (lane & 3) * 2;
            float as0 = Asrc[cc], as1v = Asrc[cc + 1];
            float ad0 = Adst[cc], ad1v = Adst[cc + 1];
            ps0 += acc[mt][nt][0] * as0 + acc[mt][nt][1] * as1v;
            pd0 += acc[mt][nt][0] * ad0 + acc[mt][nt][1] * ad1v;
            ps1 += acc[mt][nt][2] * as0 + acc[mt][nt][3] * as1v;
            pd1 += acc[mt][nt][2] * ad0 + acc[mt][nt][3] * ad1v;
            if (r0 < NNODES) {
                *(__half2*)(H + (size_t)r0 * FDIM + cc) =
                    __floats2half2_rn(acc[mt][nt][0], acc[mt][nt][1]);
            }
            if (r0 + 8 < NNODES) {
                *(__half2*)(H + (size_t)(r0 + 8) * FDIM + cc) =
                    __floats2half2_rn(acc[mt][nt][2], acc[mt][nt][3]);
            }
        }
#pragma unroll
        for (int off = 1; off <= 2; off <<= 1) {
            ps0 += __shfl_xor_sync(0xffffffffu, ps0, off);
            ps1 += __shfl_xor_sync(0xffffffffu, ps1, off);
            pd0 += __shfl_xor_sync(0xffffffffu, pd0, off);
            pd1 += __shfl_xor_sync(0xffffffffu, pd1, off);
        }
        if ((lane & 3) == 0) {
            if (r0 < NNODES) {
                g_asrcv[r0 * 4 + head] = ps0;
                g_adstv[r0 * 4 + head] = pd0;
            }
            if (r0 + 8 < NNODES) {
                g_asrcv[(r0 + 8) * 4 + head] = ps1;
                g_adstv[(r0 + 8) * 4 + head] = pd1;
            }
        }
    }
}

// ---------------- GAT aggregation: two-pass exact softmax, unrolled, folded BN ----------------
// MODE 0: write bf16 hi/lo (next layer's A operand). MODE 1: log_softmax + fp32 out.
template <int MODE>
__global__ void __launch_bounds__(256) k_agg(const __half* __restrict__ X,
                      const float* __restrict__ bnA,
                      const float* __restrict__ bnB,
                      float* __restrict__ OUT) {
    int gwarp = (blockIdx.x * blockDim.x + threadIdx.x) >> 5;
    int lane = threadIdx.x & 31;
    if (gwarp >= NNODES) return;
    int n = gwarp;
    int ch0 = lane * 8;
    int hl = lane >> 3;

    const float* __restrict__ sc = g_asrcv;
    const int* __restrict__ lst = g_srclist;

    float adv = g_adstv[n * 4 + hl];
    int r0 = g_rowptr[n], r1 = g_rowptr[n + 1];

    // ---- pass 1: exact segment max, unrolled x4 with tree max ----
    float mxa = -1e30f, mxb = -1e30f;
    int k = r0;
    for (; k + 3 < r1; k += 4) {
        int s0 = lst[k], s1 = lst[k + 1], s2 = lst[k + 2], s3 = lst[k + 3];
        float e0 = lrelu(sc[s0 * 4 + hl] + adv);
        float e1 = lrelu(sc[s1 * 4 + hl] + adv);
        float e2 = lrelu(sc[s2 * 4 + hl] + adv);
        float e3 = lrelu(sc[s3 * 4 + hl] + adv);
        mxa = fmaxf(mxa, fmaxf(e0, e1));
        mxb = fmaxf(mxb, fmaxf(e2, e3));
    }
    for (; k < r1; k++) {
        int s0 = lst[k];
        mxa = fmaxf(mxa, lrelu(sc[s0 * 4 + hl] + adv));
    }
    float mx = fmaxf(mxa, mxb);

    // ---- pass 2: gather + weighted sum, unrolled x2 (2 rows in flight) ----
    float dsum = 0.f;
    float acc[8];
#pragma unroll
    for (int j = 0; j < 8; j++) acc[j] = 0.f;

    k = r0;
    for (; k + 1 < r1; k += 2) {
        int s0 = lst[k], s1 = lst[k + 1];
        uint4 ra = *(const uint4*)(X + (size_t)s0 * FDIM + ch0);
        uint4 rb = *(const uint4*)(X + (size_t)s1 * FDIM + ch0);
        float e0 = lrelu(sc[s0 * 4 + hl] + adv);
        float e1 = lrelu(sc[s1 * 4 + hl] + adv);
        float p0 = __expf(e0 - mx);
        float p1 = __expf(e1 - mx);
        dsum += p0 + p1;
        float2 a0 = __half22float2(*(__half2*)&ra.x);
        float2 a1 = __half22float2(*(__half2*)&ra.y);
        float2 a2 = __half22float2(*(__half2*)&ra.z);
        float2 a3 = __half22float2(*(__half2*)&ra.w);
        float2 b0 = __half22float2(*(__half2*)&rb.x);
        float2 b1 = __half22float2(*(__half2*)&rb.y);
        float2 b2 = __half22float2(*(__half2*)&rb.z);
        float2 b3 = __half22float2(*(__half2*)&rb.w);
        acc[0] += p0 * a0.x + p1 * b0.x;
        acc[1] += p0 * a0.y + p1 * b0.y;
        acc[2] += p0 * a1.x + p1 * b1.x;
        acc[3] += p0 * a1.y + p1 * b1.y;
        acc[4] += p0 * a2.x + p1 * b2.x;
        acc[5] += p0 * a2.y + p1 * b2.y;
        acc[6] += p0 * a3.x + p1 * b3.x;
        acc[7] += p0 * a3.y + p1 * b3.y;
    }
    if (k < r1) {
        int s0 = lst[k];
        uint4 ra = *(const uint4*)(X + (size_t)s0 * FDIM + ch0);
        float e0 = lrelu(sc[s0 * 4 + hl] + adv);
        float p0 = __expf(e0 - mx);
        dsum += p0;
        float2 a0 = __half22float2(*(__half2*)&ra.x);
        float2 a1 = __half22float2(*(__half2*)&ra.y);
        float2 a2 = __half22float2(*(__half2*)&ra.z);
        float2 a3 = __half22float2(*(__half2*)&ra.w);
        acc[0] += p0 * a0.x;
        acc[1] += p0 * a0.y;
        acc[2] += p0 * a1.x;
        acc[3] += p0 * a1.y;
        acc[4] += p0 * a2.x;
        acc[5] += p0 * a2.y;
        acc[6] += p0 * a3.x;
        acc[7] += p0 * a3.y;
    }

    float inv = 1.f / (dsum + 1e-16f);
    float ov[8];
#pragma unroll
    for (int j = 0; j < 8; j++) {
        int ch = ch0 + j;
        ov[j] = fmaxf(fmaf(acc[j] * inv, bnA[ch], bnB[ch]), 0.f);
    }

    if (MODE == 0) {
        ushort hs[8], ls[8];
#pragma unroll
        for (int j = 0; j < 8; j++) {
            __nv_bfloat16 h = __float2bfloat16_rn(ov[j]);
            hs[j] = __bfloat16_as_ushort(h);
            ls[j] = __bfloat16_as_ushort(__float2bfloat16_rn(ov[j] - __bfloat162float(h)));
        }
        uint4 hv, lv;
        hv.x = (uint32_t)hs[0] | ((uint32_t)hs[1] << 16);
        hv.y = (uint32_t)hs[2] | ((uint32_t)hs[3] << 16);
        hv.z = (uint32_t)hs[4] | ((uint32_t)hs[5] << 16);
        hv.w = (uint32_t)hs[6] | ((uint32_t)hs[7] << 16);
        lv.x = (uint32_t)ls[0] | ((uint32_t)ls[1] << 16);
        lv.y = (uint32_t)ls[2] | ((uint32_t)ls[3] << 16);
        lv.z = (uint32_t)ls[4] | ((uint32_t)ls[5] << 16);
        lv.w = (uint32_t)ls[6] | ((uint32_t)ls[7] << 16);
        *(uint4*)(g_Ah + (size_t)n * FDIM + ch0) = hv;
        *(uint4*)(g_Al + (size_t)n * FDIM + ch0) = lv;
    } else {
        float m2 = ov[0];
#pragma unroll
        for (int j = 1; j < 8; j++) m2 = fmaxf(m2, ov[j]);
#pragma unroll
        for (int off = 16; off > 0; off >>= 1) m2 = fmaxf(m2, __shfl_xor_sync(0xffffffffu, m2, off));
        float se = 0.f;
#pragma unroll
        for (int j = 0; j < 8; j++) se += __expf(ov[j] - m2);
#pragma unroll
        for (int off = 16; off > 0; off >>= 1) se += __shfl_xor_sync(0xffffffffu, se, off);
        float lse = m2 + logf(se);
        float4* op = (float4*)(OUT + (size_t)n * FDIM + ch0);
        op[0] = make_float4(ov[0] - lse, ov[1] - lse, ov[2] - lse, ov[3] - lse);
        op[1] = make_float4(ov[4] - lse, ov[5] - lse, ov[6] - lse, ov[7] - lse);
    }
}

// ---------------- launch ----------------
extern "C" void kernel_launch(void* const* d_in, const int* in_sizes, int n_in,
                              void* d_out, int out_size) {
    const float* x    = (const float*)d_in[0];
    const int*   ei   = (const int*)d_in[1];
    const float* W1   = (const float*)d_in[2];
    const float* as1  = (const float*)d_in[3];
    const float* ad1  = (const float*)d_in[4];
    const float* b1   = (const float*)d_in[5];
    const float* gam1 = (const float*)d_in[6];
    const float* be1  = (const float*)d_in[7];
    const float* m1   = (const float*)d_in[8];
    const float* v1   = (const float*)d_in[9];
    const float* W2   = (const float*)d_in[10];
    const float* as2  = (const float*)d_in[11];
    const float* ad2  = (const float*)d_in[12];
    const float* b2   = (const float*)d_in[13];
    const float* gam2 = (const float*)d_in[14];
    const float* be2  = (const float*)d_in[15];
    const float* m2   = (const float*)d_in[16];
    const float* v2   = (const float*)d_in[17];
    float* out = (float*)d_out;

    __nv_bfloat16 *Ah, *Al;
    __half *bufH;
    float *bnA, *bnB;
    cudaGetSymbolAddress((void**)&Ah, g_Ah);
    cudaGetSymbolAddress((void**)&Al, g_Al);
    cudaGetSymbolAddress((void**)&bufH, g_bufH);
    cudaGetSymbolAddress((void**)&bnA, g_bnA);
    cudaGetSymbolAddress((void**)&bnB, g_bnB);

    const int GSMEM = 2 * GSTAGE;  // 108544
    cudaFuncSetAttribute(k_gemm_mma, cudaFuncAttributeMaxDynamicSharedMemorySize, GSMEM);

    int gemmBlocks = (NNODES + 127) / 128;   // 391
    int nodeBlocks = (NNODES + 7) / 8;

    k_prepA<<<(NNODES * 128 + 255) / 256, 256>>>(x, NNODES * 128);        // 0
    k_prepB<<<(128 * 256 + 255) / 256, 256>>>(W1, 128 * 256);             // 1
    k_init_deg<<<(NNODES + 255) / 256, 256>>>();                          // 2
    k_gemm_mma<<<gemmBlocks, 512, GSMEM>>>(Ah, Al, bufH, 128, as1, ad1);  // 3  <- profiled
    k_count<<<(NEDGES + 255) / 256, 256>>>(ei);                           // 4
    k_scan1<<<NB_SCAN, 512>>>();                                          // 5
    k_scan2<<<1, 32>>>();                                                 // 6
    k_scan3f<<<(NNODES + 255) / 256, 256>>>();                            // 7
    k_fill<<<(NEDGES + 255) / 256, 256>>>(ei);                            // 8
    k_sort<<<(NNODES + 255) / 256, 256>>>();                              // 9
    k_prepBN<<<1, 256>>>(b1, gam1, be1, m1, v1, 0);                       // 10
    k_agg<0><<<nodeBlocks, 256>>>(bufH, bnA, bnB, nullptr);               // 11

    // ---- layer 2 ----
    k_prepB<<<(256 * 256 + 255) / 256, 256>>>(W2, 256 * 256);             // 12
    k_prepBN<<<1, 256>>>(b2, gam2, be2, m2, v2, 1);                       // 13
    k_gemm_mma<<<gemmBlocks, 512, GSMEM>>>(Ah, Al, bufH, 256, as2, ad2);  // 14
    k_agg<1><<<nodeBlocks, 256>>>(bufH, bnA + 256, bnB + 256, out);       // 15
}

// round 8
// speedup vs baseline: 1.8572x; 1.0752x over previous
#include <cuda_runtime.h>
#include <cuda_bf16.h>
#include <cuda_fp16.h>
#include <math.h>
#include <stdint.h>

#define NNODES 50000
#define NEDGES 800000
#define FDIM   256          // H*C
#define TOTE   (NEDGES + NNODES)
#define NB_SCAN ((NNODES + 511) / 512)

// ---------------- scratch (static device globals; no allocation) ----------------
__device__ __nv_bfloat16 g_Ah[(size_t)NNODES * FDIM];  // A operand hi (bf16)
__device__ __nv_bfloat16 g_Al[(size_t)NNODES * FDIM];  // A operand lo (bf16)
__device__ __half g_bufH[(size_t)NNODES * FDIM];       // fp16 h image (gather source)
__device__ float g_asrcv[NNODES * 4];
__device__ float g_adstv[NNODES * 4];
__device__ int   g_deg[NNODES];
__device__ int   g_rowptr[NNODES + 1];
__device__ int   g_cursor[NNODES];
__device__ int   g_srclist[TOTE];
__device__ int   g_blksums[256];
__device__ __nv_bfloat16 g_Bh[65536];   // weights hi, row-major [K][256]
__device__ __nv_bfloat16 g_Bl[65536];   // weights lo
__device__ float g_bnA[512];            // folded BN scale (layer0: [0,256), layer1: [256,512))
__device__ float g_bnB[512];            // folded BN shift
__device__ float g_gmax[8];             // per-head global max of asrc (slot0: [0,4), slot1: [4,8))

// ---------------- PTX helpers (portable: sm_80+ instructions only) ----------------
__device__ __forceinline__ uint32_t s2u(const void* p) {
    uint32_t a;
    asm("{ .reg .u64 t; cvta.to.shared.u64 t, %1; cvt.u32.u64 %0, t; }" : "=r"(a) : "l"(p));
    return a;
}

__device__ __forceinline__ void ldsm4(uint32_t* r, uint32_t addr) {
    asm volatile("ldmatrix.sync.aligned.m8n8.x4.shared.b16 {%0,%1,%2,%3}, [%4];"
                 : "=r"(r[0]), "=r"(r[1]), "=r"(r[2]), "=r"(r[3]) : "r"(addr));
}

__device__ __forceinline__ void ldsm4t(uint32_t* r, uint32_t addr) {
    asm volatile("ldmatrix.sync.aligned.m8n8.x4.trans.shared.b16 {%0,%1,%2,%3}, [%4];"
                 : "=r"(r[0]), "=r"(r[1]), "=r"(r[2]), "=r"(r[3]) : "r"(addr));
}

__device__ __forceinline__ void mma16816(float* d, const uint32_t* a, const uint32_t* b) {
    asm volatile("mma.sync.aligned.m16n8k16.row.col.f32.bf16.bf16.f32 "
                 "{%0,%1,%2,%3}, {%4,%5,%6,%7}, {%8,%9}, {%0,%1,%2,%3};"
                 : "+f"(d[0]), "+f"(d[1]), "+f"(d[2]), "+f"(d[3])
                 : "r"(a[0]), "r"(a[1]), "r"(a[2]), "r"(a[3]), "r"(b[0]), "r"(b[1]));
}

__device__ __forceinline__ void cpasync16(uint32_t dst, const void* src, int sz) {
    asm volatile("cp.async.cg.shared.global [%0], [%1], 16, %2;"
                 :: "r"(dst), "l"(src), "r"(sz) : "memory");
}

__device__ __forceinline__ float lrelu(float e) {
    return (e > 0.f) ? e : 0.2f * e;
}

// float atomic max via integer ordering trick
__device__ __forceinline__ void atomicMaxF(float* a, float v) {
    if (v >= 0.f) atomicMax((int*)a, __float_as_int(v));
    else atomicMin((unsigned int*)a, __float_as_uint(v));
}

// ---------------- CSR build ----------------
__global__ void k_init_deg() {
    int i = blockIdx.x * blockDim.x + threadIdx.x;
    if (i < NNODES) g_deg[i] = 1;   // self loop
}

__global__ void k_count(const int* __restrict__ ei) {
    int i = blockIdx.x * blockDim.x + threadIdx.x;
    if (i < NEDGES) atomicAdd(&g_deg[ei[NEDGES + i]], 1);
}

__global__ void k_scan1() {
    __shared__ int s[512];
    int tid = threadIdx.x;
    int i = blockIdx.x * 512 + tid;
    int v = (i < NNODES) ? g_deg[i] : 0;
    s[tid] = v;
    __syncthreads();
    for (int off = 1; off < 512; off <<= 1) {
        int t = (tid >= off) ? s[tid - off] : 0;
        __syncthreads();
        s[tid] += t;
        __syncthreads();
    }
    if (i < NNODES) g_rowptr[i] = s[tid] - v;
    if (tid == 511) g_blksums[blockIdx.x] = s[511];
}

__global__ void k_scan2() {
    if (threadIdx.x == 0 && blockIdx.x == 0) {
        int run = 0;
        for (int b = 0; b < NB_SCAN; b++) {
            int t = g_blksums[b];
            g_blksums[b] = run;
            run += t;
        }
    }
}

__global__ void k_scan3f() {
    int i = blockIdx.x * blockDim.x + threadIdx.x;
    if (i < NNODES) {
        int r = g_rowptr[i] + g_blksums[i >> 9];
        g_rowptr[i] = r;
        g_srclist[r] = i;        // self loop first
        g_cursor[i] = r + 1;
    }
    if (i == 0) g_rowptr[NNODES] = TOTE;
}

__global__ void k_fill(const int* __restrict__ ei) {
    int i = blockIdx.x * blockDim.x + threadIdx.x;
    if (i < NEDGES) {
        int s = ei[i];
        int d = ei[NEDGES + i];
        int pos = atomicAdd(&g_cursor[d], 1);
        g_srclist[pos] = s;
    }
}

__global__ void k_sort() {
    int n = blockIdx.x * blockDim.x + threadIdx.x;
    if (n >= NNODES) return;
    int beg = g_rowptr[n] + 1;
    int end = g_rowptr[n + 1];
    for (int i = beg + 1; i < end; i++) {
        int key = g_srclist[i];
        int j = i - 1;
        while (j >= beg && g_srclist[j] > key) {
            g_srclist[j + 1] = g_srclist[j];
            j--;
        }
        g_srclist[j + 1] = key;
    }
}

// ---------------- operand splits + BN fold ----------------
__global__ void k_prepB(const float* __restrict__ W, int total) {
    int i = blockIdx.x * 256 + threadIdx.x;
    if (i >= total) return;
    float v = W[i];
    __nv_bfloat16 h = __float2bfloat16_rn(v);
    g_Bh[i] = h;
    g_Bl[i] = __float2bfloat16_rn(v - __bfloat162float(h));
}

__global__ void k_prepA(const float* __restrict__ X, int total) {
    int i = blockIdx.x * 256 + threadIdx.x;
    if (i >= total) return;
    float v = X[i];
    __nv_bfloat16 h = __float2bfloat16_rn(v);
    g_Ah[i] = h;
    g_Al[i] = __float2bfloat16_rn(v - __bfloat162float(h));
}

// folded BN (both layers) + gmax reset, one launch of 512 threads
__global__ void k_prepBN2(const float* __restrict__ b1, const float* __restrict__ g1,
                          const float* __restrict__ be1, const float* __restrict__ m1,
                          const float* __restrict__ v1,
                          const float* __restrict__ b2, const float* __restrict__ g2,
                          const float* __restrict__ be2, const float* __restrict__ m2,
                          const float* __restrict__ v2) {
    int i = threadIdx.x;
    if (i < 256) {
        float s = g1[i] * rsqrtf(v1[i] + 1e-5f);
        g_bnA[i] = s;
        g_bnB[i] = (b1[i] - m1[i]) * s + be1[i];
    } else {
        int j = i - 256;
        float s = g2[j] * rsqrtf(v2[j] + 1e-5f);
        g_bnA[i] = s;
        g_bnB[i] = (b2[j] - m2[j]) * s + be2[j];
    }
    if (i < 8) g_gmax[i] = -1e30f;
}

// ---------------- tensor-core GEMM: cp.async double-buffered, 512 thr, 128x256 tile ----------------
#define GSTAGE 54272
__global__ void __launch_bounds__(512) k_gemm_mma(const __nv_bfloat16* __restrict__ Ahp,
                                                  const __nv_bfloat16* __restrict__ Alp,
                                                  __half* __restrict__ H, int K,
                                                  const float* __restrict__ Asrc,
                                                  const float* __restrict__ Adst,
                                                  float* __restrict__ gmax) {
    extern __shared__ char sm[];
    uint32_t sbase = s2u(sm);

    int tid = threadIdx.x;
    int lane = tid & 31, w = tid >> 5;
    int wm = w & 3, wn = w >> 2;          // warp tile origin (wm*32, wn*64)
    int by = blockIdx.x;
    int nch = K >> 5;

    int ar = tid >> 2, ac = tid & 3;
    int agr = by * 128 + ar;
    int asz = (agr < NNODES) ? 16 : 0;
    int agc = (agr < NNODES) ? agr : 0;
    const char* gAh = (const char*)(Ahp + (size_t)agc * K + ac * 8);
    const char* gAl = (const char*)(Alp + (size_t)agc * K + ac * 8);
    uint32_t dA = (uint32_t)(ar * 80 + ac * 16);

    float acc[2][8][4];
#pragma unroll
    for (int i = 0; i < 2; i++)
#pragma unroll
        for (int j = 0; j < 8; j++)
#pragma unroll
            for (int q = 0; q < 4; q++) acc[i][j][q] = 0.f;

#define ISSUE(kc, s) do {                                                          \
        uint32_t so = sbase + (s) * GSTAGE;                                        \
        cpasync16(so + dA, gAh + (size_t)(kc) * 64, asz);                          \
        cpasync16(so + 10240 + dA, gAl + (size_t)(kc) * 64, asz);                  \
        _Pragma("unroll")                                                          \
        for (int i = 0; i < 2; i++) {                                              \
            int p = tid + 512 * i;                                                 \
            int rr = p >> 5, c2 = p & 31;                                          \
            size_t go = (size_t)((kc) * 32 + rr) * 256 + c2 * 8;                   \
            uint32_t db = so + 20480 + rr * 528 + c2 * 16;                         \
            cpasync16(db, (const char*)(g_Bh + go), 16);                           \
            cpasync16(db + 16896, (const char*)(g_Bl + go), 16);                   \
        }                                                                          \
        asm volatile("cp.async.commit_group;" ::: "memory");                       \
    } while (0)

    ISSUE(0, 0);

    for (int kc = 0; kc < nch; kc++) {
        int s = kc & 1;
        if (kc + 1 < nch) {
            ISSUE(kc + 1, (kc + 1) & 1);
            asm volatile("cp.async.wait_group 1;" ::: "memory");
        } else {
            asm volatile("cp.async.wait_group 0;" ::: "memory");
        }
        __syncthreads();

        uint32_t aoff = sbase + s * GSTAGE;
        uint32_t boff = aoff + 20480;
#pragma unroll
        for (int ks = 0; ks < 2; ks++) {
            uint32_t ah[2][4], al[2][4], bh[4][4], bl[4][4];
#pragma unroll
            for (int mt = 0; mt < 2; mt++) {
                int row = wm * 32 + mt * 16 + (lane & 15);
                uint32_t addr = aoff + row * 80 + ks * 32 + (lane >> 4) * 16;
                ldsm4(ah[mt], addr);
                ldsm4(al[mt], addr + 10240);
            }
#pragma unroll
            for (int nt = 0; nt < 4; nt++) {
                int row = ks * 16 + (lane & 15);
                uint32_t addr = boff + row * 528 + (wn * 64 + nt * 16) * 2 + (lane >> 4) * 16;
                ldsm4t(bh[nt], addr);
                ldsm4t(bl[nt], addr + 16896);
            }
#pragma unroll
            for (int mt = 0; mt < 2; mt++)
#pragma unroll
                for (int nt = 0; nt < 4; nt++)
#pragma unroll
                    for (int h = 0; h < 2; h++) {
                        float* d = acc[mt][nt * 2 + h];
                        mma16816(d, ah[mt], &bh[nt][h * 2]);
                        mma16816(d, ah[mt], &bl[nt][h * 2]);
                        mma16816(d, al[mt], &bh[nt][h * 2]);
                    }
        }
        __syncthreads();
    }

    // ---- epilogue: write fp16 H + fused per-head attention dots + global asrc max ----
    int head = wn;
    float wmax = -1e30f;
#pragma unroll
    for (int mt = 0; mt < 2; mt++) {
        int r0 = by * 128 + wm * 32 + mt * 16 + (lane >> 2);
        float ps0 = 0.f, ps1 = 0.f, pd0 = 0.f, pd1 = 0.f;
#pragma unroll
        for (int nt = 0; nt < 8; nt++) {
            int cc = wn * 64 + nt * 8 + (lane & 3) * 2;
            float as0 = Asrc[cc], as1v = Asrc[cc + 1];
            float ad0 = Adst[cc], ad1v = Adst[cc + 1];
            ps0 += acc[mt][nt][0] * as0 + acc[mt][nt][1] * as1v;
            pd0 += acc[mt][nt][0] * ad0 + acc[mt][nt][1] * ad1v;
            ps1 += acc[mt][nt][2] * as0 + acc[mt][nt][3] * as1v;
            pd1 += acc[mt][nt][2] * ad0 + acc[mt][nt][3] * ad1v;
            if (r0 < NNODES) {
                *(__half2*)(H + (size_t)r0 * FDIM + cc) =
                    __floats2half2_rn(acc[mt][nt][0], acc[mt][nt][1]);
            }
            if (r0 + 8 < NNODES) {
                *(__half2*)(H + (size_t)(r0 + 8) * FDIM + cc) =
                    __floats2half2_rn(acc[mt][nt][2], acc[mt][nt][3]);
            }
        }
#pragma unroll
        for (int off = 1; off <= 2; off <<= 1) {
            ps0 += __shfl_xor_sync(0xffffffffu, ps0, off);
            ps1 += __shfl_xor_sync(0xffffffffu, ps1, off);
            pd0 += __shfl_xor_sync(0xffffffffu, pd0, off);
            pd1 += __shfl_xor_sync(0xffffffffu, pd1, off);
        }
        // rows >= NNODES have acc==0 (zero-filled A) -> ps==0; harmless upper bound
        wmax = fmaxf(wmax, fmaxf(ps0, ps1));
        if ((lane & 3) == 0) {
            if (r0 < NNODES) {
                g_asrcv[r0 * 4 + head] = ps0;
                g_adstv[r0 * 4 + head] = pd0;
            }
            if (r0 + 8 < NNODES) {
                g_asrcv[(r0 + 8) * 4 + head] = ps1;
                g_adstv[(r0 + 8) * 4 + head] = pd1;
            }
        }
    }
#pragma unroll
    for (int off = 4; off <= 16; off <<= 1)
        wmax = fmaxf(wmax, __shfl_xor_sync(0xffffffffu, wmax, off));
    if (lane == 0) atomicMaxF(&gmax[head], wmax);
}

// ---------------- GAT aggregation: single-pass softmax vs global bound ----------------
// alpha = exp(e-m)/sum(exp(e-m)) is invariant to m; m = lrelu(gmax_asrc[h]+adst) >= all e
// (lrelu monotone), so no overflow and score spread is far too small to underflow.
// MODE 0: write bf16 hi/lo (next layer's A operand). MODE 1: log_softmax + fp32 out.
template <int MODE>
__global__ void __launch_bounds__(256) k_agg(const __half* __restrict__ X,
                      const float* __restrict__ bnA,
                      const float* __restrict__ bnB,
                      const float* __restrict__ gmax,
                      float* __restrict__ OUT) {
    int gwarp = (blockIdx.x * blockDim.x + threadIdx.x) >> 5;
    int lane = threadIdx.x & 31;
    if (gwarp >= NNODES) return;
    int n = gwarp;
    int ch0 = lane * 8;
    int hl = lane >> 3;

    const float* __restrict__ sc = g_asrcv;
    const int* __restrict__ lst = g_srclist;

    float adv = g_adstv[n * 4 + hl];
    float mx = lrelu(gmax[hl] + adv);        // upper bound on all edge scores of n
    int r0 = g_rowptr[n], r1 = g_rowptr[n + 1];

    float dsum = 0.f;
    float acc[8];
#pragma unroll
    for (int j = 0; j < 8; j++) acc[j] = 0.f;

    int k = r0;
    for (; k + 3 < r1; k += 4) {
        int s0 = lst[k], s1 = lst[k + 1], s2 = lst[k + 2], s3 = lst[k + 3];
        uint4 ra = *(const uint4*)(X + (size_t)s0 * FDIM + ch0);
        uint4 rb = *(const uint4*)(X + (size_t)s1 * FDIM + ch0);
        uint4 rc = *(const uint4*)(X + (size_t)s2 * FDIM + ch0);
        uint4 rd = *(const uint4*)(X + (size_t)s3 * FDIM + ch0);
        float p0 = __expf(lrelu(sc[s0 * 4 + hl] + adv) - mx);
        float p1 = __expf(lrelu(sc[s1 * 4 + hl] + adv) - mx);
        float p2 = __expf(lrelu(sc[s2 * 4 + hl] + adv) - mx);
        float p3 = __expf(lrelu(sc[s3 * 4 + hl] + adv) - mx);
        dsum += (p0 + p1) + (p2 + p3);
        float2 a0 = __half22float2(*(__half2*)&ra.x);
        float2 a1 = __half22float2(*(__half2*)&ra.y);
        float2 a2 = __half22float2(*(__half2*)&ra.z);
        float2 a3 = __half22float2(*(__half2*)&ra.w);
        float2 b0 = __half22float2(*(__half2*)&rb.x);
        float2 b1 = __half22float2(*(__half2*)&rb.y);
        float2 b2 = __half22float2(*(__half2*)&rb.z);
        float2 b3 = __half22float2(*(__half2*)&rb.w);
        float2 c0 = __half22float2(*(__half2*)&rc.x);
        float2 c1 = __half22float2(*(__half2*)&rc.y);
        float2 c2 = __half22float2(*(__half2*)&rc.z);
        float2 c3 = __half22float2(*(__half2*)&rc.w);
        float2 d0 = __half22float2(*(__half2*)&rd.x);
        float2 d1 = __half22float2(*(__half2*)&rd.y);
        float2 d2 = __half22float2(*(__half2*)&rd.z);
        float2 d3 = __half22float2(*(__half2*)&rd.w);
        acc[0] += (p0 * a0.x + p1 * b0.x) + (p2 * c0.x + p3 * d0.x);
        acc[1] += (p0 * a0.y + p1 * b0.y) + (p2 * c0.y + p3 * d0.y);
        acc[2] += (p0 * a1.x + p1 * b1.x) + (p2 * c1.x + p3 * d1.x);
        acc[3] += (p0 * a1.y + p1 * b1.y) + (p2 * c1.y + p3 * d1.y);
        acc[4] += (p0 * a2.x + p1 * b2.x) + (p2 * c2.x + p3 * d2.x);
        acc[5] += (p0 * a2.y + p1 * b2.y) + (p2 * c2.y + p3 * d2.y);
        acc[6] += (p0 * a3.x + p1 * b3.x) + (p2 * c3.x + p3 * d3.x);
        acc[7] += (p0 * a3.y + p1 * b3.y) + (p2 * c3.y + p3 * d3.y);
    }
    for (; k < r1; k++) {
        int s0 = lst[k];
        uint4 ra = *(const uint4*)(X + (size_t)s0 * FDIM + ch0);
        float p0 = __expf(lrelu(sc[s0 * 4 + hl] + adv) - mx);
        dsum += p0;
        float2 a0 = __half22float2(*(__half2*)&ra.x);
        float2 a1 = __half22float2(*(__half2*)&ra.y);
        float2 a2 = __half22float2(*(__half2*)&ra.z);
        float2 a3 = __half22float2(*(__half2*)&ra.w);
        acc[0] += p0 * a0.x;
        acc[1] += p0 * a0.y;
        acc[2] += p0 * a1.x;
        acc[3] += p0 * a1.y;
        acc[4] += p0 * a2.x;
        acc[5] += p0 * a2.y;
        acc[6] += p0 * a3.x;
        acc[7] += p0 * a3.y;
    }

    float inv = 1.f / (dsum + 1e-16f);
    float ov[8];
#pragma unroll
    for (int j = 0; j < 8; j++) {
        int ch = ch0 + j;
        ov[j] = fmaxf(fmaf(acc[j] * inv, bnA[ch], bnB[ch]), 0.f);
    }

    if (MODE == 0) {
        ushort hs[8], ls[8];
#pragma unroll
        for (int j = 0; j < 8; j++) {
            __nv_bfloat16 h = __float2bfloat16_rn(ov[j]);
            hs[j] = __bfloat16_as_ushort(h);
            ls[j] = __bfloat16_as_ushort(__float2bfloat16_rn(ov[j] - __bfloat162float(h)));
        }
        uint4 hv, lv;
        hv.x = (uint32_t)hs[0] | ((uint32_t)hs[1] << 16);
        hv.y = (uint32_t)hs[2] | ((uint32_t)hs[3] << 16);
        hv.z = (uint32_t)hs[4] | ((uint32_t)hs[5] << 16);
        hv.w = (uint32_t)hs[6] | ((uint32_t)hs[7] << 16);
        lv.x = (uint32_t)ls[0] | ((uint32_t)ls[1] << 16);
        lv.y = (uint32_t)ls[2] | ((uint32_t)ls[3] << 16);
        lv.z = (uint32_t)ls[4] | ((uint32_t)ls[5] << 16);
        lv.w = (uint32_t)ls[6] | ((uint32_t)ls[7] << 16);
        *(uint4*)(g_Ah + (size_t)n * FDIM + ch0) = hv;
        *(uint4*)(g_Al + (size_t)n * FDIM + ch0) = lv;
    } else {
        float m2 = ov[0];
#pragma unroll
        for (int j = 1; j < 8; j++) m2 = fmaxf(m2, ov[j]);
#pragma unroll
        for (int off = 16; off > 0; off >>= 1) m2 = fmaxf(m2, __shfl_xor_sync(0xffffffffu, m2, off));
        float se = 0.f;
#pragma unroll
        for (int j = 0; j < 8; j++) se += __expf(ov[j] - m2);
#pragma unroll
        for (int off = 16; off > 0; off >>= 1) se += __shfl_xor_sync(0xffffffffu, se, off);
        float lse = m2 + logf(se);
        float4* op = (float4*)(OUT + (size_t)n * FDIM + ch0);
        op[0] = make_float4(ov[0] - lse, ov[1] - lse, ov[2] - lse, ov[3] - lse);
        op[1] = make_float4(ov[4] - lse, ov[5] - lse, ov[6] - lse, ov[7] - lse);
    }
}

// ---------------- launch ----------------
extern "C" void kernel_launch(void* const* d_in, const int* in_sizes, int n_in,
                              void* d_out, int out_size) {
    const float* x    = (const float*)d_in[0];
    const int*   ei   = (const int*)d_in[1];
    const float* W1   = (const float*)d_in[2];
    const float* as1  = (const float*)d_in[3];
    const float* ad1  = (const float*)d_in[4];
    const float* b1   = (const float*)d_in[5];
    const float* gam1 = (const float*)d_in[6];
    const float* be1  = (const float*)d_in[7];
    const float* m1   = (const float*)d_in[8];
    const float* v1   = (const float*)d_in[9];
    const float* W2   = (const float*)d_in[10];
    const float* as2  = (const float*)d_in[11];
    const float* ad2  = (const float*)d_in[12];
    const float* b2   = (const float*)d_in[13];
    const float* gam2 = (const float*)d_in[14];
    const float* be2  = (const float*)d_in[15];
    const float* m2   = (const float*)d_in[16];
    const float* v2   = (const float*)d_in[17];
    float* out = (float*)d_out;

    __nv_bfloat16 *Ah, *Al;
    __half *bufH;
    float *bnA, *bnB, *gmax;
    cudaGetSymbolAddress((void**)&Ah, g_Ah);
    cudaGetSymbolAddress((void**)&Al, g_Al);
    cudaGetSymbolAddress((void**)&bufH, g_bufH);
    cudaGetSymbolAddress((void**)&bnA, g_bnA);
    cudaGetSymbolAddress((void**)&bnB, g_bnB);
    cudaGetSymbolAddress((void**)&gmax, g_gmax);

    const int GSMEM = 2 * GSTAGE;  // 108544
    cudaFuncSetAttribute(k_gemm_mma, cudaFuncAttributeMaxDynamicSharedMemorySize, GSMEM);

    int gemmBlocks = (NNODES + 127) / 128;   // 391
    int nodeBlocks = (NNODES + 7) / 8;

    k_prepA<<<(NNODES * 128 + 255) / 256, 256>>>(x, NNODES * 128);              // 0
    k_prepB<<<(128 * 256 + 255) / 256, 256>>>(W1, 128 * 256);                   // 1
    k_prepBN2<<<1, 512>>>(b1, gam1, be1, m1, v1, b2, gam2, be2, m2, v2);        // 2
    k_gemm_mma<<<gemmBlocks, 512, GSMEM>>>(Ah, Al, bufH, 128, as1, ad1, gmax);  // 3  <- profiled
    k_init_deg<<<(NNODES + 255) / 256, 256>>>();                                // 4
    k_count<<<(NEDGES + 255) / 256, 256>>>(ei);                                 // 5
    k_scan1<<<NB_SCAN, 512>>>();                                                // 6
    k_scan2<<<1, 32>>>();                                                       // 7
    k_scan3f<<<(NNODES + 255) / 256, 256>>>();                                  // 8
    k_fill<<<(NEDGES + 255) / 256, 256>>>(ei);                                  // 9
    k_sort<<<(NNODES + 255) / 256, 256>>>();                                    // 10
    k_agg<0><<<nodeBlocks, 256>>>(bufH, bnA, bnB, gmax, nullptr);               // 11

    // ---- layer 2 ----
    k_prepB<<<(256 * 256 + 255) / 256, 256>>>(W2, 256 * 256);                   // 12
    k_gemm_mma<<<gemmBlocks, 512, GSMEM>>>(Ah, Al, bufH, 256, as2, ad2, gmax + 4); // 13
    k_agg<1><<<nodeBlocks, 256>>>(bufH, bnA + 256, bnB + 256, gmax + 4, out);   // 14
}

// round 9
// speedup vs baseline: 1.9297x; 1.0390x over previous
#include <cuda_runtime.h>
#include <cuda_bf16.h>
#include <cuda_fp16.h>
#include <math.h>
#include <stdint.h>

#define NNODES 50000
#define NEDGES 800000
#define FDIM   256          // H*C
#define TOTE   (NEDGES + NNODES)
#define NB_SCAN ((NNODES + 511) / 512)

// ---------------- scratch (static device globals; no allocation) ----------------
__device__ __nv_bfloat16 g_Ah[(size_t)NNODES * FDIM];  // A operand hi (bf16)
__device__ __nv_bfloat16 g_Al[(size_t)NNODES * FDIM];  // A operand lo (bf16)
__device__ __half g_bufH[(size_t)NNODES * FDIM];       // fp16 h image (gather source)
__device__ float g_asrcv[NNODES * 4];
__device__ float g_adstv[NNODES * 4];
__device__ int   g_deg[NNODES];
__device__ int   g_rowptr[NNODES + 1];
__device__ int   g_cursor[NNODES];
__device__ int   g_srclist[TOTE];
__device__ int   g_blksums[256];
__device__ __nv_bfloat16 g_Bh1[65536];  // layer-1 weights hi, row-major [K][256]
__device__ __nv_bfloat16 g_Bl1[65536];
__device__ __nv_bfloat16 g_Bh2[65536];  // layer-2 weights (separate: prepped concurrently w/ gemm1)
__device__ __nv_bfloat16 g_Bl2[65536];
__device__ float g_bnA[512];            // folded BN scale (layer0: [0,256), layer1: [256,512))
__device__ float g_bnB[512];            // folded BN shift
__device__ float g_gmax[8];             // per-head global max of asrc (slot0: [0,4), slot1: [4,8))

// ---------------- PTX helpers (portable: sm_80+ instructions only) ----------------
__device__ __forceinline__ uint32_t s2u(const void* p) {
    uint32_t a;
    asm("{ .reg .u64 t; cvta.to.shared.u64 t, %1; cvt.u32.u64 %0, t; }" : "=r"(a) : "l"(p));
    return a;
}

__device__ __forceinline__ void ldsm4(uint32_t* r, uint32_t addr) {
    asm volatile("ldmatrix.sync.aligned.m8n8.x4.shared.b16 {%0,%1,%2,%3}, [%4];"
                 : "=r"(r[0]), "=r"(r[1]), "=r"(r[2]), "=r"(r[3]) : "r"(addr));
}

__device__ __forceinline__ void ldsm4t(uint32_t* r, uint32_t addr) {
    asm volatile("ldmatrix.sync.aligned.m8n8.x4.trans.shared.b16 {%0,%1,%2,%3}, [%4];"
                 : "=r"(r[0]), "=r"(r[1]), "=r"(r[2]), "=r"(r[3]) : "r"(addr));
}

__device__ __forceinline__ void mma16816(float* d, const uint32_t* a, const uint32_t* b) {
    asm volatile("mma.sync.aligned.m16n8k16.row.col.f32.bf16.bf16.f32 "
                 "{%0,%1,%2,%3}, {%4,%5,%6,%7}, {%8,%9}, {%0,%1,%2,%3};"
                 : "+f"(d[0]), "+f"(d[1]), "+f"(d[2]), "+f"(d[3])
                 : "r"(a[0]), "r"(a[1]), "r"(a[2]), "r"(a[3]), "r"(b[0]), "r"(b[1]));
}

__device__ __forceinline__ void cpasync16(uint32_t dst, const void* src, int sz) {
    asm volatile("cp.async.cg.shared.global [%0], [%1], 16, %2;"
                 :: "r"(dst), "l"(src), "r"(sz) : "memory");
}

__device__ __forceinline__ float lrelu(float e) {
    return (e > 0.f) ? e : 0.2f * e;
}

// float atomic max via integer ordering trick
__device__ __forceinline__ void atomicMaxF(float* a, float v) {
    if (v >= 0.f) atomicMax((int*)a, __float_as_int(v));
    else atomicMin((unsigned int*)a, __float_as_uint(v));
}

// ---------------- CSR build ----------------
__global__ void k_init_deg() {
    int i = blockIdx.x * blockDim.x + threadIdx.x;
    if (i < NNODES) g_deg[i] = 1;   // self loop
}

__global__ void k_count(const int* __restrict__ ei) {
    int i = blockIdx.x * blockDim.x + threadIdx.x;
    if (i < NEDGES) atomicAdd(&g_deg[ei[NEDGES + i]], 1);
}

__global__ void k_scan1() {
    __shared__ int s[512];
    int tid = threadIdx.x;
    int i = blockIdx.x * 512 + tid;
    int v = (i < NNODES) ? g_deg[i] : 0;
    s[tid] = v;
    __syncthreads();
    for (int off = 1; off < 512; off <<= 1) {
        int t = (tid >= off) ? s[tid - off] : 0;
        __syncthreads();
        s[tid] += t;
        __syncthreads();
    }
    if (i < NNODES) g_rowptr[i] = s[tid] - v;
    if (tid == 511) g_blksums[blockIdx.x] = s[511];
}

__global__ void k_scan2() {
    if (threadIdx.x == 0 && blockIdx.x == 0) {
        int run = 0;
        for (int b = 0; b < NB_SCAN; b++) {
            int t = g_blksums[b];
            g_blksums[b] = run;
            run += t;
        }
    }
}

__global__ void k_scan3f() {
    int i = blockIdx.x * blockDim.x + threadIdx.x;
    if (i < NNODES) {
        int r = g_rowptr[i] + g_blksums[i >> 9];
        g_rowptr[i] = r;
        g_srclist[r] = i;        // self loop first
        g_cursor[i] = r + 1;
    }
    if (i == 0) g_rowptr[NNODES] = TOTE;
}

__global__ void k_fill(const int* __restrict__ ei) {
    int i = blockIdx.x * blockDim.x + threadIdx.x;
    if (i < NEDGES) {
        int s = ei[i];
        int d = ei[NEDGES + i];
        int pos = atomicAdd(&g_cursor[d], 1);
        g_srclist[pos] = s;
    }
}

__global__ void k_sort() {
    int n = blockIdx.x * blockDim.x + threadIdx.x;
    if (n >= NNODES) return;
    int beg = g_rowptr[n] + 1;
    int end = g_rowptr[n + 1];
    for (int i = beg + 1; i < end; i++) {
        int key = g_srclist[i];
        int j = i - 1;
        while (j >= beg && g_srclist[j] > key) {
            g_srclist[j + 1] = g_srclist[j];
            j--;
        }
        g_srclist[j + 1] = key;
    }
}

// ---------------- operand splits + BN fold ----------------
__global__ void k_prepB(const float* __restrict__ W,
                        __nv_bfloat16* __restrict__ Bh, __nv_bfloat16* __restrict__ Bl,
                        int total) {
    int i = blockIdx.x * 256 + threadIdx.x;
    if (i >= total) return;
    float v = W[i];
    __nv_bfloat16 h = __float2bfloat16_rn(v);
    Bh[i] = h;
    Bl[i] = __float2bfloat16_rn(v - __bfloat162float(h));
}

__global__ void k_prepA(const float* __restrict__ X, int total) {
    int i = blockIdx.x * 256 + threadIdx.x;
    if (i >= total) return;
    float v = X[i];
    __nv_bfloat16 h = __float2bfloat16_rn(v);
    g_Ah[i] = h;
    g_Al[i] = __float2bfloat16_rn(v - __bfloat162float(h));
}

// folded BN (both layers) + gmax reset, one launch of 512 threads
__global__ void k_prepBN2(const float* __restrict__ b1, const float* __restrict__ g1,
                          const float* __restrict__ be1, const float* __restrict__ m1,
                          const float* __restrict__ v1,
                          const float* __restrict__ b2, const float* __restrict__ g2,
                          const float* __restrict__ be2, const float* __restrict__ m2,
                          const float* __restrict__ v2) {
    int i = threadIdx.x;
    if (i < 256) {
        float s = g1[i] * rsqrtf(v1[i] + 1e-5f);
        g_bnA[i] = s;
        g_bnB[i] = (b1[i] - m1[i]) * s + be1[i];
    } else {
        int j = i - 256;
        float s = g2[j] * rsqrtf(v2[j] + 1e-5f);
        g_bnA[i] = s;
        g_bnB[i] = (b2[j] - m2[j]) * s + be2[j];
    }
    if (i < 8) g_gmax[i] = -1e30f;
}

// ---------------- tensor-core GEMM: cp.async double-buffered, 512 thr, 128x256 tile ----------------
#define GSTAGE 54272
__global__ void __launch_bounds__(512) k_gemm_mma(const __nv_bfloat16* __restrict__ Ahp,
                                                  const __nv_bfloat16* __restrict__ Alp,
                                                  const __nv_bfloat16* __restrict__ Bhp,
                                                  const __nv_bfloat16* __restrict__ Blp,
                                                  __half* __restrict__ H, int K,
                                                  const float* __restrict__ Asrc,
                                                  const float* __restrict__ Adst,
                                                  float* __restrict__ gmax) {
    extern __shared__ char sm[];
    uint32_t sbase = s2u(sm);

    int tid = threadIdx.x;
    int lane = tid & 31, w = tid >> 5;
    int wm = w & 3, wn = w >> 2;          // warp tile origin (wm*32, wn*64)
    int by = blockIdx.x;
    int nch = K >> 5;

    int ar = tid >> 2, ac = tid & 3;
    int agr = by * 128 + ar;
    int asz = (agr < NNODES) ? 16 : 0;
    int agc = (agr < NNODES) ? agr : 0;
    const char* gAh = (const char*)(Ahp + (size_t)agc * K + ac * 8);
    const char* gAl = (const char*)(Alp + (size_t)agc * K + ac * 8);
    uint32_t dA = (uint32_t)(ar * 80 + ac * 16);

    float acc[2][8][4];
#pragma unroll
    for (int i = 0; i < 2; i++)
#pragma unroll
        for (int j = 0; j < 8; j++)
#pragma unroll
            for (int q = 0; q < 4; q++) acc[i][j][q] = 0.f;

#define ISSUE(kc, s) do {                                                          \
        uint32_t so = sbase + (s) * GSTAGE;                                        \
        cpasync16(so + dA, gAh + (size_t)(kc) * 64, asz);                          \
        cpasync16(so + 10240 + dA, gAl + (size_t)(kc) * 64, asz);                  \
        _Pragma("unroll")                                                          \
        for (int i = 0; i < 2; i++) {                                              \
            int p = tid + 512 * i;                                                 \
            int rr = p >> 5, c2 = p & 31;                                          \
            size_t go = (size_t)((kc) * 32 + rr) * 256 + c2 * 8;                   \
            uint32_t db = so + 20480 + rr * 528 + c2 * 16;                         \
            cpasync16(db, (const char*)(Bhp + go), 16);                            \
            cpasync16(db + 16896, (const char*)(Blp + go), 16);                    \
        }                                                                          \
        asm volatile("cp.async.commit_group;" ::: "memory");                       \
    } while (0)

    ISSUE(0, 0);

    for (int kc = 0; kc < nch; kc++) {
        int s = kc & 1;
        if (kc + 1 < nch) {
            ISSUE(kc + 1, (kc + 1) & 1);
            asm volatile("cp.async.wait_group 1;" ::: "memory");
        } else {
            asm volatile("cp.async.wait_group 0;" ::: "memory");
        }
        __syncthreads();

        uint32_t aoff = sbase + s * GSTAGE;
        uint32_t boff = aoff + 20480;
#pragma unroll
        for (int ks = 0; ks < 2; ks++) {
            uint32_t ah[2][4], al[2][4], bh[4][4], bl[4][4];
#pragma unroll
            for (int mt = 0; mt < 2; mt++) {
                int row = wm * 32 + mt * 16 + (lane & 15);
                uint32_t addr = aoff + row * 80 + ks * 32 + (lane >> 4) * 16;
                ldsm4(ah[mt], addr);
                ldsm4(al[mt], addr + 10240);
            }
#pragma unroll
            for (int nt = 0; nt < 4; nt++) {
                int row = ks * 16 + (lane & 15);
                uint32_t addr = boff + row * 528 + (wn * 64 + nt * 16) * 2 + (lane >> 4) * 16;
                ldsm4t(bh[nt], addr);
                ldsm4t(bl[nt], addr + 16896);
            }
#pragma unroll
            for (int mt = 0; mt < 2; mt++)
#pragma unroll
                for (int nt = 0; nt < 4; nt++)
#pragma unroll
                    for (int h = 0; h < 2; h++) {
                        float* d = acc[mt][nt * 2 + h];
                        mma16816(d, ah[mt], &bh[nt][h * 2]);
                        mma16816(d, ah[mt], &bl[nt][h * 2]);
                        mma16816(d, al[mt], &bh[nt][h * 2]);
                    }
        }
        __syncthreads();
    }

    // ---- epilogue: write fp16 H + fused per-head attention dots + global asrc max ----
    int head = wn;
    float wmax = -1e30f;
#pragma unroll
    for (int mt = 0; mt < 2; mt++) {
        int r0 = by * 128 + wm * 32 + mt * 16 + (lane >> 2);
        float ps0 = 0.f, ps1 = 0.f, pd0 = 0.f, pd1 = 0.f;
#pragma unroll
        for (int nt = 0; nt < 8; nt++) {
            int cc = wn * 64 + nt * 8 + (lane & 3) * 2;
            float as0 = Asrc[cc], as1v = Asrc[cc + 1];
            float ad0 = Adst[cc], ad1v = Adst[cc + 1];
            ps0 += acc[mt][nt][0] * as0 + acc[mt][nt][1] * as1v;
            pd0 += acc[mt][nt][0] * ad0 + acc[mt][nt][1] * ad1v;
            ps1 += acc[mt][nt][2] * as0 + acc[mt][nt][3] * as1v;
            pd1 += acc[mt][nt][2] * ad0 + acc[mt][nt][3] * ad1v;
            if (r0 < NNODES) {
                *(__half2*)(H + (size_t)r0 * FDIM + cc) =
                    __floats2half2_rn(acc[mt][nt][0], acc[mt][nt][1]);
            }
            if (r0 + 8 < NNODES) {
                *(__half2*)(H + (size_t)(r0 + 8) * FDIM + cc) =
                    __floats2half2_rn(acc[mt][nt][2], acc[mt][nt][3]);
            }
        }
#pragma unroll
        for (int off = 1; off <= 2; off <<= 1) {
            ps0 += __shfl_xor_sync(0xffffffffu, ps0, off);
            ps1 += __shfl_xor_sync(0xffffffffu, ps1, off);
            pd0 += __shfl_xor_sync(0xffffffffu, pd0, off);
            pd1 += __shfl_xor_sync(0xffffffffu, pd1, off);
        }
        wmax = fmaxf(wmax, fmaxf(ps0, ps1));
        if ((lane & 3) == 0) {
            if (r0 < NNODES) {
                g_asrcv[r0 * 4 + head] = ps0;
                g_adstv[r0 * 4 + head] = pd0;
            }
            if (r0 + 8 < NNODES) {
                g_asrcv[(r0 + 8) * 4 + head] = ps1;
                g_adstv[(r0 + 8) * 4 + head] = pd1;
            }
        }
    }
#pragma unroll
    for (int off = 4; off <= 16; off <<= 1)
        wmax = fmaxf(wmax, __shfl_xor_sync(0xffffffffu, wmax, off));
    if (lane == 0) atomicMaxF(&gmax[head], wmax);
}

// ---------------- GAT aggregation: single-pass softmax vs global bound ----------------
template <int MODE>
__global__ void __launch_bounds__(256) k_agg(const __half* __restrict__ X,
                      const float* __restrict__ bnA,
                      const float* __restrict__ bnB,
                      const float* __restrict__ gmax,
                      float* __restrict__ OUT) {
    int gwarp = (blockIdx.x * blockDim.x + threadIdx.x) >> 5;
    int lane = threadIdx.x & 31;
    if (gwarp >= NNODES) return;
    int n = gwarp;
    int ch0 = lane * 8;
    int hl = lane >> 3;

    const float* __restrict__ sc = g_asrcv;
    const int* __restrict__ lst = g_srclist;

    float adv = g_adstv[n * 4 + hl];
    float mx = lrelu(gmax[hl] + adv);        // upper bound on all edge scores of n
    int r0 = g_rowptr[n], r1 = g_rowptr[n + 1];

    float dsum = 0.f;
    float acc[8];
#pragma unroll
    for (int j = 0; j < 8; j++) acc[j] = 0.f;

    int k = r0;
    for (; k + 3 < r1; k += 4) {
        int s0 = lst[k], s1 = lst[k + 1], s2 = lst[k + 2], s3 = lst[k + 3];
        uint4 ra = *(const uint4*)(X + (size_t)s0 * FDIM + ch0);
        uint4 rb = *(const uint4*)(X + (size_t)s1 * FDIM + ch0);
        uint4 rc = *(const uint4*)(X + (size_t)s2 * FDIM + ch0);
        uint4 rd = *(const uint4*)(X + (size_t)s3 * FDIM + ch0);
        float p0 = __expf(lrelu(sc[s0 * 4 + hl] + adv) - mx);
        float p1 = __expf(lrelu(sc[s1 * 4 + hl] + adv) - mx);
        float p2 = __expf(lrelu(sc[s2 * 4 + hl] + adv) - mx);
        float p3 = __expf(lrelu(sc[s3 * 4 + hl] + adv) - mx);
        dsum += (p0 + p1) + (p2 + p3);
        float2 a0 = __half22float2(*(__half2*)&ra.x);
        float2 a1 = __half22float2(*(__half2*)&ra.y);
        float2 a2 = __half22float2(*(__half2*)&ra.z);
        float2 a3 = __half22float2(*(__half2*)&ra.w);
        float2 b0 = __half22float2(*(__half2*)&rb.x);
        float2 b1 = __half22float2(*(__half2*)&rb.y);
        float2 b2 = __half22float2(*(__half2*)&rb.z);
        float2 b3 = __half22float2(*(__half2*)&rb.w);
        float2 c0 = __half22float2(*(__half2*)&rc.x);
        float2 c1 = __half22float2(*(__half2*)&rc.y);
        float2 c2 = __half22float2(*(__half2*)&rc.z);
        float2 c3 = __half22float2(*(__half2*)&rc.w);
        float2 d0 = __half22float2(*(__half2*)&rd.x);
        float2 d1 = __half22float2(*(__half2*)&rd.y);
        float2 d2 = __half22float2(*(__half2*)&rd.z);
        float2 d3 = __half22float2(*(__half2*)&rd.w);
        acc[0] += (p0 * a0.x + p1 * b0.x) + (p2 * c0.x + p3 * d0.x);
        acc[1] += (p0 * a0.y + p1 * b0.y) + (p2 * c0.y + p3 * d0.y);
        acc[2] += (p0 * a1.x + p1 * b1.x) + (p2 * c1.x + p3 * d1.x);
        acc[3] += (p0 * a1.y + p1 * b1.y) + (p2 * c1.y + p3 * d1.y);
        acc[4] += (p0 * a2.x + p1 * b2.x) + (p2 * c2.x + p3 * d2.x);
        acc[5] += (p0 * a2.y + p1 * b2.y) + (p2 * c2.y + p3 * d2.y);
        acc[6] += (p0 * a3.x + p1 * b3.x) + (p2 * c3.x + p3 * d3.x);
        acc[7] += (p0 * a3.y + p1 * b3.y) + (p2 * c3.y + p3 * d3.y);
    }
    for (; k < r1; k++) {
        int s0 = lst[k];
        uint4 ra = *(const uint4*)(X + (size_t)s0 * FDIM + ch0);
        float p0 = __expf(lrelu(sc[s0 * 4 + hl] + adv) - mx);
        dsum += p0;
        float2 a0 = __half22float2(*(__half2*)&ra.x);
        float2 a1 = __half22float2(*(__half2*)&ra.y);
        float2 a2 = __half22float2(*(__half2*)&ra.z);
        float2 a3 = __half22float2(*(__half2*)&ra.w);
        acc[0] += p0 * a0.x;
        acc[1] += p0 * a0.y;
        acc[2] += p0 * a1.x;
        acc[3] += p0 * a1.y;
        acc[4] += p0 * a2.x;
        acc[5] += p0 * a2.y;
        acc[6] += p0 * a3.x;
        acc[7] += p0 * a3.y;
    }

    float inv = 1.f / (dsum + 1e-16f);
    float ov[8];
#pragma unroll
    for (int j = 0; j < 8; j++) {
        int ch = ch0 + j;
        ov[j] = fmaxf(fmaf(acc[j] * inv, bnA[ch], bnB[ch]), 0.f);
    }

    if (MODE == 0) {
        ushort hs[8], ls[8];
#pragma unroll
        for (int j = 0; j < 8; j++) {
            __nv_bfloat16 h = __float2bfloat16_rn(ov[j]);
            hs[j] = __bfloat16_as_ushort(h);
            ls[j] = __bfloat16_as_ushort(__float2bfloat16_rn(ov[j] - __bfloat162float(h)));
        }
        uint4 hv, lv;
        hv.x = (uint32_t)hs[0] | ((uint32_t)hs[1] << 16);
        hv.y = (uint32_t)hs[2] | ((uint32_t)hs[3] << 16);
        hv.z = (uint32_t)hs[4] | ((uint32_t)hs[5] << 16);
        hv.w = (uint32_t)hs[6] | ((uint32_t)hs[7] << 16);
        lv.x = (uint32_t)ls[0] | ((uint32_t)ls[1] << 16);
        lv.y = (uint32_t)ls[2] | ((uint32_t)ls[3] << 16);
        lv.z = (uint32_t)ls[4] | ((uint32_t)ls[5] << 16);
        lv.w = (uint32_t)ls[6] | ((uint32_t)ls[7] << 16);
        *(uint4*)(g_Ah + (size_t)n * FDIM + ch0) = hv;
        *(uint4*)(g_Al + (size_t)n * FDIM + ch0) = lv;
    } else {
        float m2 = ov[0];
#pragma unroll
        for (int j = 1; j < 8; j++) m2 = fmaxf(m2, ov[j]);
#pragma unroll
        for (int off = 16; off > 0; off >>= 1) m2 = fmaxf(m2, __shfl_xor_sync(0xffffffffu, m2, off));
        float se = 0.f;
#pragma unroll
        for (int j = 0; j < 8; j++) se += __expf(ov[j] - m2);
#pragma unroll
        for (int off = 16; off > 0; off >>= 1) se += __shfl_xor_sync(0xffffffffu, se, off);
        float lse = m2 + logf(se);
        float4* op = (float4*)(OUT + (size_t)n * FDIM + ch0);
        op[0] = make_float4(ov[0] - lse, ov[1] - lse, ov[2] - lse, ov[3] - lse);
        op[1] = make_float4(ov[4] - lse, ov[5] - lse, ov[6] - lse, ov[7] - lse);
    }
}

// ---------------- launch: fork CSR chain onto a second captured stream ----------------
extern "C" void kernel_launch(void* const* d_in, const int* in_sizes, int n_in,
                              void* d_out, int out_size) {
    const float* x    = (const float*)d_in[0];
    const int*   ei   = (const int*)d_in[1];
    const float* W1   = (const float*)d_in[2];
    const float* as1  = (const float*)d_in[3];
    const float* ad1  = (const float*)d_in[4];
    const float* b1   = (const float*)d_in[5];
    const float* gam1 = (const float*)d_in[6];
    const float* be1  = (const float*)d_in[7];
    const float* m1   = (const float*)d_in[8];
    const float* v1   = (const float*)d_in[9];
    const float* W2   = (const float*)d_in[10];
    const float* as2  = (const float*)d_in[11];
    const float* ad2  = (const float*)d_in[12];
    const float* b2   = (const float*)d_in[13];
    const float* gam2 = (const float*)d_in[14];
    const float* be2  = (const float*)d_in[15];
    const float* m2   = (const float*)d_in[16];
    const float* v2   = (const float*)d_in[17];
    float* out = (float*)d_out;

    __nv_bfloat16 *Ah, *Al, *Bh1, *Bl1, *Bh2, *Bl2;
    __half *bufH;
    float *bnA, *bnB, *gmax;
    cudaGetSymbolAddress((void**)&Ah, g_Ah);
    cudaGetSymbolAddress((void**)&Al, g_Al);
    cudaGetSymbolAddress((void**)&Bh1, g_Bh1);
    cudaGetSymbolAddress((void**)&Bl1, g_Bl1);
    cudaGetSymbolAddress((void**)&Bh2, g_Bh2);
    cudaGetSymbolAddress((void**)&Bl2, g_Bl2);
    cudaGetSymbolAddress((void**)&bufH, g_bufH);
    cudaGetSymbolAddress((void**)&bnA, g_bnA);
    cudaGetSymbolAddress((void**)&bnB, g_bnB);
    cudaGetSymbolAddress((void**)&gmax, g_gmax);

    // side stream + fork/join events (host objects; created once, before any capture)
    static cudaStream_t s2 = nullptr;
    static cudaEvent_t evF = nullptr, evJ = nullptr;
    if (s2 == nullptr) {
        cudaStreamCreateWithFlags(&s2, cudaStreamNonBlocking);
        cudaEventCreateWithFlags(&evF, cudaEventDisableTiming);
        cudaEventCreateWithFlags(&evJ, cudaEventDisableTiming);
    }

    const int GSMEM = 2 * GSTAGE;  // 108544
    cudaFuncSetAttribute(k_gemm_mma, cudaFuncAttributeMaxDynamicSharedMemorySize, GSMEM);

    int gemmBlocks = (NNODES + 127) / 128;   // 391
    int nodeBlocks = (NNODES + 7) / 8;

    // ---- fork ----
    cudaEventRecord(evF, 0);
    cudaStreamWaitEvent(s2, evF, 0);

    // branch B (stream s2): CSR build + layer-2 weight prep (independent of x/W1)
    k_init_deg<<<(NNODES + 255) / 256, 256, 0, s2>>>();
    k_count<<<(NEDGES + 255) / 256, 256, 0, s2>>>(ei);
    k_scan1<<<NB_SCAN, 512, 0, s2>>>();
    k_scan2<<<1, 32, 0, s2>>>();
    k_scan3f<<<(NNODES + 255) / 256, 256, 0, s2>>>();
    k_fill<<<(NEDGES + 255) / 256, 256, 0, s2>>>(ei);
    k_sort<<<(NNODES + 255) / 256, 256, 0, s2>>>();
    k_prepB<<<(256 * 256 + 255) / 256, 256, 0, s2>>>(W2, Bh2, Bl2, 256 * 256);
    cudaEventRecord(evJ, s2);

    // branch A (stream 0): operand prep + layer-1 GEMM
    k_prepA<<<(NNODES * 128 + 255) / 256, 256>>>(x, NNODES * 128);
    k_prepB<<<(128 * 256 + 255) / 256, 256>>>(W1, Bh1, Bl1, 128 * 256);
    k_prepBN2<<<1, 512>>>(b1, gam1, be1, m1, v1, b2, gam2, be2, m2, v2);
    k_gemm_mma<<<gemmBlocks, 512, GSMEM>>>(Ah, Al, Bh1, Bl1, bufH, 128, as1, ad1, gmax);

    // ---- join ----
    cudaStreamWaitEvent(0, evJ, 0);

    k_agg<0><<<nodeBlocks, 256>>>(bufH, bnA, bnB, gmax, nullptr);
    k_gemm_mma<<<gemmBlocks, 512, GSMEM>>>(Ah, Al, Bh2, Bl2, bufH, 256, as2, ad2, gmax + 4);
    k_agg<1><<<nodeBlocks, 256>>>(bufH, bnA + 256, bnB + 256, gmax + 4, out);
}

// round 10
// speedup vs baseline: 2.2645x; 1.1735x over previous
#include <cuda_runtime.h>
#include <cuda_bf16.h>
#include <cuda_fp16.h>
#include <math.h>
#include <stdint.h>

#define NNODES 50000
#define NEDGES 800000
#define FDIM   256          // H*C
#define TOTE   (NEDGES + NNODES)
#define NB_SCAN ((NNODES + 511) / 512)

// ---------------- scratch (static device globals; no allocation) ----------------
__device__ __half g_A16[(size_t)NNODES * FDIM];   // fp16 A operand (layer1: stride 128, layer2: stride 256)
__device__ __half g_bufH[(size_t)NNODES * FDIM];  // fp16 h image (gather source)
__device__ float g_asrcv[NNODES * 4];
__device__ float g_adstv[NNODES * 4];
__device__ int   g_deg[NNODES];
__device__ int   g_rowptr[NNODES + 1];
__device__ int   g_cursor[NNODES];
__device__ int   g_srclist[TOTE];
__device__ int   g_blksums[256];
__device__ __half g_B16_1[32768];       // layer-1 weights fp16, row-major [128][256]
__device__ __half g_B16_2[65536];       // layer-2 weights fp16, row-major [256][256]
__device__ float g_bnA[512];            // folded BN scale (layer0: [0,256), layer1: [256,512))
__device__ float g_bnB[512];            // folded BN shift
__device__ float g_gmax[8];             // per-head global max of asrc (slot0: [0,4), slot1: [4,8))

// ---------------- PTX helpers (portable: sm_80+ instructions only) ----------------
__device__ __forceinline__ uint32_t s2u(const void* p) {
    uint32_t a;
    asm("{ .reg .u64 t; cvta.to.shared.u64 t, %1; cvt.u32.u64 %0, t; }" : "=r"(a) : "l"(p));
    return a;
}

__device__ __forceinline__ void ldsm4(uint32_t* r, uint32_t addr) {
    asm volatile("ldmatrix.sync.aligned.m8n8.x4.shared.b16 {%0,%1,%2,%3}, [%4];"
                 : "=r"(r[0]), "=r"(r[1]), "=r"(r[2]), "=r"(r[3]) : "r"(addr));
}

__device__ __forceinline__ void ldsm4t(uint32_t* r, uint32_t addr) {
    asm volatile("ldmatrix.sync.aligned.m8n8.x4.trans.shared.b16 {%0,%1,%2,%3}, [%4];"
                 : "=r"(r[0]), "=r"(r[1]), "=r"(r[2]), "=r"(r[3]) : "r"(addr));
}

__device__ __forceinline__ void mma16816h(float* d, const uint32_t* a, const uint32_t* b) {
    asm volatile("mma.sync.aligned.m16n8k16.row.col.f32.f16.f16.f32 "
                 "{%0,%1,%2,%3}, {%4,%5,%6,%7}, {%8,%9}, {%0,%1,%2,%3};"
                 : "+f"(d[0]), "+f"(d[1]), "+f"(d[2]), "+f"(d[3])
                 : "r"(a[0]), "r"(a[1]), "r"(a[2]), "r"(a[3]), "r"(b[0]), "r"(b[1]));
}

__device__ __forceinline__ void cpasync16(uint32_t dst, const void* src, int sz) {
    asm volatile("cp.async.cg.shared.global [%0], [%1], 16, %2;"
                 :: "r"(dst), "l"(src), "r"(sz) : "memory");
}

__device__ __forceinline__ float lrelu(float e) {
    return (e > 0.f) ? e : 0.2f * e;
}

// float atomic max via integer ordering trick
__device__ __forceinline__ void atomicMaxF(float* a, float v) {
    if (v >= 0.f) atomicMax((int*)a, __float_as_int(v));
    else atomicMin((unsigned int*)a, __float_as_uint(v));
}

// ---------------- CSR build ----------------
__global__ void k_init_deg() {
    int i = blockIdx.x * blockDim.x + threadIdx.x;
    if (i < NNODES) g_deg[i] = 1;   // self loop
}

__global__ void k_count(const int* __restrict__ ei) {
    int i = blockIdx.x * blockDim.x + threadIdx.x;
    if (i < NEDGES) atomicAdd(&g_deg[ei[NEDGES + i]], 1);
}

__global__ void k_scan1() {
    __shared__ int s[512];
    int tid = threadIdx.x;
    int i = blockIdx.x * 512 + tid;
    int v = (i < NNODES) ? g_deg[i] : 0;
    s[tid] = v;
    __syncthreads();
    for (int off = 1; off < 512; off <<= 1) {
        int t = (tid >= off) ? s[tid - off] : 0;
        __syncthreads();
        s[tid] += t;
        __syncthreads();
    }
    if (i < NNODES) g_rowptr[i] = s[tid] - v;
    if (tid == 511) g_blksums[blockIdx.x] = s[511];
}

__global__ void k_scan2() {
    if (threadIdx.x == 0 && blockIdx.x == 0) {
        int run = 0;
        for (int b = 0; b < NB_SCAN; b++) {
            int t = g_blksums[b];
            g_blksums[b] = run;
            run += t;
        }
    }
}

__global__ void k_scan3f() {
    int i = blockIdx.x * blockDim.x + threadIdx.x;
    if (i < NNODES) {
        int r = g_rowptr[i] + g_blksums[i >> 9];
        g_rowptr[i] = r;
        g_srclist[r] = i;        // self loop first
        g_cursor[i] = r + 1;
    }
    if (i == 0) g_rowptr[NNODES] = TOTE;
}

__global__ void k_fill(const int* __restrict__ ei) {
    int i = blockIdx.x * blockDim.x + threadIdx.x;
    if (i < NEDGES) {
        int s = ei[i];
        int d = ei[NEDGES + i];
        int pos = atomicAdd(&g_cursor[d], 1);
        g_srclist[pos] = s;
    }
}

__global__ void k_sort() {
    int n = blockIdx.x * blockDim.x + threadIdx.x;
    if (n >= NNODES) return;
    int beg = g_rowptr[n] + 1;
    int end = g_rowptr[n + 1];
    for (int i = beg + 1; i < end; i++) {
        int key = g_srclist[i];
        int j = i - 1;
        while (j >= beg && g_srclist[j] > key) {
            g_srclist[j + 1] = g_srclist[j];
            j--;
        }
        g_srclist[j + 1] = key;
    }
}

// ---------------- operand conversion + BN fold ----------------
__global__ void k_prepB(const float* __restrict__ W, __half* __restrict__ B, int total) {
    int i = blockIdx.x * 256 + threadIdx.x;
    if (i >= total) return;
    B[i] = __float2half_rn(W[i]);
}

__global__ void k_prepA(const float* __restrict__ X, int total) {
    int i = blockIdx.x * 256 + threadIdx.x;
    if (i >= total) return;
    g_A16[i] = __float2half_rn(X[i]);
}

// folded BN (both layers) + gmax reset, one launch of 512 threads
__global__ void k_prepBN2(const float* __restrict__ b1, const float* __restrict__ g1,
                          const float* __restrict__ be1, const float* __restrict__ m1,
                          const float* __restrict__ v1,
                          const float* __restrict__ b2, const float* __restrict__ g2,
                          const float* __restrict__ be2, const float* __restrict__ m2,
                          const float* __restrict__ v2) {
    int i = threadIdx.x;
    if (i < 256) {
        float s = g1[i] * rsqrtf(v1[i] + 1e-5f);
        g_bnA[i] = s;
        g_bnB[i] = (b1[i] - m1[i]) * s + be1[i];
    } else {
        int j = i - 256;
        float s = g2[j] * rsqrtf(v2[j] + 1e-5f);
        g_bnA[i] = s;
        g_bnB[i] = (b2[j] - m2[j]) * s + be2[j];
    }
    if (i < 8) g_gmax[i] = -1e30f;
}

// ---------------- fp16 tensor-core GEMM: cp.async double-buffered, 512 thr, 128x256 tile ----------------
// stage: A[128][80B] (10240) + B[32][528B] (16896) = 27136 B; 2 stages.
#define GSTAGE 27136
__global__ void __launch_bounds__(512) k_gemm_mma(const __half* __restrict__ Ap,
                                                  const __half* __restrict__ Bp,
                                                  __half* __restrict__ H, int K,
                                                  const float* __restrict__ Asrc,
                                                  const float* __restrict__ Adst,
                                                  float* __restrict__ gmax) {
    extern __shared__ char sm[];
    uint32_t sbase = s2u(sm);

    int tid = threadIdx.x;
    int lane = tid & 31, w = tid >> 5;
    int wm = w & 3, wn = w >> 2;          // warp tile origin (wm*32, wn*64)
    int by = blockIdx.x;
    int nch = K >> 5;

    int ar = tid >> 2, ac = tid & 3;
    int agr = by * 128 + ar;
    int asz = (agr < NNODES) ? 16 : 0;
    int agc = (agr < NNODES) ? agr : 0;
    const char* gA = (const char*)(Ap + (size_t)agc * K + ac * 8);
    uint32_t dA = (uint32_t)(ar * 80 + ac * 16);

    float acc[2][8][4];
#pragma unroll
    for (int i = 0; i < 2; i++)
#pragma unroll
        for (int j = 0; j < 8; j++)
#pragma unroll
            for (int q = 0; q < 4; q++) acc[i][j][q] = 0.f;

#define ISSUE(kc, s) do {                                                          \
        uint32_t so = sbase + (s) * GSTAGE;                                        \
        cpasync16(so + dA, gA + (size_t)(kc) * 64, asz);                           \
        _Pragma("unroll")                                                          \
        for (int i = 0; i < 2; i++) {                                              \
            int p = tid + 512 * i;                                                 \
            int rr = p >> 5, c2 = p & 31;                                          \
            size_t go = (size_t)((kc) * 32 + rr) * 256 + c2 * 8;                   \
            cpasync16(so + 10240 + rr * 528 + c2 * 16, (const char*)(Bp + go), 16);\
        }                                                                          \
        asm volatile("cp.async.commit_group;" ::: "memory");                       \
    } while (0)

    ISSUE(0, 0);

    for (int kc = 0; kc < nch; kc++) {
        int s = kc & 1;
        if (kc + 1 < nch) {
            ISSUE(kc + 1, (kc + 1) & 1);
            asm volatile("cp.async.wait_group 1;" ::: "memory");
        } else {
            asm volatile("cp.async.wait_group 0;" ::: "memory");
        }
        __syncthreads();

        uint32_t aoff = sbase + s * GSTAGE;
        uint32_t boff = aoff + 10240;
#pragma unroll
        for (int ks = 0; ks < 2; ks++) {
            uint32_t av[2][4], bv[4][4];
#pragma unroll
            for (int mt = 0; mt < 2; mt++) {
                int row = wm * 32 + mt * 16 + (lane & 15);
                ldsm4(av[mt], aoff + row * 80 + ks * 32 + (lane >> 4) * 16);
            }
#pragma unroll
            for (int nt = 0; nt < 4; nt++) {
                int row = ks * 16 + (lane & 15);
                ldsm4t(bv[nt], boff + row * 528 + (wn * 64 + nt * 16) * 2 + (lane >> 4) * 16);
            }
#pragma unroll
            for (int mt = 0; mt < 2; mt++)
#pragma unroll
                for (int nt = 0; nt < 4; nt++)
#pragma unroll
                    for (int h = 0; h < 2; h++)
                        mma16816h(acc[mt][nt * 2 + h], av[mt], &bv[nt][h * 2]);
        }
        __syncthreads();
    }

    // ---- epilogue: write fp16 H + fused per-head attention dots + global asrc max ----
    int head = wn;
    float wmax = -1e30f;
#pragma unroll
    for (int mt = 0; mt < 2; mt++) {
        int r0 = by * 128 + wm * 32 + mt * 16 + (lane >> 2);
        float ps0 = 0.f, ps1 = 0.f, pd0 = 0.f, pd1 = 0.f;
#pragma unroll
        for (int nt = 0; nt < 8; nt++) {
            int cc = wn * 64 + nt * 8 + (lane & 3) * 2;
            float as0 = Asrc[cc], as1v = Asrc[cc + 1];
            float ad0 = Adst[cc], ad1v = Adst[cc + 1];
            ps0 += acc[mt][nt][0] * as0 + acc[mt][nt][1] * as1v;
            pd0 += acc[mt][nt][0] * ad0 + acc[mt][nt][1] * ad1v;
            ps1 += acc[mt][nt][2] * as0 + acc[mt][nt][3] * as1v;
            pd1 += acc[mt][nt][2] * ad0 + acc[mt][nt][3] * ad1v;
            if (r0 < NNODES) {
                *(__half2*)(H + (size_t)r0 * FDIM + cc) =
                    __floats2half2_rn(acc[mt][nt][0], acc[mt][nt][1]);
            }
            if (r0 + 8 < NNODES) {
                *(__half2*)(H + (size_t)(r0 + 8) * FDIM + cc) =
                    __floats2half2_rn(acc[mt][nt][2], acc[mt][nt][3]);
            }
        }
#pragma unroll
        for (int off = 1; off <= 2; off <<= 1) {
            ps0 += __shfl_xor_sync(0xffffffffu, ps0, off);
            ps1 += __shfl_xor_sync(0xffffffffu, ps1, off);
            pd0 += __shfl_xor_sync(0xffffffffu, pd0, off);
            pd1 += __shfl_xor_sync(0xffffffffu, pd1, off);
        }
        wmax = fmaxf(wmax, fmaxf(ps0, ps1));
        if ((lane & 3) == 0) {
            if (r0 < NNODES) {
                g_asrcv[r0 * 4 + head] = ps0;
                g_adstv[r0 * 4 + head] = pd0;
            }
            if (r0 + 8 < NNODES) {
                g_asrcv[(r0 + 8) * 4 + head] = ps1;
                g_adstv[(r0 + 8) * 4 + head] = pd1;
            }
        }
    }
#pragma unroll
    for (int off = 4; off <= 16; off <<= 1)
        wmax = fmaxf(wmax, __shfl_xor_sync(0xffffffffu, wmax, off));
    if (lane == 0) atomicMaxF(&gmax[head], wmax);
}

// ---------------- GAT aggregation: single-pass softmax vs global bound ----------------
// MODE 0: write fp16 (next layer's A operand, stride 256). MODE 1: log_softmax + fp32 out.
template <int MODE>
__global__ void __launch_bounds__(256) k_agg(const __half* __restrict__ X,
                      const float* __restrict__ bnA,
                      const float* __restrict__ bnB,
                      const float* __restrict__ gmax,
                      float* __restrict__ OUT) {
    int gwarp = (blockIdx.x * blockDim.x + threadIdx.x) >> 5;
    int lane = threadIdx.x & 31;
    if (gwarp >= NNODES) return;
    int n = gwarp;
    int ch0 = lane * 8;
    int hl = lane >> 3;

    const float* __restrict__ sc = g_asrcv;
    const int* __restrict__ lst = g_srclist;

    float adv = g_adstv[n * 4 + hl];
    float mx = lrelu(gmax[hl] + adv);        // upper bound on all edge scores of n
    int r0 = g_rowptr[n], r1 = g_rowptr[n + 1];

    float dsum = 0.f;
    float acc[8];
#pragma unroll
    for (int j = 0; j < 8; j++) acc[j] = 0.f;

    int k = r0;
    for (; k + 3 < r1; k += 4) {
        int s0 = lst[k], s1 = lst[k + 1], s2 = lst[k + 2], s3 = lst[k + 3];
        uint4 ra = *(const uint4*)(X + (size_t)s0 * FDIM + ch0);
        uint4 rb = *(const uint4*)(X + (size_t)s1 * FDIM + ch0);
        uint4 rc = *(const uint4*)(X + (size_t)s2 * FDIM + ch0);
        uint4 rd = *(const uint4*)(X + (size_t)s3 * FDIM + ch0);
        float p0 = __expf(lrelu(sc[s0 * 4 + hl] + adv) - mx);
        float p1 = __expf(lrelu(sc[s1 * 4 + hl] + adv) - mx);
        float p2 = __expf(lrelu(sc[s2 * 4 + hl] + adv) - mx);
        float p3 = __expf(lrelu(sc[s3 * 4 + hl] + adv) - mx);
        dsum += (p0 + p1) + (p2 + p3);
        float2 a0 = __half22float2(*(__half2*)&ra.x);
        float2 a1 = __half22float2(*(__half2*)&ra.y);
        float2 a2 = __half22float2(*(__half2*)&ra.z);
        float2 a3 = __half22float2(*(__half2*)&ra.w);
        float2 b0 = __half22float2(*(__half2*)&rb.x);
        float2 b1 = __half22float2(*(__half2*)&rb.y);
        float2 b2 = __half22float2(*(__half2*)&rb.z);
        float2 b3 = __half22float2(*(__half2*)&rb.w);
        float2 c0 = __half22float2(*(__half2*)&rc.x);
        float2 c1 = __half22float2(*(__half2*)&rc.y);
        float2 c2 = __half22float2(*(__half2*)&rc.z);
        float2 c3 = __half22float2(*(__half2*)&rc.w);
        float2 d0 = __half22float2(*(__half2*)&rd.x);
        float2 d1 = __half22float2(*(__half2*)&rd.y);
        float2 d2 = __half22float2(*(__half2*)&rd.z);
        float2 d3 = __half22float2(*(__half2*)&rd.w);
        acc[0] += (p0 * a0.x + p1 * b0.x) + (p2 * c0.x + p3 * d0.x);
        acc[1] += (p0 * a0.y + p1 * b0.y) + (p2 * c0.y + p3 * d0.y);
        acc[2] += (p0 * a1.x + p1 * b1.x) + (p2 * c1.x + p3 * d1.x);
        acc[3] += (p0 * a1.y + p1 * b1.y) + (p2 * c1.y + p3 * d1.y);
        acc[4] += (p0 * a2.x + p1 * b2.x) + (p2 * c2.x + p3 * d2.x);
        acc[5] += (p0 * a2.y + p1 * b2.y) + (p2 * c2.y + p3 * d2.y);
        acc[6] += (p0 * a3.x + p1 * b3.x) + (p2 * c3.x + p3 * d3.x);
        acc[7] += (p0 * a3.y + p1 * b3.y) + (p2 * c3.y + p3 * d3.y);
    }
    for (; k < r1; k++) {
        int s0 = lst[k];
        uint4 ra = *(const uint4*)(X + (size_t)s0 * FDIM + ch0);
        float p0 = __expf(lrelu(sc[s0 * 4 + hl] + adv) - mx);
        dsum += p0;
        float2 a0 = __half22float2(*(__half2*)&ra.x);
        float2 a1 = __half22float2(*(__half2*)&ra.y);
        float2 a2 = __half22float2(*(__half2*)&ra.z);
        float2 a3 = __half22float2(*(__half2*)&ra.w);
        acc[0] += p0 * a0.x;
        acc[1] += p0 * a0.y;
        acc[2] += p0 * a1.x;
        acc[3] += p0 * a1.y;
        acc[4] += p0 * a2.x;
        acc[5] += p0 * a2.y;
        acc[6] += p0 * a3.x;
        acc[7] += p0 * a3.y;
    }

    float inv = 1.f / (dsum + 1e-16f);
    float ov[8];
#pragma unroll
    for (int j = 0; j < 8; j++) {
        int ch = ch0 + j;
        ov[j] = fmaxf(fmaf(acc[j] * inv, bnA[ch], bnB[ch]), 0.f);
    }

    if (MODE == 0) {
        // emit fp16 (layer-2 A operand)
        uint4 hv;
        *(__half2*)&hv.x = __floats2half2_rn(ov[0], ov[1]);
        *(__half2*)&hv.y = __floats2half2_rn(ov[2], ov[3]);
        *(__half2*)&hv.z = __floats2half2_rn(ov[4], ov[5]);
        *(__half2*)&hv.w = __floats2half2_rn(ov[6], ov[7]);
        *(uint4*)(g_A16 + (size_t)n * FDIM + ch0) = hv;
    } else {
        float m2 = ov[0];
#pragma unroll
        for (int j = 1; j < 8; j++) m2 = fmaxf(m2, ov[j]);
#pragma unroll
        for (int off = 16; off > 0; off >>= 1) m2 = fmaxf(m2, __shfl_xor_sync(0xffffffffu, m2, off));
        float se = 0.f;
#pragma unroll
        for (int j = 0; j < 8; j++) se += __expf(ov[j] - m2);
#pragma unroll
        for (int off = 16; off > 0; off >>= 1) se += __shfl_xor_sync(0xffffffffu, se, off);
        float lse = m2 + logf(se);
        float4* op = (float4*)(OUT + (size_t)n * FDIM + ch0);
        op[0] = make_float4(ov[0] - lse, ov[1] - lse, ov[2] - lse, ov[3] - lse);
        op[1] = make_float4(ov[4] - lse, ov[5] - lse, ov[6] - lse, ov[7] - lse);
    }
}

// ---------------- launch: fork CSR chain onto a second captured stream ----------------
extern "C" void kernel_launch(void* const* d_in, const int* in_sizes, int n_in,
                              void* d_out, int out_size) {
    const float* x    = (const float*)d_in[0];
    const int*   ei   = (const int*)d_in[1];
    const float* W1   = (const float*)d_in[2];
    const float* as1  = (const float*)d_in[3];
    const float* ad1  = (const float*)d_in[4];
    const float* b1   = (const float*)d_in[5];
    const float* gam1 = (const float*)d_in[6];
    const float* be1  = (const float*)d_in[7];
    const float* m1   = (const float*)d_in[8];
    const float* v1   = (const float*)d_in[9];
    const float* W2   = (const float*)d_in[10];
    const float* as2  = (const float*)d_in[11];
    const float* ad2  = (const float*)d_in[12];
    const float* b2   = (const float*)d_in[13];
    const float* gam2 = (const float*)d_in[14];
    const float* be2  = (const float*)d_in[15];
    const float* m2   = (const float*)d_in[16];
    const float* v2   = (const float*)d_in[17];
    float* out = (float*)d_out;

    __half *A16, *B1, *B2, *bufH;
    float *bnA, *bnB, *gmax;
    cudaGetSymbolAddress((void**)&A16, g_A16);
    cudaGetSymbolAddress((void**)&B1, g_B16_1);
    cudaGetSymbolAddress((void**)&B2, g_B16_2);
    cudaGetSymbolAddress((void**)&bufH, g_bufH);
    cudaGetSymbolAddress((void**)&bnA, g_bnA);
    cudaGetSymbolAddress((void**)&bnB, g_bnB);
    cudaGetSymbolAddress((void**)&gmax, g_gmax);

    // side stream + fork/join events (host objects; created once, before any capture)
    static cudaStream_t s2 = nullptr;
    static cudaEvent_t evF = nullptr, evJ = nullptr;
    if (s2 == nullptr) {
        cudaStreamCreateWithFlags(&s2, cudaStreamNonBlocking);
        cudaEventCreateWithFlags(&evF, cudaEventDisableTiming);
        cudaEventCreateWithFlags(&evJ, cudaEventDisableTiming);
    }

    const int GSMEM = 2 * GSTAGE;  // 54272
    cudaFuncSetAttribute(k_gemm_mma, cudaFuncAttributeMaxDynamicSharedMemorySize, GSMEM);

    int gemmBlocks = (NNODES + 127) / 128;   // 391
    int nodeBlocks = (NNODES + 7) / 8;

    // ---- fork ----
    cudaEventRecord(evF, 0);
    cudaStreamWaitEvent(s2, evF, 0);

    // branch B (stream s2): CSR build + layer-2 weight prep (independent of x/W1)
    k_init_deg<<<(NNODES + 255) / 256, 256, 0, s2>>>();
    k_count<<<(NEDGES + 255) / 256, 256, 0, s2>>>(ei);
    k_scan1<<<NB_SCAN, 512, 0, s2>>>();
    k_scan2<<<1, 32, 0, s2>>>();
    k_scan3f<<<(NNODES + 255) / 256, 256, 0, s2>>>();
    k_fill<<<(NEDGES + 255) / 256, 256, 0, s2>>>(ei);
    k_sort<<<(NNODES + 255) / 256, 256, 0, s2>>>();
    k_prepB<<<(256 * 256 + 255) / 256, 256, 0, s2>>>(W2, B2, 256 * 256);
    cudaEventRecord(evJ, s2);

    // branch A (stream 0): operand prep + layer-1 GEMM
    k_prepA<<<(NNODES * 128 + 255) / 256, 256>>>(x, NNODES * 128);
    k_prepB<<<(128 * 256 + 255) / 256, 256>>>(W1, B1, 128 * 256);
    k_prepBN2<<<1, 512>>>(b1, gam1, be1, m1, v1, b2, gam2, be2, m2, v2);
    k_gemm_mma<<<gemmBlocks, 512, GSMEM>>>(A16, B1, bufH, 128, as1, ad1, gmax);

    // ---- join ----
    cudaStreamWaitEvent(0, evJ, 0);

    k_agg<0><<<nodeBlocks, 256>>>(bufH, bnA, bnB, gmax, nullptr);
    k_gemm_mma<<<gemmBlocks, 512, GSMEM>>>(A16, B2, bufH, 256, as2, ad2, gmax + 4);
    k_agg<1><<<nodeBlocks, 256>>>(bufH, bnA + 256, bnB + 256, gmax + 4, out);
}

// round 11
// speedup vs baseline: 2.4207x; 1.0690x over previous
#include <cuda_runtime.h>
#include <cuda_bf16.h>
#include <cuda_fp16.h>
#include <math.h>
#include <stdint.h>

#define NNODES 50000
#define NEDGES 800000
#define FDIM   256          // H*C
#define TOTE   (NEDGES + NNODES)
#define NB_SCAN ((NNODES + 511) / 512)

// ---------------- scratch (static device globals; no allocation) ----------------
__device__ __half g_A16[(size_t)NNODES * FDIM];   // fp16 A operand (layer1: stride 128, layer2: stride 256)
__device__ __half g_bufH[(size_t)NNODES * FDIM];  // fp16 h image (gather source)
__device__ float g_asrcv[NNODES * 4];
__device__ float g_adstv[NNODES * 4];
__device__ int   g_deg[NNODES];                   // invariant: zero at call entry (zero-init + scan1 reset)
__device__ int   g_rowptr[NNODES + 1];
__device__ int   g_cursor[NNODES];
__device__ int   g_srclist[TOTE];
__device__ int   g_blksums[256];
__device__ __half g_B16_1[32768];       // layer-1 weights fp16, row-major [128][256]
__device__ __half g_B16_2[65536];       // layer-2 weights fp16, row-major [256][256]
__device__ float g_bnA[512];            // folded BN scale (layer0: [0,256), layer1: [256,512))
__device__ float g_bnB[512];            // folded BN shift
__device__ float g_gmax[8];             // per-head global max of asrc (slot0: [0,4), slot1: [4,8))

// ---------------- PTX helpers (portable: sm_80+ instructions only) ----------------
__device__ __forceinline__ uint32_t s2u(const void* p) {
    uint32_t a;
    asm("{ .reg .u64 t; cvta.to.shared.u64 t, %1; cvt.u32.u64 %0, t; }" : "=r"(a) : "l"(p));
    return a;
}

__device__ __forceinline__ void ldsm4(uint32_t* r, uint32_t addr) {
    asm volatile("ldmatrix.sync.aligned.m8n8.x4.shared.b16 {%0,%1,%2,%3}, [%4];"
                 : "=r"(r[0]), "=r"(r[1]), "=r"(r[2]), "=r"(r[3]) : "r"(addr));
}

__device__ __forceinline__ void ldsm4t(uint32_t* r, uint32_t addr) {
    asm volatile("ldmatrix.sync.aligned.m8n8.x4.trans.shared.b16 {%0,%1,%2,%3}, [%4];"
                 : "=r"(r[0]), "=r"(r[1]), "=r"(r[2]), "=r"(r[3]) : "r"(addr));
}

__device__ __forceinline__ void mma16816h(float* d, const uint32_t* a, const uint32_t* b) {
    asm volatile("mma.sync.aligned.m16n8k16.row.col.f32.f16.f16.f32 "
                 "{%0,%1,%2,%3}, {%4,%5,%6,%7}, {%8,%9}, {%0,%1,%2,%3};"
                 : "+f"(d[0]), "+f"(d[1]), "+f"(d[2]), "+f"(d[3])
                 : "r"(a[0]), "r"(a[1]), "r"(a[2]), "r"(a[3]), "r"(b[0]), "r"(b[1]));
}

__device__ __forceinline__ void cpasync16(uint32_t dst, const void* src, int sz) {
    asm volatile("cp.async.cg.shared.global [%0], [%1], 16, %2;"
                 :: "r"(dst), "l"(src), "r"(sz) : "memory");
}

__device__ __forceinline__ float lrelu(float e) {
    return (e > 0.f) ? e : 0.2f * e;
}

// float atomic max via integer ordering trick
__device__ __forceinline__ void atomicMaxF(float* a, float v) {
    if (v >= 0.f) atomicMax((int*)a, __float_as_int(v));
    else atomicMin((unsigned int*)a, __float_as_uint(v));
}

// ---------------- CSR build ----------------
__global__ void k_count(const int* __restrict__ ei) {
    int i = blockIdx.x * blockDim.x + threadIdx.x;
    if (i < NEDGES) atomicAdd(&g_deg[ei[NEDGES + i]], 1);
}

// reads deg (+1 self-loop) and RESETS it to zero for the next call/replay
__global__ void k_scan1() {
    __shared__ int s[512];
    int tid = threadIdx.x;
    int i = blockIdx.x * 512 + tid;
    int v = 0;
    if (i < NNODES) {
        v = g_deg[i] + 1;     // +1 = self loop
        g_deg[i] = 0;         // restore zero invariant
    }
    s[tid] = v;
    __syncthreads();
    for (int off = 1; off < 512; off <<= 1) {
        int t = (tid >= off) ? s[tid - off] : 0;
        __syncthreads();
        s[tid] += t;
        __syncthreads();
    }
    if (i < NNODES) g_rowptr[i] = s[tid] - v;
    if (tid == 511) g_blksums[blockIdx.x] = s[511];
}

// parallel exclusive scan of the 98 block sums (one block, smem Hillis-Steele)
__global__ void k_scan2p() {
    __shared__ int s[128];
    int t = threadIdx.x;
    int v = (t < NB_SCAN) ? g_blksums[t] : 0;
    s[t] = v;
    __syncthreads();
#pragma unroll
    for (int off = 1; off < 128; off <<= 1) {
        int u = (t >= off) ? s[t - off] : 0;
        __syncthreads();
        s[t] += u;
        __syncthreads();
    }
    if (t < NB_SCAN) g_blksums[t] = s[t] - v;   // exclusive
}

__global__ void k_scan3f() {
    int i = blockIdx.x * blockDim.x + threadIdx.x;
    if (i < NNODES) {
        int r = g_rowptr[i] + g_blksums[i >> 9];
        g_rowptr[i] = r;
        g_srclist[r] = i;        // self loop first
        g_cursor[i] = r + 1;
    }
    if (i == 0) g_rowptr[NNODES] = TOTE;
}

__global__ void k_fill(const int* __restrict__ ei) {
    int i = blockIdx.x * blockDim.x + threadIdx.x;
    if (i < NEDGES) {
        int s = ei[i];
        int d = ei[NEDGES + i];
        int pos = atomicAdd(&g_cursor[d], 1);
        g_srclist[pos] = s;
    }
}

// sort each node's segment by src (canonical order for determinism).
// L1-backed local buffer for the common case; global fallback for huge segments.
__global__ void k_sort() {
    int n = blockIdx.x * blockDim.x + threadIdx.x;
    if (n >= NNODES) return;
    int beg = g_rowptr[n] + 1;
    int end = g_rowptr[n + 1];
    int len = end - beg;
    if (len <= 1) return;
    if (len <= 56) {
        int buf[56];
        for (int i = 0; i < len; i++) buf[i] = g_srclist[beg + i];
        for (int i = 1; i < len; i++) {
            int key = buf[i];
            int j = i - 1;
            while (j >= 0 && buf[j] > key) {
                buf[j + 1] = buf[j];
                j--;
            }
            buf[j + 1] = key;
        }
        for (int i = 0; i < len; i++) g_srclist[beg + i] = buf[i];
    } else {
        for (int i = beg + 1; i < end; i++) {
            int key = g_srclist[i];
            int j = i - 1;
            while (j >= beg && g_srclist[j] > key) {
                g_srclist[j + 1] = g_srclist[j];
                j--;
            }
            g_srclist[j + 1] = key;
        }
    }
}

// ---------------- operand conversion + BN fold ----------------
__global__ void k_prepB(const float* __restrict__ W, __half* __restrict__ B, int total) {
    int i = blockIdx.x * 256 + threadIdx.x;
    if (i >= total) return;
    B[i] = __float2half_rn(W[i]);
}

__global__ void k_prepA(const float* __restrict__ X, int total) {
    int i = blockIdx.x * 256 + threadIdx.x;
    if (i >= total) return;
    g_A16[i] = __float2half_rn(X[i]);
}

// folded BN (both layers) + gmax reset, one launch of 512 threads
__global__ void k_prepBN2(const float* __restrict__ b1, const float* __restrict__ g1,
                          const float* __restrict__ be1, const float* __restrict__ m1,
                          const float* __restrict__ v1,
                          const float* __restrict__ b2, const float* __restrict__ g2,
                          const float* __restrict__ be2, const float* __restrict__ m2,
                          const float* __restrict__ v2) {
    int i = threadIdx.x;
    if (i < 256) {
        float s = g1[i] * rsqrtf(v1[i] + 1e-5f);
        g_bnA[i] = s;
        g_bnB[i] = (b1[i] - m1[i]) * s + be1[i];
    } else {
        int j = i - 256;
        float s = g2[j] * rsqrtf(v2[j] + 1e-5f);
        g_bnA[i] = s;
        g_bnB[i] = (b2[j] - m2[j]) * s + be2[j];
    }
    if (i < 8) g_gmax[i] = -1e30f;
}

// ---------------- fp16 tensor-core GEMM: cp.async double-buffered, 512 thr, 128x256 tile ----------------
// stage: A[128][80B] (10240) + B[32][528B] (16896) = 27136 B; 2 stages.
#define GSTAGE 27136
__global__ void __launch_bounds__(512) k_gemm_mma(const __half* __restrict__ Ap,
                                                  const __half* __restrict__ Bp,
                                                  __half* __restrict__ H, int K,
                                                  const float* __restrict__ Asrc,
                                                  const float* __restrict__ Adst,
                                                  float* __restrict__ gmax) {
    extern __shared__ char sm[];
    uint32_t sbase = s2u(sm);

    int tid = threadIdx.x;
    int lane = tid & 31, w = tid >> 5;
    int wm = w & 3, wn = w >> 2;          // warp tile origin (wm*32, wn*64)
    int by = blockIdx.x;
    int nch = K >> 5;

    int ar = tid >> 2, ac = tid & 3;
    int agr = by * 128 + ar;
    int asz = (agr < NNODES) ? 16 : 0;
    int agc = (agr < NNODES) ? agr : 0;
    const char* gA = (const char*)(Ap + (size_t)agc * K + ac * 8);
    uint32_t dA = (uint32_t)(ar * 80 + ac * 16);

    float acc[2][8][4];
#pragma unroll
    for (int i = 0; i < 2; i++)
#pragma unroll
        for (int j = 0; j < 8; j++)
#pragma unroll
            for (int q = 0; q < 4; q++) acc[i][j][q] = 0.f;

#define ISSUE(kc, s) do {                                                          \
        uint32_t so = sbase + (s) * GSTAGE;                                        \
        cpasync16(so + dA, gA + (size_t)(kc) * 64, asz);                           \
        _Pragma("unroll")                                                          \
        for (int i = 0; i < 2; i++) {                                              \
            int p = tid + 512 * i;                                                 \
            int rr = p >> 5, c2 = p & 31;                                          \
            size_t go = (size_t)((kc) * 32 + rr) * 256 + c2 * 8;                   \
            cpasync16(so + 10240 + rr * 528 + c2 * 16, (const char*)(Bp + go), 16);\
        }                                                                          \
        asm volatile("cp.async.commit_group;" ::: "memory");                       \
    } while (0)

    ISSUE(0, 0);

    for (int kc = 0; kc < nch; kc++) {
        int s = kc & 1;
        if (kc + 1 < nch) {
            ISSUE(kc + 1, (kc + 1) & 1);
            asm volatile("cp.async.wait_group 1;" ::: "memory");
        } else {
            asm volatile("cp.async.wait_group 0;" ::: "memory");
        }
        __syncthreads();

        uint32_t aoff = sbase + s * GSTAGE;
        uint32_t boff = aoff + 10240;
#pragma unroll
        for (int ks = 0; ks < 2; ks++) {
            uint32_t av[2][4], bv[4][4];
#pragma unroll
            for (int mt = 0; mt < 2; mt++) {
                int row = wm * 32 + mt * 16 + (lane & 15);
                ldsm4(av[mt], aoff + row * 80 + ks * 32 + (lane >> 4) * 16);
            }
#pragma unroll
            for (int nt = 0; nt < 4; nt++) {
                int row = ks * 16 + (lane & 15);
                ldsm4t(bv[nt], boff + row * 528 + (wn * 64 + nt * 16) * 2 + (lane >> 4) * 16);
            }
#pragma unroll
            for (int mt = 0; mt < 2; mt++)
#pragma unroll
                for (int nt = 0; nt < 4; nt++)
#pragma unroll
                    for (int h = 0; h < 2; h++)
                        mma16816h(acc[mt][nt * 2 + h], av[mt], &bv[nt][h * 2]);
        }
        __syncthreads();
    }

    // ---- epilogue: write fp16 H + fused per-head attention dots + global asrc max ----
    int head = wn;
    float wmax = -1e30f;
#pragma unroll
    for (int mt = 0; mt < 2; mt++) {
        int r0 = by * 128 + wm * 32 + mt * 16 + (lane >> 2);
        float ps0 = 0.f, ps1 = 0.f, pd0 = 0.f, pd1 = 0.f;
#pragma unroll
        for (int nt = 0; nt < 8; nt++) {
            int cc = wn * 64 + nt * 8 + (lane & 3) * 2;
            float as0 = Asrc[cc], as1v = Asrc[cc + 1];
            float ad0 = Adst[cc], ad1v = Adst[cc + 1];
            ps0 += acc[mt][nt][0] * as0 + acc[mt][nt][1] * as1v;
            pd0 += acc[mt][nt][0] * ad0 + acc[mt][nt][1] * ad1v;
            ps1 += acc[mt][nt][2] * as0 + acc[mt][nt][3] * as1v;
            pd1 += acc[mt][nt][2] * ad0 + acc[mt][nt][3] * ad1v;
            if (r0 < NNODES) {
                *(__half2*)(H + (size_t)r0 * FDIM + cc) =
                    __floats2half2_rn(acc[mt][nt][0], acc[mt][nt][1]);
            }
            if (r0 + 8 < NNODES) {
                *(__half2*)(H + (size_t)(r0 + 8) * FDIM + cc) =
                    __floats2half2_rn(acc[mt][nt][2], acc[mt][nt][3]);
            }
        }
#pragma unroll
        for (int off = 1; off <= 2; off <<= 1) {
            ps0 += __shfl_xor_sync(0xffffffffu, ps0, off);
            ps1 += __shfl_xor_sync(0xffffffffu, ps1, off);
            pd0 += __shfl_xor_sync(0xffffffffu, pd0, off);
            pd1 += __shfl_xor_sync(0xffffffffu, pd1, off);
        }
        wmax = fmaxf(wmax, fmaxf(ps0, ps1));
        if ((lane & 3) == 0) {
            if (r0 < NNODES) {
                g_asrcv[r0 * 4 + head] = ps0;
                g_adstv[r0 * 4 + head] = pd0;
            }
            if (r0 + 8 < NNODES) {
                g_asrcv[(r0 + 8) * 4 + head] = ps1;
                g_adstv[(r0 + 8) * 4 + head] = pd1;
            }
        }
    }
#pragma unroll
    for (int off = 4; off <= 16; off <<= 1)
        wmax = fmaxf(wmax, __shfl_xor_sync(0xffffffffu, wmax, off));
    if (lane == 0) atomicMaxF(&gmax[head], wmax);
}

// ---------------- GAT aggregation: single-pass softmax vs global bound ----------------
// MODE 0: write fp16 (next layer's A operand). MODE 1: log_softmax + fp32 out.
template <int MODE>
__global__ void __launch_bounds__(256) k_agg(const __half* __restrict__ X,
                      const float* __restrict__ bnA,
                      const float* __restrict__ bnB,
                      const float* __restrict__ gmax,
                      float* __restrict__ OUT) {
    int gwarp = (blockIdx.x * blockDim.x + threadIdx.x) >> 5;
    int lane = threadIdx.x & 31;
    if (gwarp >= NNODES) return;
    int n = gwarp;
    int ch0 = lane * 8;
    int hl = lane >> 3;

    const float* __restrict__ sc = g_asrcv;
    const int* __restrict__ lst = g_srclist;

    float adv = g_adstv[n * 4 + hl];
    float mx = lrelu(gmax[hl] + adv);        // upper bound on all edge scores of n
    int r0 = g_rowptr[n], r1 = g_rowptr[n + 1];

    float dsum = 0.f;
    float acc[8];
#pragma unroll
    for (int j = 0; j < 8; j++) acc[j] = 0.f;

    int k = r0;
    for (; k + 3 < r1; k += 4) {
        int s0 = lst[k], s1 = lst[k + 1], s2 = lst[k + 2], s3 = lst[k + 3];
        uint4 ra = *(const uint4*)(X + (size_t)s0 * FDIM + ch0);
        uint4 rb = *(const uint4*)(X + (size_t)s1 * FDIM + ch0);
        uint4 rc = *(const uint4*)(X + (size_t)s2 * FDIM + ch0);
        uint4 rd = *(const uint4*)(X + (size_t)s3 * FDIM + ch0);
        float p0 = __expf(lrelu(sc[s0 * 4 + hl] + adv) - mx);
        float p1 = __expf(lrelu(sc[s1 * 4 + hl] + adv) - mx);
        float p2 = __expf(lrelu(sc[s2 * 4 + hl] + adv) - mx);
        float p3 = __expf(lrelu(sc[s3 * 4 + hl] + adv) - mx);
        dsum += (p0 + p1) + (p2 + p3);
        float2 a0 = __half22float2(*(__half2*)&ra.x);
        float2 a1 = __half22float2(*(__half2*)&ra.y);
        float2 a2 = __half22float2(*(__half2*)&ra.z);
        float2 a3 = __half22float2(*(__half2*)&ra.w);
        float2 b0 = __half22float2(*(__half2*)&rb.x);
        float2 b1 = __half22float2(*(__half2*)&rb.y);
        float2 b2 = __half22float2(*(__half2*)&rb.z);
        float2 b3 = __half22float2(*(__half2*)&rb.w);
        float2 c0 = __half22float2(*(__half2*)&rc.x);
        float2 c1 = __half22float2(*(__half2*)&rc.y);
        float2 c2 = __half22float2(*(__half2*)&rc.z);
        float2 c3 = __half22float2(*(__half2*)&rc.w);
        float2 d0 = __half22float2(*(__half2*)&rd.x);
        float2 d1 = __half22float2(*(__half2*)&rd.y);
        float2 d2 = __half22float2(*(__half2*)&rd.z);
        float2 d3 = __half22float2(*(__half2*)&rd.w);
        acc[0] += (p0 * a0.x + p1 * b0.x) + (p2 * c0.x + p3 * d0.x);
        acc[1] += (p0 * a0.y + p1 * b0.y) + (p2 * c0.y + p3 * d0.y);
        acc[2] += (p0 * a1.x + p1 * b1.x) + (p2 * c1.x + p3 * d1.x);
        acc[3] += (p0 * a1.y + p1 * b1.y) + (p2 * c1.y + p3 * d1.y);
        acc[4] += (p0 * a2.x + p1 * b2.x) + (p2 * c2.x + p3 * d2.x);
        acc[5] += (p0 * a2.y + p1 * b2.y) + (p2 * c2.y + p3 * d2.y);
        acc[6] += (p0 * a3.x + p1 * b3.x) + (p2 * c3.x + p3 * d3.x);
        acc[7] += (p0 * a3.y + p1 * b3.y) + (p2 * c3.y + p3 * d3.y);
    }
    for (; k < r1; k++) {
        int s0 = lst[k];
        uint4 ra = *(const uint4*)(X + (size_t)s0 * FDIM + ch0);
        float p0 = __expf(lrelu(sc[s0 * 4 + hl] + adv) - mx);
        dsum += p0;
        float2 a0 = __half22float2(*(__half2*)&ra.x);
        float2 a1 = __half22float2(*(__half2*)&ra.y);
        float2 a2 = __half22float2(*(__half2*)&ra.z);
        float2 a3 = __half22float2(*(__half2*)&ra.w);
        acc[0] += p0 * a0.x;
        acc[1] += p0 * a0.y;
        acc[2] += p0 * a1.x;
        acc[3] += p0 * a1.y;
        acc[4] += p0 * a2.x;
        acc[5] += p0 * a2.y;
        acc[6] += p0 * a3.x;
        acc[7] += p0 * a3.y;
    }

    float inv = 1.f / (dsum + 1e-16f);
    float ov[8];
#pragma unroll
    for (int j = 0; j < 8; j++) {
        int ch = ch0 + j;
        ov[j] = fmaxf(fmaf(acc[j] * inv, bnA[ch], bnB[ch]), 0.f);
    }

    if (MODE == 0) {
        uint4 hv;
        *(__half2*)&hv.x = __floats2half2_rn(ov[0], ov[1]);
        *(__half2*)&hv.y = __floats2half2_rn(ov[2], ov[3]);
        *(__half2*)&hv.z = __floats2half2_rn(ov[4], ov[5]);
        *(__half2*)&hv.w = __floats2half2_rn(ov[6], ov[7]);
        *(uint4*)(g_A16 + (size_t)n * FDIM + ch0) = hv;
    } else {
        float m2 = ov[0];
#pragma unroll
        for (int j = 1; j < 8; j++) m2 = fmaxf(m2, ov[j]);
#pragma unroll
        for (int off = 16; off > 0; off >>= 1) m2 = fmaxf(m2, __shfl_xor_sync(0xffffffffu, m2, off));
        float se = 0.f;
#pragma unroll
        for (int j = 0; j < 8; j++) se += __expf(ov[j] - m2);
#pragma unroll
        for (int off = 16; off > 0; off >>= 1) se += __shfl_xor_sync(0xffffffffu, se, off);
        float lse = m2 + logf(se);
        float4* op = (float4*)(OUT + (size_t)n * FDIM + ch0);
        op[0] = make_float4(ov[0] - lse, ov[1] - lse, ov[2] - lse, ov[3] - lse);
        op[1] = make_float4(ov[4] - lse, ov[5] - lse, ov[6] - lse, ov[7] - lse);
    }
}

// ---------------- launch: fork CSR chain onto a second captured stream ----------------
extern "C" void kernel_launch(void* const* d_in, const int* in_sizes, int n_in,
                              void* d_out, int out_size) {
    const float* x    = (const float*)d_in[0];
    const int*   ei   = (const int*)d_in[1];
    const float* W1   = (const float*)d_in[2];
    const float* as1  = (const float*)d_in[3];
    const float* ad1  = (const float*)d_in[4];
    const float* b1   = (const float*)d_in[5];
    const float* gam1 = (const float*)d_in[6];
    const float* be1  = (const float*)d_in[7];
    const float* m1   = (const float*)d_in[8];
    const float* v1   = (const float*)d_in[9];
    const float* W2   = (const float*)d_in[10];
    const float* as2  = (const float*)d_in[11];
    const float* ad2  = (const float*)d_in[12];
    const float* b2   = (const float*)d_in[13];
    const float* gam2 = (const float*)d_in[14];
    const float* be2  = (const float*)d_in[15];
    const float* m2   = (const float*)d_in[16];
    const float* v2   = (const float*)d_in[17];
    float* out = (float*)d_out;

    __half *A16, *B1, *B2, *bufH;
    float *bnA, *bnB, *gmax;
    cudaGetSymbolAddress((void**)&A16, g_A16);
    cudaGetSymbolAddress((void**)&B1, g_B16_1);
    cudaGetSymbolAddress((void**)&B2, g_B16_2);
    cudaGetSymbolAddress((void**)&bufH, g_bufH);
    cudaGetSymbolAddress((void**)&bnA, g_bnA);
    cudaGetSymbolAddress((void**)&bnB, g_bnB);
    cudaGetSymbolAddress((void**)&gmax, g_gmax);

    // side stream + fork/join events (host objects; created once, before any capture)
    static cudaStream_t s2 = nullptr;
    static cudaEvent_t evF = nullptr, evJ = nullptr;
    if (s2 == nullptr) {
        cudaStreamCreateWithFlags(&s2, cudaStreamNonBlocking);
        cudaEventCreateWithFlags(&evF, cudaEventDisableTiming);
        cudaEventCreateWithFlags(&evJ, cudaEventDisableTiming);
    }

    const int GSMEM = 2 * GSTAGE;  // 54272
    cudaFuncSetAttribute(k_gemm_mma, cudaFuncAttributeMaxDynamicSharedMemorySize, GSMEM);

    int gemmBlocks = (NNODES + 127) / 128;   // 391
    int nodeBlocks = (NNODES + 7) / 8;

    // ---- fork ----
    cudaEventRecord(evF, 0);
    cudaStreamWaitEvent(s2, evF, 0);

    // branch B (stream s2): layer-2 weight prep + CSR build (independent of x/W1)
    k_prepB<<<(256 * 256 + 255) / 256, 256, 0, s2>>>(W2, B2, 256 * 256);
    k_count<<<(NEDGES + 255) / 256, 256, 0, s2>>>(ei);
    k_scan1<<<NB_SCAN, 512, 0, s2>>>();
    k_scan2p<<<1, 128, 0, s2>>>();
    k_scan3f<<<(NNODES + 255) / 256, 256, 0, s2>>>();
    k_fill<<<(NEDGES + 255) / 256, 256, 0, s2>>>(ei);
    k_sort<<<(NNODES + 255) / 256, 256, 0, s2>>>();
    cudaEventRecord(evJ, s2);

    // branch A (stream 0): operand prep + layer-1 GEMM
    k_prepA<<<(NNODES * 128 + 255) / 256, 256>>>(x, NNODES * 128);
    k_prepB<<<(128 * 256 + 255) / 256, 256>>>(W1, B1, 128 * 256);
    k_prepBN2<<<1, 512>>>(b1, gam1, be1, m1, v1, b2, gam2, be2, m2, v2);
    k_gemm_mma<<<gemmBlocks, 512, GSMEM>>>(A16, B1, bufH, 128, as1, ad1, gmax);

    // ---- join ----
    cudaStreamWaitEvent(0, evJ, 0);

    k_agg<0><<<nodeBlocks, 256>>>(bufH, bnA, bnB, gmax, nullptr);
    k_gemm_mma<<<gemmBlocks, 512, GSMEM>>>(A16, B2, bufH, 256, as2, ad2, gmax + 4);
    k_agg<1><<<nodeBlocks, 256>>>(bufH, bnA + 256, bnB + 256, gmax + 4, out);
}